// round 1
// baseline (speedup 1.0000x reference)
#include <cuda_runtime.h>
#include <math.h>

#define NE    512
#define NH    8
#define ND    64
#define NB    2
#define NT    1024
#define NHD   512
#define NROWS 2048          // B*T
#define NFFN  2048

// ------------------------------ scratch (static device globals; no allocs) --
static __device__ float g_xn  [NROWS * NE];          // LN1 output
static __device__ float g_Wkqv[NE * 3 * NHD];        // packed [Wk|Wq|Wv]
static __device__ float g_bkqv[3 * NHD];
static __device__ float g_kqv [NROWS * 3 * NHD];     // k|q|v (post-activation)
static __device__ float g_coef[NROWS * NH];          // d*gw
static __device__ float g_logd[NROWS * NH];          // log(clip(d*gf))
static __device__ float g_ecum[NB * NH * NT];        // exp(cumsum(log decay))
static __device__ float g_invd[NB * NH * NT];        // 1/(ecum+1e-8)
static __device__ float g_read[NROWS * NHD];         // readout
static __device__ float g_x2  [NROWS * NE];
static __device__ float g_hh  [NROWS * NE];          // LN2 output
static __device__ float g_mid [NROWS * NFFN];        // gelu(h@W1+b1)

// ------------------------------------------------------------- LayerNorm ---
__global__ __launch_bounds__(256) void ln_k(const float* __restrict__ x,
                                            const float* __restrict__ g,
                                            const float* __restrict__ b,
                                            float* __restrict__ o) {
    __shared__ float sh[8];
    const int row = blockIdx.x, tid = threadIdx.x;
    const float v0 = x[(size_t)row * NE + tid];
    const float v1 = x[(size_t)row * NE + tid + 256];

    float s = v0 + v1;
    #pragma unroll
    for (int off = 16; off; off >>= 1) s += __shfl_xor_sync(~0u, s, off);
    if ((tid & 31) == 0) sh[tid >> 5] = s;
    __syncthreads();
    if (tid < 32) {
        float t = (tid < 8) ? sh[tid] : 0.f;
        #pragma unroll
        for (int off = 4; off; off >>= 1) t += __shfl_xor_sync(~0u, t, off);
        if (tid == 0) sh[0] = t;
    }
    __syncthreads();
    const float mu = sh[0] * (1.f / NE);
    __syncthreads();

    const float d0 = v0 - mu, d1 = v1 - mu;
    s = d0 * d0 + d1 * d1;
    #pragma unroll
    for (int off = 16; off; off >>= 1) s += __shfl_xor_sync(~0u, s, off);
    if ((tid & 31) == 0) sh[tid >> 5] = s;
    __syncthreads();
    if (tid < 32) {
        float t = (tid < 8) ? sh[tid] : 0.f;
        #pragma unroll
        for (int off = 4; off; off >>= 1) t += __shfl_xor_sync(~0u, t, off);
        if (tid == 0) sh[0] = t;
    }
    __syncthreads();
    const float var = sh[0] * (1.f / NE);
    const float inv = 1.f / sqrtf(var + 1e-5f);

    o[(size_t)row * NE + tid]       = d0 * inv * g[tid]       + b[tid];
    o[(size_t)row * NE + tid + 256] = d1 * inv * g[tid + 256] + b[tid + 256];
}

// --------------------------------------------------- pack Wk|Wq|Wv, biases -
__global__ void concat_w(const float* __restrict__ Wk, const float* __restrict__ Wq,
                         const float* __restrict__ Wv, const float* __restrict__ bk,
                         const float* __restrict__ bq, const float* __restrict__ bv) {
    const int idx = blockIdx.x * 256 + threadIdx.x;
    if (idx < NE * NHD) {
        const int r = idx / NHD, c = idx % NHD;
        g_Wkqv[(size_t)r * 1536 + c]        = Wk[idx];
        g_Wkqv[(size_t)r * 1536 + 512 + c]  = Wq[idx];
        g_Wkqv[(size_t)r * 1536 + 1024 + c] = Wv[idx];
    }
    if (idx < NHD) {
        g_bkqv[idx] = bk[idx];
        g_bkqv[512 + idx] = bq[idx];
        g_bkqv[1024 + idx] = bv[idx];
    }
}

// ------------------------------------------- generic SGEMM with epilogues --
// MODE 0: C = A@B + bias
// MODE 1: C = A@B + bias + aux1 + 0.1*aux2           (x2 = res + proj + motif)
// MODE 2: C = gelu_exact(A@B + bias)                 (ffn1)
// MODE 3: C = A@B + bias + aux1                      (x3 = x2 + ffn2)
// MODE 4: C = aux1 + v; C2 = aux2 + v  (v=A@B+bias)  (probe outputs)
template <int MODE>
__global__ __launch_bounds__(256) void sgemm_k(
    const float* __restrict__ A, const float* __restrict__ B,
    const float* __restrict__ bias, float* __restrict__ C,
    int K, int N, int ldc,
    const float* __restrict__ aux1, const float* __restrict__ aux2,
    float* __restrict__ C2) {
    __shared__ float As[8][128];
    __shared__ float Bs[8][128];
    const int tid = threadIdx.x;
    const int mBase = blockIdx.y * 128;
    const int nBase = blockIdx.x * 128;
    const int tr = (tid >> 4) << 3;   // 0..120 row offset in tile
    const int tc = (tid & 15) << 3;   // 0..120 col offset in tile

    float acc[8][8];
    #pragma unroll
    for (int i = 0; i < 8; i++)
        #pragma unroll
        for (int j = 0; j < 8; j++) acc[i][j] = 0.f;

    const int aRow = tid >> 1, aCol = (tid & 1) << 2;
    const int bRow = tid >> 5, bCol = (tid & 31) << 2;
    const float* Ag = A + (size_t)(mBase + aRow) * K + aCol;
    const float* Bg = B + (size_t)bRow * N + nBase + bCol;

    for (int kb = 0; kb < K; kb += 8) {
        const float4 av = *(const float4*)(Ag + kb);
        As[aCol + 0][aRow] = av.x;
        As[aCol + 1][aRow] = av.y;
        As[aCol + 2][aRow] = av.z;
        As[aCol + 3][aRow] = av.w;
        *(float4*)&Bs[bRow][bCol] = *(const float4*)(Bg + (size_t)kb * N);
        __syncthreads();
        #pragma unroll
        for (int k = 0; k < 8; k++) {
            float ra[8], rb[8];
            *(float4*)&ra[0] = *(const float4*)&As[k][tr];
            *(float4*)&ra[4] = *(const float4*)&As[k][tr + 4];
            *(float4*)&rb[0] = *(const float4*)&Bs[k][tc];
            *(float4*)&rb[4] = *(const float4*)&Bs[k][tc + 4];
            #pragma unroll
            for (int i = 0; i < 8; i++)
                #pragma unroll
                for (int j = 0; j < 8; j++)
                    acc[i][j] = fmaf(ra[i], rb[j], acc[i][j]);
        }
        __syncthreads();
    }

    #pragma unroll
    for (int i = 0; i < 8; i++) {
        const int row = mBase + tr + i;
        #pragma unroll
        for (int j = 0; j < 8; j++) {
            const int col = nBase + tc + j;
            const float v = acc[i][j] + bias[col];
            const size_t idx = (size_t)row * ldc + col;
            if (MODE == 0) {
                C[idx] = v;
            } else if (MODE == 1) {
                C[idx] = v + aux1[idx] + 0.1f * aux2[idx];
            } else if (MODE == 2) {
                C[idx] = 0.5f * v * (1.f + erff(v * 0.7071067811865475f));
            } else if (MODE == 3) {
                C[idx] = v + aux1[idx];
            } else {
                C[idx]  = aux1[idx] + v;
                C2[idx] = aux2[idx] + v;
            }
        }
    }
}

// ------------------------------------------ k/q l2norm + v tanh (per head) -
__global__ __launch_bounds__(32) void act_k() {
    const int rowh = blockIdx.x;
    const int row = rowh >> 3, h = rowh & 7, lane = threadIdx.x;
    float* base = g_kqv + (size_t)row * 1536 + h * 64;
    #pragma unroll
    for (int p = 0; p < 2; p++) {
        float* ptr = base + p * 512;
        const float a = ptr[lane], c = ptr[lane + 32];
        float ss = a * a + c * c;
        #pragma unroll
        for (int off = 16; off; off >>= 1) ss += __shfl_xor_sync(~0u, ss, off);
        const float inv = 1.f / fmaxf(sqrtf(ss), 1e-12f);
        ptr[lane] = a * inv;
        ptr[lane + 32] = c * inv;
    }
    float* ptr = base + 1024;
    ptr[lane]      = tanhf(ptr[lane]);
    ptr[lane + 32] = tanhf(ptr[lane + 32]);
}

// -------------------------- d/gw/gf projection + gate math (24 cols total) -
__global__ __launch_bounds__(32) void proj_small_k(
    const float* __restrict__ Wd,  const float* __restrict__ bd,
    const float* __restrict__ Wgw, const float* __restrict__ bgw,
    const float* __restrict__ Wgf, const float* __restrict__ bgf) {
    __shared__ float sh[24];
    const int row = blockIdx.x, tid = threadIdx.x;
    if (tid < 24) {
        const int grp = tid >> 3, c = tid & 7;
        const float* W  = (grp == 0) ? Wd  : ((grp == 1) ? Wgw : Wgf);
        const float* bb = (grp == 0) ? bd  : ((grp == 1) ? bgw : bgf);
        const float* xr = g_xn + (size_t)row * NE;
        float acc = 0.f;
        #pragma unroll 8
        for (int k = 0; k < NE; k++) acc = fmaf(xr[k], W[k * NH + c], acc);
        sh[tid] = acc + bb[c];
    }
    __syncwarp();
    if (tid < NH) {
        const float xd = sh[tid], xgw = sh[8 + tid], xgf = sh[16 + tid];
        const float d  = fmaxf(xd, 0.f) + log1pf(expf(-fabsf(xd)));   // softplus
        const float sw = 1.f / (1.f + expf(-xgw));
        const float sf = 1.f / (1.f + expf(-xgf));
        const float gw = sw * sw;
        const float gf = 1.f - sf * sf;
        g_coef[row * NH + tid] = d * gw;
        const float dec = fminf(fmaxf(d * gf, 1e-6f), 0.999f);
        g_logd[row * NH + tid] = logf(dec);
    }
}

// ------------------- sequential cumsum of log-decay (exact fp32 underflow) -
__global__ void cumsum_k() {
    const int s = threadIdx.x;
    if (s >= NB * NH) return;
    const int b = s >> 3, h = s & 7;
    float c = 0.f;
    for (int t = 0; t < NT; t++) {
        c += g_logd[(b * NT + t) * NH + h];
        const float e = expf(c);             // underflows to 0 exactly like ref
        g_ecum[s * NT + t] = e;
        g_invd[s * NT + t] = 1.f / (e + 1e-8f);
    }
}

// ------------------------------------------------- state scan + readout ----
// block = (i-chunk, bh); warp w handles state row i = ichunk*8+w; lane covers
// j and j+32. Per step: cum_ij += (v_i*coef*invden) * k_j ;
// readout_i = ecum * sum_j cum_ij * q_j (warp reduce). next_mem at t=T-1.
__global__ __launch_bounds__(256) void scan_k(float* __restrict__ next_mem) {
    __shared__ float ks[64][64];
    __shared__ float qs[64][64];
    __shared__ float a_s[8][64];
    __shared__ float es[64];
    const int bh = blockIdx.y, b = bh >> 3, h = bh & 7;
    const int warp = threadIdx.x >> 5, lane = threadIdx.x & 31;
    const int i = blockIdx.x * 8 + warp;
    const int tid = threadIdx.x;
    float cum0 = 0.f, cum1 = 0.f;

    for (int t0 = 0; t0 < NT; t0 += 64) {
        #pragma unroll
        for (int f = 0; f < 4; f++) {
            const int e4 = f * 256 + tid;          // 0..1023 float4 slots
            const int tt = e4 >> 4, j4 = (e4 & 15) << 2;
            const float* rp = g_kqv + (size_t)(b * NT + t0 + tt) * 1536 + h * 64;
            *(float4*)&ks[tt][j4] = *(const float4*)(rp + j4);
            *(float4*)&qs[tt][j4] = *(const float4*)(rp + 512 + j4);
        }
        #pragma unroll
        for (int u = 0; u < 2; u++) {
            const int tt = lane + u * 32;
            const int row = b * NT + t0 + tt;
            const float vv = g_kqv[(size_t)row * 1536 + 1024 + h * 64 + i];
            a_s[warp][tt] = vv * g_coef[row * NH + h] * g_invd[bh * NT + t0 + tt];
            if (warp == 0) es[tt] = g_ecum[bh * NT + t0 + tt];
        }
        __syncthreads();
        #pragma unroll 4
        for (int tt = 0; tt < 64; tt++) {
            const float a = a_s[warp][tt];
            cum0 = fmaf(a, ks[tt][lane], cum0);
            cum1 = fmaf(a, ks[tt][lane + 32], cum1);
            float r = cum0 * qs[tt][lane] + cum1 * qs[tt][lane + 32];
            #pragma unroll
            for (int off = 16; off; off >>= 1) r += __shfl_xor_sync(~0u, r, off);
            if (lane == 0)
                g_read[(size_t)(b * NT + t0 + tt) * NHD + h * 64 + i] = r * es[tt];
        }
        __syncthreads();
    }
    const float e = g_ecum[bh * NT + NT - 1];
    const size_t base = ((size_t)(b * NH + h) * ND + i) * ND;
    next_mem[base + lane]      = cum0 * e;
    next_mem[base + lane + 32] = cum1 * e;
}

// ---------------------------------------------------------------- launch ---
static float* sym(const void* s) {
    void* p = nullptr;
    cudaGetSymbolAddress(&p, s);
    return (float*)p;
}

extern "C" void kernel_launch(void* const* d_in, const int* in_sizes, int n_in,
                              void* d_out, int out_size) {
    const float* x     = (const float*)d_in[0];
    const float* b_min = (const float*)d_in[1];
    const float* b_max = (const float*)d_in[2];
    const float* motif = (const float*)d_in[3];
    const float* Wk    = (const float*)d_in[4];
    const float* bk    = (const float*)d_in[5];
    const float* Wq    = (const float*)d_in[6];
    const float* bq    = (const float*)d_in[7];
    const float* Wv    = (const float*)d_in[8];
    const float* bv    = (const float*)d_in[9];
    const float* Wo    = (const float*)d_in[10];
    const float* bo    = (const float*)d_in[11];
    const float* Wd    = (const float*)d_in[12];
    const float* bd    = (const float*)d_in[13];
    const float* Wgw   = (const float*)d_in[14];
    const float* bgw   = (const float*)d_in[15];
    const float* Wgf   = (const float*)d_in[16];
    const float* bgf   = (const float*)d_in[17];
    const float* Wps   = (const float*)d_in[18];
    const float* bps   = (const float*)d_in[19];
    const float* ln1g  = (const float*)d_in[20];
    const float* ln1b  = (const float*)d_in[21];
    const float* ln2g  = (const float*)d_in[22];
    const float* ln2b  = (const float*)d_in[23];
    const float* W1    = (const float*)d_in[24];
    const float* b1    = (const float*)d_in[25];
    const float* W2    = (const float*)d_in[26];
    const float* b2    = (const float*)d_in[27];

    float* out    = (float*)d_out;
    float* out_x3 = out;                            // [2,1024,512]
    float* out_nm = out + (size_t)NROWS * NE;       // [2,8,64,64]
    float* out_pm = out_nm + NB * NH * ND * ND;     // b_min + probe
    float* out_px = out_pm + (size_t)NROWS * NE;    // b_max + probe

    float* xn   = sym(g_xn);
    float* Wkqv = sym(g_Wkqv);
    float* bkqv = sym(g_bkqv);
    float* kqv  = sym(g_kqv);
    float* rd   = sym(g_read);
    float* x2   = sym(g_x2);
    float* hh   = sym(g_hh);
    float* mid  = sym(g_mid);

    // Phase A: LN1 + packed QKV projection + activations + gates
    ln_k<<<NROWS, 256>>>(x, ln1g, ln1b, xn);
    concat_w<<<(NE * NHD + 255) / 256, 256>>>(Wk, Wq, Wv, bk, bq, bv);
    sgemm_k<0><<<dim3(12, 16), 256>>>(xn, Wkqv, bkqv, kqv, 512, 1536, 1536,
                                      nullptr, nullptr, nullptr);
    proj_small_k<<<NROWS, 32>>>(Wd, bd, Wgw, bgw, Wgf, bgf);
    cumsum_k<<<1, 32>>>();
    act_k<<<NROWS * NH, 32>>>();

    // Phase B: state scan -> readout + next_mem
    scan_k<<<dim3(8, 16), 256>>>(out_nm);

    // Phase C: out-proj + residual + motif, LN2, FFN, probe
    sgemm_k<1><<<dim3(4, 16), 256>>>(rd, Wo, bo, x2, 512, 512, 512,
                                     x, motif, nullptr);
    ln_k<<<NROWS, 256>>>(x2, ln2g, ln2b, hh);
    sgemm_k<2><<<dim3(16, 16), 256>>>(hh, W1, b1, mid, 512, 2048, 2048,
                                      nullptr, nullptr, nullptr);
    sgemm_k<3><<<dim3(4, 16), 256>>>(mid, W2, b2, out_x3, 2048, 512, 512,
                                     x2, nullptr, nullptr);
    sgemm_k<4><<<dim3(4, 16), 256>>>(out_x3, Wps, bps, out_pm, 512, 512, 512,
                                     b_min, b_max, out_px);
}

// round 2
// speedup vs baseline: 1.7626x; 1.7626x over previous
#include <cuda_runtime.h>
#include <math.h>

#define NE    512
#define NH    8
#define ND    64
#define NB    2
#define NT    1024
#define NHD   512
#define NROWS 2048          // B*T
#define NFFN  2048

// ------------------------------ scratch (static device globals; no allocs) --
static __device__ float g_xn  [NROWS * NE];          // LN1 output
static __device__ float g_Wkqv[NE * 3 * NHD];        // packed [Wk|Wq|Wv]
static __device__ float g_bkqv[3 * NHD];
static __device__ float g_kqv [NROWS * 3 * NHD];     // k|q|v (post-activation)
static __device__ float g_coef[NROWS * NH];          // d*gw
static __device__ float g_logd[NROWS * NH];          // log(clip(d*gf))
static __device__ float g_ecum[NB * NH * NT];        // exp(cumsum(log decay))
static __device__ float g_invd[NB * NH * NT];        // 1/(ecum+1e-8)
static __device__ float g_read[NROWS * NHD];         // readout
static __device__ float g_x2  [NROWS * NE];
static __device__ float g_hh  [NROWS * NE];          // LN2 output
static __device__ float g_mid [NROWS * NFFN];        // gelu(h@W1+b1)
static __device__ float g_Wt  [24 * NE];             // transposed small weights
static __device__ float g_bsm [24];

// ------------------------------------------------------------- LayerNorm ---
__global__ __launch_bounds__(256) void ln_k(const float* __restrict__ x,
                                            const float* __restrict__ g,
                                            const float* __restrict__ b,
                                            float* __restrict__ o) {
    __shared__ float sh[8];
    const int row = blockIdx.x, tid = threadIdx.x;
    const float v0 = x[(size_t)row * NE + tid];
    const float v1 = x[(size_t)row * NE + tid + 256];

    float s = v0 + v1;
    #pragma unroll
    for (int off = 16; off; off >>= 1) s += __shfl_xor_sync(~0u, s, off);
    if ((tid & 31) == 0) sh[tid >> 5] = s;
    __syncthreads();
    if (tid < 32) {
        float t = (tid < 8) ? sh[tid] : 0.f;
        #pragma unroll
        for (int off = 4; off; off >>= 1) t += __shfl_xor_sync(~0u, t, off);
        if (tid == 0) sh[0] = t;
    }
    __syncthreads();
    const float mu = sh[0] * (1.f / NE);
    __syncthreads();

    const float d0 = v0 - mu, d1 = v1 - mu;
    s = d0 * d0 + d1 * d1;
    #pragma unroll
    for (int off = 16; off; off >>= 1) s += __shfl_xor_sync(~0u, s, off);
    if ((tid & 31) == 0) sh[tid >> 5] = s;
    __syncthreads();
    if (tid < 32) {
        float t = (tid < 8) ? sh[tid] : 0.f;
        #pragma unroll
        for (int off = 4; off; off >>= 1) t += __shfl_xor_sync(~0u, t, off);
        if (tid == 0) sh[0] = t;
    }
    __syncthreads();
    const float var = sh[0] * (1.f / NE);
    const float inv = 1.f / sqrtf(var + 1e-5f);

    o[(size_t)row * NE + tid]       = d0 * inv * g[tid]       + b[tid];
    o[(size_t)row * NE + tid + 256] = d1 * inv * g[tid + 256] + b[tid + 256];
}

// --------------------------------------------------- pack Wk|Wq|Wv, biases -
__global__ void concat_w(const float* __restrict__ Wk, const float* __restrict__ Wq,
                         const float* __restrict__ Wv, const float* __restrict__ bk,
                         const float* __restrict__ bq, const float* __restrict__ bv) {
    const int idx = blockIdx.x * 256 + threadIdx.x;
    if (idx < NE * NHD) {
        const int r = idx / NHD, c = idx % NHD;
        g_Wkqv[(size_t)r * 1536 + c]        = Wk[idx];
        g_Wkqv[(size_t)r * 1536 + 512 + c]  = Wq[idx];
        g_Wkqv[(size_t)r * 1536 + 1024 + c] = Wv[idx];
    }
    if (idx < NHD) {
        g_bkqv[idx] = bk[idx];
        g_bkqv[512 + idx] = bq[idx];
        g_bkqv[1024 + idx] = bv[idx];
    }
}

// ------------------------------------------ transpose small proj weights ---
__global__ void prep_small(const float* __restrict__ Wd,  const float* __restrict__ bd,
                           const float* __restrict__ Wgw, const float* __restrict__ bgw,
                           const float* __restrict__ Wgf, const float* __restrict__ bgf) {
    const int idx = blockIdx.x * 256 + threadIdx.x;
    if (idx < 24 * NE) {
        const int c = idx / NE, k = idx % NE, cc = c & 7;
        const float* W = (c < 8) ? Wd : ((c < 16) ? Wgw : Wgf);
        g_Wt[idx] = W[k * NH + cc];
    }
    if (idx < 24) {
        const int cc = idx & 7;
        const float* bb = (idx < 8) ? bd : ((idx < 16) ? bgw : bgf);
        g_bsm[idx] = bb[cc];
    }
}

// ----------------------------------------------------------- tf32 helpers --
__device__ __forceinline__ unsigned int to_tf32(float f) {
    unsigned int r;
    asm("cvt.rna.tf32.f32 %0, %1;" : "=r"(r) : "f"(f));
    return r;
}

__device__ __forceinline__ void mma_tf32(float* d,
                                         unsigned int a0, unsigned int a1,
                                         unsigned int a2, unsigned int a3,
                                         unsigned int b0, unsigned int b1) {
    asm volatile(
        "mma.sync.aligned.m16n8k8.row.col.f32.tf32.tf32.f32 "
        "{%0,%1,%2,%3}, {%4,%5,%6,%7}, {%8,%9}, {%0,%1,%2,%3};"
        : "+f"(d[0]), "+f"(d[1]), "+f"(d[2]), "+f"(d[3])
        : "r"(a0), "r"(a1), "r"(a2), "r"(a3), "r"(b0), "r"(b1));
}

// ------------------------------------ tf32 tensor-core GEMM with epilogues -
// MODE 0: C = A@B + bias
// MODE 1: C = A@B + bias + aux1 + 0.1*aux2
// MODE 2: C = gelu_exact(A@B + bias)
// MODE 3: C = A@B + bias + aux1
// MODE 4: C = aux1 + v; C2 = aux2 + v
#define APAD 36
#define BPAD 136
template <int MODE>
__global__ __launch_bounds__(256) void tgemm_k(
    const float* __restrict__ A, const float* __restrict__ B,
    const float* __restrict__ bias, float* __restrict__ C,
    int K, int N, int ldc,
    const float* __restrict__ aux1, const float* __restrict__ aux2,
    float* __restrict__ C2) {
    __shared__ unsigned int As[128][APAD];   // [m][k], pad 36 (bank-safe)
    __shared__ unsigned int Bs[32][BPAD];    // [k][n], pad 136 (bank-safe)

    const int tid  = threadIdx.x;
    const int warp = tid >> 5, lane = tid & 31;
    const int g    = lane >> 2, tg = lane & 3;
    const int wm   = warp >> 1, wn = warp & 1;
    const int mBase = blockIdx.y * 128;
    const int nBase = blockIdx.x * 128;

    float acc[2][8][4];
    #pragma unroll
    for (int mt = 0; mt < 2; mt++)
        #pragma unroll
        for (int nt = 0; nt < 8; nt++)
            #pragma unroll
            for (int e = 0; e < 4; e++) acc[mt][nt][e] = 0.f;

    for (int ks = 0; ks < K; ks += 32) {
        // stage A: 128 rows x 32 cols (tf32-converted)
        #pragma unroll
        for (int i = 0; i < 4; i++) {
            const int idx = tid + 256 * i;
            const int row = idx >> 3, c4 = (idx & 7) << 2;
            const float4 v = *(const float4*)(A + (size_t)(mBase + row) * K + ks + c4);
            uint4 u;
            u.x = to_tf32(v.x); u.y = to_tf32(v.y);
            u.z = to_tf32(v.z); u.w = to_tf32(v.w);
            *(uint4*)&As[row][c4] = u;
        }
        // stage B: 32 rows x 128 cols
        #pragma unroll
        for (int i = 0; i < 4; i++) {
            const int idx = tid + 256 * i;
            const int row = idx >> 5, c4 = (idx & 31) << 2;
            const float4 v = *(const float4*)(B + (size_t)(ks + row) * N + nBase + c4);
            uint4 u;
            u.x = to_tf32(v.x); u.y = to_tf32(v.y);
            u.z = to_tf32(v.z); u.w = to_tf32(v.w);
            *(uint4*)&Bs[row][c4] = u;
        }
        __syncthreads();

        #pragma unroll
        for (int k8 = 0; k8 < 4; k8++) {
            const int kk = k8 << 3;
            unsigned int bf[8][2];
            #pragma unroll
            for (int nt = 0; nt < 8; nt++) {
                const int n = wn * 64 + nt * 8 + g;
                bf[nt][0] = Bs[kk + tg][n];
                bf[nt][1] = Bs[kk + tg + 4][n];
            }
            #pragma unroll
            for (int mt = 0; mt < 2; mt++) {
                const int m = wm * 32 + mt * 16;
                const unsigned int a0 = As[m + g][kk + tg];
                const unsigned int a1 = As[m + g + 8][kk + tg];
                const unsigned int a2 = As[m + g][kk + tg + 4];
                const unsigned int a3 = As[m + g + 8][kk + tg + 4];
                #pragma unroll
                for (int nt = 0; nt < 8; nt++)
                    mma_tf32(acc[mt][nt], a0, a1, a2, a3, bf[nt][0], bf[nt][1]);
            }
        }
        __syncthreads();
    }

    // epilogue
    #pragma unroll
    for (int mt = 0; mt < 2; mt++) {
        const int r0 = mBase + wm * 32 + mt * 16 + g;
        const int r1 = r0 + 8;
        #pragma unroll
        for (int nt = 0; nt < 8; nt++) {
            const int col = nBase + wn * 64 + nt * 8 + 2 * tg;
            const float b0 = bias[col], b1 = bias[col + 1];
            float e00 = acc[mt][nt][0] + b0, e01 = acc[mt][nt][1] + b1;
            float e10 = acc[mt][nt][2] + b0, e11 = acc[mt][nt][3] + b1;
            const size_t i0 = (size_t)r0 * ldc + col;
            const size_t i1 = (size_t)r1 * ldc + col;
            if (MODE == 0) {
                *(float2*)&C[i0] = make_float2(e00, e01);
                *(float2*)&C[i1] = make_float2(e10, e11);
            } else if (MODE == 1) {
                const float2 a0v = *(const float2*)&aux1[i0];
                const float2 a1v = *(const float2*)&aux1[i1];
                const float2 m0v = *(const float2*)&aux2[i0];
                const float2 m1v = *(const float2*)&aux2[i1];
                *(float2*)&C[i0] = make_float2(e00 + a0v.x + 0.1f * m0v.x,
                                               e01 + a0v.y + 0.1f * m0v.y);
                *(float2*)&C[i1] = make_float2(e10 + a1v.x + 0.1f * m1v.x,
                                               e11 + a1v.y + 0.1f * m1v.y);
            } else if (MODE == 2) {
                e00 = 0.5f * e00 * (1.f + erff(e00 * 0.7071067811865475f));
                e01 = 0.5f * e01 * (1.f + erff(e01 * 0.7071067811865475f));
                e10 = 0.5f * e10 * (1.f + erff(e10 * 0.7071067811865475f));
                e11 = 0.5f * e11 * (1.f + erff(e11 * 0.7071067811865475f));
                *(float2*)&C[i0] = make_float2(e00, e01);
                *(float2*)&C[i1] = make_float2(e10, e11);
            } else if (MODE == 3) {
                const float2 a0v = *(const float2*)&aux1[i0];
                const float2 a1v = *(const float2*)&aux1[i1];
                *(float2*)&C[i0] = make_float2(e00 + a0v.x, e01 + a0v.y);
                *(float2*)&C[i1] = make_float2(e10 + a1v.x, e11 + a1v.y);
            } else {
                const float2 p0 = *(const float2*)&aux1[i0];
                const float2 p1 = *(const float2*)&aux1[i1];
                const float2 q0 = *(const float2*)&aux2[i0];
                const float2 q1 = *(const float2*)&aux2[i1];
                *(float2*)&C[i0]  = make_float2(p0.x + e00, p0.y + e01);
                *(float2*)&C[i1]  = make_float2(p1.x + e10, p1.y + e11);
                *(float2*)&C2[i0] = make_float2(q0.x + e00, q0.y + e01);
                *(float2*)&C2[i1] = make_float2(q1.x + e10, q1.y + e11);
            }
        }
    }
}

// ------------------------------------------ k/q l2norm + v tanh (per head) -
__global__ __launch_bounds__(32) void act_k() {
    const int rowh = blockIdx.x;
    const int row = rowh >> 3, h = rowh & 7, lane = threadIdx.x;
    float* base = g_kqv + (size_t)row * 1536 + h * 64;
    #pragma unroll
    for (int p = 0; p < 2; p++) {
        float* ptr = base + p * 512;
        const float a = ptr[lane], c = ptr[lane + 32];
        float ss = a * a + c * c;
        #pragma unroll
        for (int off = 16; off; off >>= 1) ss += __shfl_xor_sync(~0u, ss, off);
        const float inv = 1.f / fmaxf(sqrtf(ss), 1e-12f);
        ptr[lane] = a * inv;
        ptr[lane + 32] = c * inv;
    }
    float* ptr = base + 1024;
    ptr[lane]      = tanhf(ptr[lane]);
    ptr[lane + 32] = tanhf(ptr[lane + 32]);
}

// ------------------ d/gw/gf projection (coalesced) + gate math -------------
__global__ __launch_bounds__(96) void proj_small_k() {
    __shared__ float sh[24];
    const int row = blockIdx.x, tid = threadIdx.x;
    const int warp = tid >> 5, lane = tid & 31;

    float acc[8];
    #pragma unroll
    for (int c = 0; c < 8; c++) acc[c] = 0.f;
    const float* xr = g_xn + (size_t)row * NE;
    const float* Wb = g_Wt + warp * 8 * NE;
    #pragma unroll 4
    for (int i = 0; i < 16; i++) {
        const int k = lane + 32 * i;
        const float xv = xr[k];
        #pragma unroll
        for (int c = 0; c < 8; c++) acc[c] = fmaf(xv, Wb[c * NE + k], acc[c]);
    }
    #pragma unroll
    for (int off = 16; off; off >>= 1)
        #pragma unroll
        for (int c = 0; c < 8; c++) acc[c] += __shfl_xor_sync(~0u, acc[c], off);
    if (lane < 8) sh[warp * 8 + lane] = acc[lane] + g_bsm[warp * 8 + lane];
    __syncthreads();
    if (tid < NH) {
        const float xd = sh[tid], xgw = sh[8 + tid], xgf = sh[16 + tid];
        const float d  = fmaxf(xd, 0.f) + log1pf(expf(-fabsf(xd)));   // softplus
        const float sw = 1.f / (1.f + expf(-xgw));
        const float sf = 1.f / (1.f + expf(-xgf));
        const float gw = sw * sw;
        const float gf = 1.f - sf * sf;
        g_coef[row * NH + tid] = d * gw;
        const float dec = fminf(fmaxf(d * gf, 1e-6f), 0.999f);
        g_logd[row * NH + tid] = logf(dec);
    }
}

// ------------------- sequential cumsum of log-decay (exact fp32 underflow) -
__global__ void cumsum_k() {
    const int s = threadIdx.x;
    if (s >= NB * NH) return;
    const int b = s >> 3, h = s & 7;
    float c = 0.f;
    for (int t = 0; t < NT; t++) {
        c += g_logd[(b * NT + t) * NH + h];
        const float e = expf(c);             // underflows to 0 exactly like ref
        g_ecum[s * NT + t] = e;
        g_invd[s * NT + t] = 1.f / (e + 1e-8f);
    }
}

// ------------------------------------------------- state scan + readout ----
__global__ __launch_bounds__(256) void scan_k(float* __restrict__ next_mem) {
    __shared__ float ks[64][64];
    __shared__ float qs[64][64];
    __shared__ float a_s[8][64];
    __shared__ float es[64];
    const int bh = blockIdx.y, b = bh >> 3, h = bh & 7;
    const int warp = threadIdx.x >> 5, lane = threadIdx.x & 31;
    const int i = blockIdx.x * 8 + warp;
    const int tid = threadIdx.x;
    float cum0 = 0.f, cum1 = 0.f;

    for (int t0 = 0; t0 < NT; t0 += 64) {
        #pragma unroll
        for (int f = 0; f < 4; f++) {
            const int e4 = f * 256 + tid;
            const int tt = e4 >> 4, j4 = (e4 & 15) << 2;
            const float* rp = g_kqv + (size_t)(b * NT + t0 + tt) * 1536 + h * 64;
            *(float4*)&ks[tt][j4] = *(const float4*)(rp + j4);
            *(float4*)&qs[tt][j4] = *(const float4*)(rp + 512 + j4);
        }
        #pragma unroll
        for (int u = 0; u < 2; u++) {
            const int tt = lane + u * 32;
            const int row = b * NT + t0 + tt;
            const float vv = g_kqv[(size_t)row * 1536 + 1024 + h * 64 + i];
            a_s[warp][tt] = vv * g_coef[row * NH + h] * g_invd[bh * NT + t0 + tt];
            if (warp == 0) es[tt] = g_ecum[bh * NT + t0 + tt];
        }
        __syncthreads();
        #pragma unroll 4
        for (int tt = 0; tt < 64; tt++) {
            const float a = a_s[warp][tt];
            cum0 = fmaf(a, ks[tt][lane], cum0);
            cum1 = fmaf(a, ks[tt][lane + 32], cum1);
            float r = cum0 * qs[tt][lane] + cum1 * qs[tt][lane + 32];
            #pragma unroll
            for (int off = 16; off; off >>= 1) r += __shfl_xor_sync(~0u, r, off);
            if (lane == 0)
                g_read[(size_t)(b * NT + t0 + tt) * NHD + h * 64 + i] = r * es[tt];
        }
        __syncthreads();
    }
    const float e = g_ecum[bh * NT + NT - 1];
    const size_t base = ((size_t)(b * NH + h) * ND + i) * ND;
    next_mem[base + lane]      = cum0 * e;
    next_mem[base + lane + 32] = cum1 * e;
}

// ---------------------------------------------------------------- launch ---
static float* sym(const void* s) {
    void* p = nullptr;
    cudaGetSymbolAddress(&p, s);
    return (float*)p;
}

extern "C" void kernel_launch(void* const* d_in, const int* in_sizes, int n_in,
                              void* d_out, int out_size) {
    const float* x     = (const float*)d_in[0];
    const float* b_min = (const float*)d_in[1];
    const float* b_max = (const float*)d_in[2];
    const float* motif = (const float*)d_in[3];
    const float* Wk    = (const float*)d_in[4];
    const float* bk    = (const float*)d_in[5];
    const float* Wq    = (const float*)d_in[6];
    const float* bq    = (const float*)d_in[7];
    const float* Wv    = (const float*)d_in[8];
    const float* bv    = (const float*)d_in[9];
    const float* Wo    = (const float*)d_in[10];
    const float* bo    = (const float*)d_in[11];
    const float* Wd    = (const float*)d_in[12];
    const float* bd    = (const float*)d_in[13];
    const float* Wgw   = (const float*)d_in[14];
    const float* bgw   = (const float*)d_in[15];
    const float* Wgf   = (const float*)d_in[16];
    const float* bgf   = (const float*)d_in[17];
    const float* Wps   = (const float*)d_in[18];
    const float* bps   = (const float*)d_in[19];
    const float* ln1g  = (const float*)d_in[20];
    const float* ln1b  = (const float*)d_in[21];
    const float* ln2g  = (const float*)d_in[22];
    const float* ln2b  = (const float*)d_in[23];
    const float* W1    = (const float*)d_in[24];
    const float* b1    = (const float*)d_in[25];
    const float* W2    = (const float*)d_in[26];
    const float* b2    = (const float*)d_in[27];

    float* out    = (float*)d_out;
    float* out_x3 = out;                            // [2,1024,512]
    float* out_nm = out + (size_t)NROWS * NE;       // [2,8,64,64]
    float* out_pm = out_nm + NB * NH * ND * ND;     // b_min + probe
    float* out_px = out_pm + (size_t)NROWS * NE;    // b_max + probe

    float* xn   = sym(g_xn);
    float* Wkqv = sym(g_Wkqv);
    float* bkqv = sym(g_bkqv);
    float* kqv  = sym(g_kqv);
    float* rd   = sym(g_read);
    float* x2   = sym(g_x2);
    float* hh   = sym(g_hh);
    float* mid  = sym(g_mid);

    // Phase A: LN1 + packed QKV projection + activations + gates
    ln_k<<<NROWS, 256>>>(x, ln1g, ln1b, xn);
    concat_w<<<(NE * NHD + 255) / 256, 256>>>(Wk, Wq, Wv, bk, bq, bv);
    prep_small<<<(24 * NE + 255) / 256, 256>>>(Wd, bd, Wgw, bgw, Wgf, bgf);
    tgemm_k<0><<<dim3(12, 16), 256>>>(xn, Wkqv, bkqv, kqv, 512, 1536, 1536,
                                      nullptr, nullptr, nullptr);
    proj_small_k<<<NROWS, 96>>>();
    cumsum_k<<<1, 32>>>();
    act_k<<<NROWS * NH, 32>>>();

    // Phase B: state scan -> readout + next_mem
    scan_k<<<dim3(8, 16), 256>>>(out_nm);

    // Phase C: out-proj + residual + motif, LN2, FFN, probe
    tgemm_k<1><<<dim3(4, 16), 256>>>(rd, Wo, bo, x2, 512, 512, 512,
                                     x, motif, nullptr);
    ln_k<<<NROWS, 256>>>(x2, ln2g, ln2b, hh);
    tgemm_k<2><<<dim3(16, 16), 256>>>(hh, W1, b1, mid, 512, 2048, 2048,
                                      nullptr, nullptr, nullptr);
    tgemm_k<3><<<dim3(4, 16), 256>>>(mid, W2, b2, out_x3, 2048, 512, 512,
                                     x2, nullptr, nullptr);
    tgemm_k<4><<<dim3(4, 16), 256>>>(out_x3, Wps, bps, out_pm, 512, 512, 512,
                                     b_min, b_max, out_px);
}

// round 3
// speedup vs baseline: 3.2893x; 1.8662x over previous
#include <cuda_runtime.h>
#include <math.h>

#define NE    512
#define NH    8
#define ND    64
#define NB    2
#define NT    1024
#define NHD   512
#define NROWS 2048          // B*T
#define NFFN  2048

// ------------------------------ scratch (static device globals; no allocs) --
static __device__ float g_xn  [NROWS * NE];          // LN1 output
static __device__ float g_Wkqv[NE * 3 * NHD];        // packed [Wk|Wq|Wv]
static __device__ float g_bkqv[3 * NHD];
static __device__ float g_kqv [NROWS * 3 * NHD];     // raw k|q|v (pre-activation)
static __device__ float g_coef[NROWS * NH];          // d*gw
static __device__ float g_logd[NROWS * NH];          // log(clip(d*gf))
static __device__ float g_ecum[NB * NH * NT];        // exp(cumsum(log decay))
static __device__ float g_invd[NB * NH * NT];        // 1/(ecum+1e-8)
static __device__ float g_read[NROWS * NHD];         // readout
static __device__ float g_x2  [NROWS * NE];
static __device__ float g_hh  [NROWS * NE];          // LN2 output
static __device__ float g_mid [NROWS * NFFN];        // gelu(h@W1+b1)
static __device__ float g_Wt  [24 * NE];             // transposed small weights
static __device__ float g_bsm [24];

// ------------------------------------------------------------- LayerNorm ---
__global__ __launch_bounds__(256) void ln_k(const float* __restrict__ x,
                                            const float* __restrict__ g,
                                            const float* __restrict__ b,
                                            float* __restrict__ o) {
    __shared__ float sh[8];
    const int row = blockIdx.x, tid = threadIdx.x;
    const float v0 = x[(size_t)row * NE + tid];
    const float v1 = x[(size_t)row * NE + tid + 256];

    float s = v0 + v1;
    #pragma unroll
    for (int off = 16; off; off >>= 1) s += __shfl_xor_sync(~0u, s, off);
    if ((tid & 31) == 0) sh[tid >> 5] = s;
    __syncthreads();
    if (tid < 32) {
        float t = (tid < 8) ? sh[tid] : 0.f;
        #pragma unroll
        for (int off = 4; off; off >>= 1) t += __shfl_xor_sync(~0u, t, off);
        if (tid == 0) sh[0] = t;
    }
    __syncthreads();
    const float mu = sh[0] * (1.f / NE);
    __syncthreads();

    const float d0 = v0 - mu, d1 = v1 - mu;
    s = d0 * d0 + d1 * d1;
    #pragma unroll
    for (int off = 16; off; off >>= 1) s += __shfl_xor_sync(~0u, s, off);
    if ((tid & 31) == 0) sh[tid >> 5] = s;
    __syncthreads();
    if (tid < 32) {
        float t = (tid < 8) ? sh[tid] : 0.f;
        #pragma unroll
        for (int off = 4; off; off >>= 1) t += __shfl_xor_sync(~0u, t, off);
        if (tid == 0) sh[0] = t;
    }
    __syncthreads();
    const float var = sh[0] * (1.f / NE);
    const float inv = 1.f / sqrtf(var + 1e-5f);

    o[(size_t)row * NE + tid]       = d0 * inv * g[tid]       + b[tid];
    o[(size_t)row * NE + tid + 256] = d1 * inv * g[tid + 256] + b[tid + 256];
}

// ----------------------- pack Wk|Wq|Wv + transpose small proj weights ------
__global__ void prep_all(const float* __restrict__ Wk, const float* __restrict__ Wq,
                         const float* __restrict__ Wv, const float* __restrict__ bk,
                         const float* __restrict__ bq, const float* __restrict__ bv,
                         const float* __restrict__ Wd,  const float* __restrict__ bd,
                         const float* __restrict__ Wgw, const float* __restrict__ bgw,
                         const float* __restrict__ Wgf, const float* __restrict__ bgf) {
    const int idx = blockIdx.x * 256 + threadIdx.x;
    if (idx < NE * NHD) {
        const int r = idx / NHD, c = idx % NHD;
        g_Wkqv[(size_t)r * 1536 + c]        = Wk[idx];
        g_Wkqv[(size_t)r * 1536 + 512 + c]  = Wq[idx];
        g_Wkqv[(size_t)r * 1536 + 1024 + c] = Wv[idx];
    }
    if (idx < NHD) {
        g_bkqv[idx] = bk[idx];
        g_bkqv[512 + idx] = bq[idx];
        g_bkqv[1024 + idx] = bv[idx];
    }
    if (idx < 24 * NE) {
        const int c = idx / NE, k = idx % NE, cc = c & 7;
        const float* W = (c < 8) ? Wd : ((c < 16) ? Wgw : Wgf);
        g_Wt[idx] = W[k * NH + cc];
    }
    if (idx < 24) {
        const int cc = idx & 7;
        const float* bb = (idx < 8) ? bd : ((idx < 16) ? bgw : bgf);
        g_bsm[idx] = bb[cc];
    }
}

// ----------------------------------------------------- mma + cp.async ------
__device__ __forceinline__ void mma_tf32(float* d,
                                         unsigned int a0, unsigned int a1,
                                         unsigned int a2, unsigned int a3,
                                         unsigned int b0, unsigned int b1) {
    asm volatile(
        "mma.sync.aligned.m16n8k8.row.col.f32.tf32.tf32.f32 "
        "{%0,%1,%2,%3}, {%4,%5,%6,%7}, {%8,%9}, {%0,%1,%2,%3};"
        : "+f"(d[0]), "+f"(d[1]), "+f"(d[2]), "+f"(d[3])
        : "r"(a0), "r"(a1), "r"(a2), "r"(a3), "r"(b0), "r"(b1));
}

__device__ __forceinline__ void cpasync16(void* s, const void* g) {
    unsigned int sa = (unsigned int)__cvta_generic_to_shared(s);
    asm volatile("cp.async.cg.shared.global [%0], [%1], 16;" :: "r"(sa), "l"(g));
}
#define CP_COMMIT()  asm volatile("cp.async.commit_group;")
#define CP_WAIT(n)   asm volatile("cp.async.wait_group %0;" :: "n"(n))

// ---------------- tf32 tensor-core GEMM, cp.async double-buffered ----------
// MODE 0: C = A@B + bias
// MODE 1: C = A@B + bias + aux1 + 0.1*aux2
// MODE 2: C = gelu_exact(A@B + bias)
// MODE 3: C = A@B + bias + aux1
// MODE 4: C = aux1 + v; C2 = aux2 + v
#define APAD 36
template <int MODE, int BN>
__global__ __launch_bounds__(256) void tgemm_k(
    const float* __restrict__ A, const float* __restrict__ B,
    const float* __restrict__ bias, float* __restrict__ C,
    int K, int N, int ldc,
    const float* __restrict__ aux1, const float* __restrict__ aux2,
    float* __restrict__ C2) {
    constexpr int BPAD = BN + 8;
    constexpr int MT   = (BN == 128) ? 2 : 1;
    extern __shared__ float sm[];
    float* Abuf = sm;                        // 2 stages of [128][APAD]
    float* Bbuf = sm + 2 * 128 * APAD;       // 2 stages of [32][BPAD]

    const int tid  = threadIdx.x;
    const int warp = tid >> 5, lane = tid & 31;
    const int g    = lane >> 2, tg = lane & 3;
    const int wm   = (BN == 128) ? (warp >> 1) : warp;
    const int wn   = (BN == 128) ? (warp & 1)  : 0;
    const int mBase = blockIdx.y * 128;
    const int nBase = blockIdx.x * BN;

    float acc[MT][8][4];
    #pragma unroll
    for (int mt = 0; mt < MT; mt++)
        #pragma unroll
        for (int nt = 0; nt < 8; nt++)
            #pragma unroll
            for (int e = 0; e < 4; e++) acc[mt][nt][e] = 0.f;

    const int nT = K >> 5;                    // K / 32 stages
    const int aRow = tid >> 3, aC4 = (tid & 7) << 2;      // +256: 32 rows step
    constexpr int BQ = BN / 4;                            // float4 per B row
    const int bRow = tid / BQ, bC4 = (tid % BQ) << 2;
    constexpr int BROWSTEP = 256 / BQ;

    auto load_stage = [&](int t, int st) {
        const int ks = t << 5;
        float* As = Abuf + st * 128 * APAD;
        float* Bs = Bbuf + st * 32 * BPAD;
        #pragma unroll
        for (int i = 0; i < 4; i++) {
            const int row = aRow + 32 * i;
            cpasync16(&As[row * APAD + aC4],
                      A + (size_t)(mBase + row) * K + ks + aC4);
        }
        #pragma unroll
        for (int i = 0; i < 32 / BROWSTEP; i++) {
            const int row = bRow + BROWSTEP * i;
            cpasync16(&Bs[row * BPAD + bC4],
                      B + (size_t)(ks + row) * N + nBase + bC4);
        }
        CP_COMMIT();
    };

    load_stage(0, 0);

    for (int t = 0; t < nT; t++) {
        if (t + 1 < nT) {
            load_stage(t + 1, (t + 1) & 1);
            CP_WAIT(1);
        } else {
            CP_WAIT(0);
        }
        __syncthreads();
        const float* As = Abuf + (t & 1) * 128 * APAD;
        const float* Bs = Bbuf + (t & 1) * 32 * BPAD;

        #pragma unroll
        for (int k8 = 0; k8 < 4; k8++) {
            const int kk = k8 << 3;
            unsigned int bf[8][2];
            #pragma unroll
            for (int nt = 0; nt < 8; nt++) {
                const int n = wn * 64 + nt * 8 + g;
                bf[nt][0] = __float_as_uint(Bs[(kk + tg) * BPAD + n]);
                bf[nt][1] = __float_as_uint(Bs[(kk + tg + 4) * BPAD + n]);
            }
            #pragma unroll
            for (int mt = 0; mt < MT; mt++) {
                const int m = (BN == 128) ? (wm * 32 + mt * 16) : (wm * 16);
                const unsigned int a0 = __float_as_uint(As[(m + g) * APAD + kk + tg]);
                const unsigned int a1 = __float_as_uint(As[(m + g + 8) * APAD + kk + tg]);
                const unsigned int a2 = __float_as_uint(As[(m + g) * APAD + kk + tg + 4]);
                const unsigned int a3 = __float_as_uint(As[(m + g + 8) * APAD + kk + tg + 4]);
                #pragma unroll
                for (int nt = 0; nt < 8; nt++)
                    mma_tf32(acc[mt][nt], a0, a1, a2, a3, bf[nt][0], bf[nt][1]);
            }
        }
        __syncthreads();
    }

    // epilogue
    #pragma unroll
    for (int mt = 0; mt < MT; mt++) {
        const int r0 = mBase + ((BN == 128) ? (wm * 32 + mt * 16) : (wm * 16)) + g;
        const int r1 = r0 + 8;
        #pragma unroll
        for (int nt = 0; nt < 8; nt++) {
            const int col = nBase + wn * 64 + nt * 8 + 2 * tg;
            const float b0 = bias[col], b1 = bias[col + 1];
            float e00 = acc[mt][nt][0] + b0, e01 = acc[mt][nt][1] + b1;
            float e10 = acc[mt][nt][2] + b0, e11 = acc[mt][nt][3] + b1;
            const size_t i0 = (size_t)r0 * ldc + col;
            const size_t i1 = (size_t)r1 * ldc + col;
            if (MODE == 0) {
                *(float2*)&C[i0] = make_float2(e00, e01);
                *(float2*)&C[i1] = make_float2(e10, e11);
            } else if (MODE == 1) {
                const float2 a0v = *(const float2*)&aux1[i0];
                const float2 a1v = *(const float2*)&aux1[i1];
                const float2 m0v = *(const float2*)&aux2[i0];
                const float2 m1v = *(const float2*)&aux2[i1];
                *(float2*)&C[i0] = make_float2(e00 + a0v.x + 0.1f * m0v.x,
                                               e01 + a0v.y + 0.1f * m0v.y);
                *(float2*)&C[i1] = make_float2(e10 + a1v.x + 0.1f * m1v.x,
                                               e11 + a1v.y + 0.1f * m1v.y);
            } else if (MODE == 2) {
                e00 = 0.5f * e00 * (1.f + erff(e00 * 0.7071067811865475f));
                e01 = 0.5f * e01 * (1.f + erff(e01 * 0.7071067811865475f));
                e10 = 0.5f * e10 * (1.f + erff(e10 * 0.7071067811865475f));
                e11 = 0.5f * e11 * (1.f + erff(e11 * 0.7071067811865475f));
                *(float2*)&C[i0] = make_float2(e00, e01);
                *(float2*)&C[i1] = make_float2(e10, e11);
            } else if (MODE == 3) {
                const float2 a0v = *(const float2*)&aux1[i0];
                const float2 a1v = *(const float2*)&aux1[i1];
                *(float2*)&C[i0] = make_float2(e00 + a0v.x, e01 + a0v.y);
                *(float2*)&C[i1] = make_float2(e10 + a1v.x, e11 + a1v.y);
            } else {
                const float2 p0 = *(const float2*)&aux1[i0];
                const float2 p1 = *(const float2*)&aux1[i1];
                const float2 q0 = *(const float2*)&aux2[i0];
                const float2 q1 = *(const float2*)&aux2[i1];
                *(float2*)&C[i0]  = make_float2(p0.x + e00, p0.y + e01);
                *(float2*)&C[i1]  = make_float2(p1.x + e10, p1.y + e11);
                *(float2*)&C2[i0] = make_float2(q0.x + e00, q0.y + e01);
                *(float2*)&C2[i1] = make_float2(q1.x + e10, q1.y + e11);
            }
        }
    }
}

// ------------------ d/gw/gf projection (coalesced) + gate math -------------
__global__ __launch_bounds__(96) void proj_small_k() {
    __shared__ float sh[24];
    const int row = blockIdx.x, tid = threadIdx.x;
    const int warp = tid >> 5, lane = tid & 31;

    float acc[8];
    #pragma unroll
    for (int c = 0; c < 8; c++) acc[c] = 0.f;
    const float* xr = g_xn + (size_t)row * NE;
    const float* Wb = g_Wt + warp * 8 * NE;
    #pragma unroll 4
    for (int i = 0; i < 16; i++) {
        const int k = lane + 32 * i;
        const float xv = xr[k];
        #pragma unroll
        for (int c = 0; c < 8; c++) acc[c] = fmaf(xv, Wb[c * NE + k], acc[c]);
    }
    #pragma unroll
    for (int off = 16; off; off >>= 1)
        #pragma unroll
        for (int c = 0; c < 8; c++) acc[c] += __shfl_xor_sync(~0u, acc[c], off);
    if (lane < 8) sh[warp * 8 + lane] = acc[lane] + g_bsm[warp * 8 + lane];
    __syncthreads();
    if (tid < NH) {
        const float xd = sh[tid], xgw = sh[8 + tid], xgf = sh[16 + tid];
        const float d  = fmaxf(xd, 0.f) + log1pf(expf(-fabsf(xd)));   // softplus
        const float sw = 1.f / (1.f + expf(-xgw));
        const float sf = 1.f / (1.f + expf(-xgf));
        const float gw = sw * sw;
        const float gf = 1.f - sf * sf;
        g_coef[row * NH + tid] = d * gw;
        const float dec = fminf(fmaxf(d * gf, 1e-6f), 0.999f);
        g_logd[row * NH + tid] = logf(dec);
    }
}

// ------- cumsum of log-decay: smem-staged serial chain + parallel exp ------
__global__ __launch_bounds__(256) void cumsum_k() {
    __shared__ float s[NT];
    __shared__ float c[NT];
    const int bh = blockIdx.x, b = bh >> 3, h = bh & 7;
    const int tid = threadIdx.x;
    for (int t = tid; t < NT; t += 256)
        s[t] = g_logd[(b * NT + t) * NH + h];
    __syncthreads();
    if (tid == 0) {
        float acc = 0.f;
        #pragma unroll 8
        for (int t = 0; t < NT; t++) { acc += s[t]; c[t] = acc; }
    }
    __syncthreads();
    for (int t = tid; t < NT; t += 256) {
        const float e = expf(c[t]);          // underflows to 0 exactly like ref
        g_ecum[bh * NT + t] = e;
        g_invd[bh * NT + t] = 1.f / (e + 1e-8f);
    }
}

// ----------------- state scan + readout (norm/tanh fused in) ---------------
#define KP 68
__global__ __launch_bounds__(256) void scan_k(float* __restrict__ next_mem) {
    __shared__ float ks[64][KP];
    __shared__ float qs[64][KP];
    __shared__ float a_s[8][64];
    __shared__ float es[64];
    const int bh = blockIdx.y, b = bh >> 3, h = bh & 7;
    const int warp = threadIdx.x >> 5, lane = threadIdx.x & 31;
    const int i = blockIdx.x * 8 + warp;
    const int tid = threadIdx.x;
    const int nr = tid >> 2, nq = tid & 3;           // norm: 4 thr per row
    float cum0 = 0.f, cum1 = 0.f;

    for (int t0 = 0; t0 < NT; t0 += 64) {
        // stage raw k/q
        #pragma unroll
        for (int f = 0; f < 4; f++) {
            const int e4 = f * 256 + tid;
            const int tt = e4 >> 4, j4 = (e4 & 15) << 2;
            const float* rp = g_kqv + (size_t)(b * NT + t0 + tt) * 1536 + h * 64;
            *(float4*)&ks[tt][j4] = *(const float4*)(rp + j4);
            *(float4*)&qs[tt][j4] = *(const float4*)(rp + 512 + j4);
        }
        // a_s from raw v (tanh fused), es
        #pragma unroll
        for (int u = 0; u < 2; u++) {
            const int tt = lane + u * 32;
            const int row = b * NT + t0 + tt;
            const float vv = tanhf(g_kqv[(size_t)row * 1536 + 1024 + h * 64 + i]);
            a_s[warp][tt] = vv * g_coef[row * NH + h] * g_invd[bh * NT + t0 + tt];
            if (warp == 0) es[tt] = g_ecum[bh * NT + t0 + tt];
        }
        __syncthreads();
        // l2-normalize k and q rows in smem (4 threads per row)
        {
            float sk = 0.f, sq = 0.f;
            #pragma unroll
            for (int e = 0; e < 16; e++) {
                const float kv = ks[nr][nq * 16 + e];
                const float qv = qs[nr][nq * 16 + e];
                sk = fmaf(kv, kv, sk);
                sq = fmaf(qv, qv, sq);
            }
            sk += __shfl_xor_sync(~0u, sk, 1); sk += __shfl_xor_sync(~0u, sk, 2);
            sq += __shfl_xor_sync(~0u, sq, 1); sq += __shfl_xor_sync(~0u, sq, 2);
            const float ik = 1.f / fmaxf(sqrtf(sk), 1e-12f);
            const float iq = 1.f / fmaxf(sqrtf(sq), 1e-12f);
            #pragma unroll
            for (int e = 0; e < 16; e++) {
                ks[nr][nq * 16 + e] *= ik;
                qs[nr][nq * 16 + e] *= iq;
            }
        }
        __syncthreads();
        #pragma unroll 4
        for (int tt = 0; tt < 64; tt++) {
            const float a = a_s[warp][tt];
            cum0 = fmaf(a, ks[tt][lane], cum0);
            cum1 = fmaf(a, ks[tt][lane + 32], cum1);
            float r = cum0 * qs[tt][lane] + cum1 * qs[tt][lane + 32];
            #pragma unroll
            for (int off = 16; off; off >>= 1) r += __shfl_xor_sync(~0u, r, off);
            if (lane == 0)
                g_read[(size_t)(b * NT + t0 + tt) * NHD + h * 64 + i] = r * es[tt];
        }
        __syncthreads();
    }
    const float e = g_ecum[bh * NT + NT - 1];
    const size_t base = ((size_t)(b * NH + h) * ND + i) * ND;
    next_mem[base + lane]      = cum0 * e;
    next_mem[base + lane + 32] = cum1 * e;
}

// ---------------------------------------------------------------- launch ---
static float* sym(const void* s) {
    void* p = nullptr;
    cudaGetSymbolAddress(&p, s);
    return (float*)p;
}

extern "C" void kernel_launch(void* const* d_in, const int* in_sizes, int n_in,
                              void* d_out, int out_size) {
    const float* x     = (const float*)d_in[0];
    const float* b_min = (const float*)d_in[1];
    const float* b_max = (const float*)d_in[2];
    const float* motif = (const float*)d_in[3];
    const float* Wk    = (const float*)d_in[4];
    const float* bk    = (const float*)d_in[5];
    const float* Wq    = (const float*)d_in[6];
    const float* bq    = (const float*)d_in[7];
    const float* Wv    = (const float*)d_in[8];
    const float* bv    = (const float*)d_in[9];
    const float* Wo    = (const float*)d_in[10];
    const float* bo    = (const float*)d_in[11];
    const float* Wd    = (const float*)d_in[12];
    const float* bd    = (const float*)d_in[13];
    const float* Wgw   = (const float*)d_in[14];
    const float* bgw   = (const float*)d_in[15];
    const float* Wgf   = (const float*)d_in[16];
    const float* bgf   = (const float*)d_in[17];
    const float* Wps   = (const float*)d_in[18];
    const float* bps   = (const float*)d_in[19];
    const float* ln1g  = (const float*)d_in[20];
    const float* ln1b  = (const float*)d_in[21];
    const float* ln2g  = (const float*)d_in[22];
    const float* ln2b  = (const float*)d_in[23];
    const float* W1    = (const float*)d_in[24];
    const float* b1    = (const float*)d_in[25];
    const float* W2    = (const float*)d_in[26];
    const float* b2    = (const float*)d_in[27];

    float* out    = (float*)d_out;
    float* out_x3 = out;                            // [2,1024,512]
    float* out_nm = out + (size_t)NROWS * NE;       // [2,8,64,64]
    float* out_pm = out_nm + NB * NH * ND * ND;     // b_min + probe
    float* out_px = out_pm + (size_t)NROWS * NE;    // b_max + probe

    float* xn   = sym(g_xn);
    float* Wkqv = sym(g_Wkqv);
    float* bkqv = sym(g_bkqv);
    float* kqv  = sym(g_kqv);
    float* rd   = sym(g_read);
    float* x2   = sym(g_x2);
    float* hh   = sym(g_hh);
    float* mid  = sym(g_mid);

    const int SM128 = (2 * 128 * APAD + 2 * 32 * 136) * 4;   // 71680
    const int SM64  = (2 * 128 * APAD + 2 * 32 * 72)  * 4;   // 55296
    cudaFuncSetAttribute(tgemm_k<0,128>, cudaFuncAttributeMaxDynamicSharedMemorySize, SM128);
    cudaFuncSetAttribute(tgemm_k<2,128>, cudaFuncAttributeMaxDynamicSharedMemorySize, SM128);
    cudaFuncSetAttribute(tgemm_k<1,64>,  cudaFuncAttributeMaxDynamicSharedMemorySize, SM64);
    cudaFuncSetAttribute(tgemm_k<3,64>,  cudaFuncAttributeMaxDynamicSharedMemorySize, SM64);
    cudaFuncSetAttribute(tgemm_k<4,64>,  cudaFuncAttributeMaxDynamicSharedMemorySize, SM64);

    // launch order chosen so ncu (-s 5 -c 1) captures scan_k
    ln_k<<<NROWS, 256>>>(x, ln1g, ln1b, xn);                                   // 0
    prep_all<<<(NE * NHD + 255) / 256, 256>>>(Wk, Wq, Wv, bk, bq, bv,
                                              Wd, bd, Wgw, bgw, Wgf, bgf);     // 1
    tgemm_k<0,128><<<dim3(12, 16), 256, SM128>>>(xn, Wkqv, bkqv, kqv,
                                                 512, 1536, 1536,
                                                 nullptr, nullptr, nullptr);   // 2
    proj_small_k<<<NROWS, 96>>>();                                             // 3
    cumsum_k<<<NB * NH, 256>>>();                                              // 4
    scan_k<<<dim3(8, 16), 256>>>(out_nm);                                      // 5  <- profiled

    tgemm_k<1,64><<<dim3(8, 16), 256, SM64>>>(rd, Wo, bo, x2, 512, 512, 512,
                                              x, motif, nullptr);              // 6
    ln_k<<<NROWS, 256>>>(x2, ln2g, ln2b, hh);                                  // 7
    tgemm_k<2,128><<<dim3(16, 16), 256, SM128>>>(hh, W1, b1, mid,
                                                 512, 2048, 2048,
                                                 nullptr, nullptr, nullptr);   // 8
    tgemm_k<3,64><<<dim3(8, 16), 256, SM64>>>(mid, W2, b2, out_x3,
                                              2048, 512, 512,
                                              x2, nullptr, nullptr);           // 9
    tgemm_k<4,64><<<dim3(8, 16), 256, SM64>>>(out_x3, Wps, bps, out_pm,
                                              512, 512, 512,
                                              b_min, b_max, out_px);           // 10
}

// round 4
// speedup vs baseline: 3.6124x; 1.0982x over previous
#include <cuda_runtime.h>
#include <math.h>

#define NE    512
#define NH    8
#define ND    64
#define NB    2
#define NT    1024
#define NHD   512
#define NROWS 2048          // B*T
#define NFFN  2048
#define NBH   16
#define NC    16            // chunks of 64 along T

// ------------------------------ scratch (static device globals; no allocs) --
static __device__ float g_xn  [NROWS * NE];          // LN1 output
static __device__ float g_Wkqv[NE * 3 * NHD];        // packed [Wk|Wq|Wv]
static __device__ float g_bkqv[3 * NHD];
static __device__ float g_kqv [NROWS * 3 * NHD];     // raw k|q|v (pre-activation)
static __device__ float g_coef[NROWS * NH];          // d*gw
static __device__ float g_logd[NROWS * NH];          // log(clip(d*gf))
static __device__ float g_ecum[NBH * NT];            // exp(cumsum(log decay))
static __device__ float g_invd[NBH * NT];            // 1/(ecum+1e-8)
static __device__ float g_read[NROWS * NHD];         // readout
static __device__ float g_x2  [NROWS * NE];
static __device__ float g_hh  [NROWS * NE];          // LN2 output
static __device__ float g_mid [NROWS * NFFN];        // gelu(h@W1+b1)
static __device__ float g_Wt  [24 * NE];             // transposed small weights
static __device__ float g_bsm [24];
static __device__ float g_qn  [NBH * NT * 64];       // normalized q
static __device__ float g_S   [NBH * NC * 64 * 64];  // per-chunk state sums
static __device__ float g_P   [NBH * NC * 64 * 64];  // exclusive prefixes

// ------------------------------------------------------------- LayerNorm ---
__global__ __launch_bounds__(256) void ln_k(const float* __restrict__ x,
                                            const float* __restrict__ g,
                                            const float* __restrict__ b,
                                            float* __restrict__ o) {
    __shared__ float sh[8];
    const int row = blockIdx.x, tid = threadIdx.x;
    const float v0 = x[(size_t)row * NE + tid];
    const float v1 = x[(size_t)row * NE + tid + 256];

    float s = v0 + v1;
    #pragma unroll
    for (int off = 16; off; off >>= 1) s += __shfl_xor_sync(~0u, s, off);
    if ((tid & 31) == 0) sh[tid >> 5] = s;
    __syncthreads();
    if (tid < 32) {
        float t = (tid < 8) ? sh[tid] : 0.f;
        #pragma unroll
        for (int off = 4; off; off >>= 1) t += __shfl_xor_sync(~0u, t, off);
        if (tid == 0) sh[0] = t;
    }
    __syncthreads();
    const float mu = sh[0] * (1.f / NE);
    __syncthreads();

    const float d0 = v0 - mu, d1 = v1 - mu;
    s = d0 * d0 + d1 * d1;
    #pragma unroll
    for (int off = 16; off; off >>= 1) s += __shfl_xor_sync(~0u, s, off);
    if ((tid & 31) == 0) sh[tid >> 5] = s;
    __syncthreads();
    if (tid < 32) {
        float t = (tid < 8) ? sh[tid] : 0.f;
        #pragma unroll
        for (int off = 4; off; off >>= 1) t += __shfl_xor_sync(~0u, t, off);
        if (tid == 0) sh[0] = t;
    }
    __syncthreads();
    const float var = sh[0] * (1.f / NE);
    const float inv = 1.f / sqrtf(var + 1e-5f);

    o[(size_t)row * NE + tid]       = d0 * inv * g[tid]       + b[tid];
    o[(size_t)row * NE + tid + 256] = d1 * inv * g[tid + 256] + b[tid + 256];
}

// ----------------------- pack Wk|Wq|Wv + transpose small proj weights ------
__global__ void prep_all(const float* __restrict__ Wk, const float* __restrict__ Wq,
                         const float* __restrict__ Wv, const float* __restrict__ bk,
                         const float* __restrict__ bq, const float* __restrict__ bv,
                         const float* __restrict__ Wd,  const float* __restrict__ bd,
                         const float* __restrict__ Wgw, const float* __restrict__ bgw,
                         const float* __restrict__ Wgf, const float* __restrict__ bgf) {
    const int idx = blockIdx.x * 256 + threadIdx.x;
    if (idx < NE * NHD) {
        const int r = idx / NHD, c = idx % NHD;
        g_Wkqv[(size_t)r * 1536 + c]        = Wk[idx];
        g_Wkqv[(size_t)r * 1536 + 512 + c]  = Wq[idx];
        g_Wkqv[(size_t)r * 1536 + 1024 + c] = Wv[idx];
    }
    if (idx < NHD) {
        g_bkqv[idx] = bk[idx];
        g_bkqv[512 + idx] = bq[idx];
        g_bkqv[1024 + idx] = bv[idx];
    }
    if (idx < 24 * NE) {
        const int c = idx / NE, k = idx % NE, cc = c & 7;
        const float* W = (c < 8) ? Wd : ((c < 16) ? Wgw : Wgf);
        g_Wt[idx] = W[k * NH + cc];
    }
    if (idx < 24) {
        const int cc = idx & 7;
        const float* bb = (idx < 8) ? bd : ((idx < 16) ? bgw : bgf);
        g_bsm[idx] = bb[cc];
    }
}

// ----------------------------------------------------- mma + cp.async ------
__device__ __forceinline__ void mma_tf32(float* d,
                                         unsigned int a0, unsigned int a1,
                                         unsigned int a2, unsigned int a3,
                                         unsigned int b0, unsigned int b1) {
    asm volatile(
        "mma.sync.aligned.m16n8k8.row.col.f32.tf32.tf32.f32 "
        "{%0,%1,%2,%3}, {%4,%5,%6,%7}, {%8,%9}, {%0,%1,%2,%3};"
        : "+f"(d[0]), "+f"(d[1]), "+f"(d[2]), "+f"(d[3])
        : "r"(a0), "r"(a1), "r"(a2), "r"(a3), "r"(b0), "r"(b1));
}

__device__ __forceinline__ void cpasync16(void* s, const void* g) {
    unsigned int sa = (unsigned int)__cvta_generic_to_shared(s);
    asm volatile("cp.async.cg.shared.global [%0], [%1], 16;" :: "r"(sa), "l"(g));
}
#define CP_COMMIT()  asm volatile("cp.async.commit_group;")
#define CP_WAIT(n)   asm volatile("cp.async.wait_group %0;" :: "n"(n))

// ---------------- tf32 tensor-core GEMM, cp.async double-buffered ----------
#define APAD 36
template <int MODE, int BN>
__global__ __launch_bounds__(256) void tgemm_k(
    const float* __restrict__ A, const float* __restrict__ B,
    const float* __restrict__ bias, float* __restrict__ C,
    int K, int N, int ldc,
    const float* __restrict__ aux1, const float* __restrict__ aux2,
    float* __restrict__ C2) {
    constexpr int BPAD = BN + 8;
    constexpr int MT   = (BN == 128) ? 2 : 1;
    extern __shared__ float sm[];
    float* Abuf = sm;
    float* Bbuf = sm + 2 * 128 * APAD;

    const int tid  = threadIdx.x;
    const int warp = tid >> 5, lane = tid & 31;
    const int g    = lane >> 2, tg = lane & 3;
    const int wm   = (BN == 128) ? (warp >> 1) : warp;
    const int wn   = (BN == 128) ? (warp & 1)  : 0;
    const int mBase = blockIdx.y * 128;
    const int nBase = blockIdx.x * BN;

    float acc[MT][8][4];
    #pragma unroll
    for (int mt = 0; mt < MT; mt++)
        #pragma unroll
        for (int nt = 0; nt < 8; nt++)
            #pragma unroll
            for (int e = 0; e < 4; e++) acc[mt][nt][e] = 0.f;

    const int nT = K >> 5;
    const int aRow = tid >> 3, aC4 = (tid & 7) << 2;
    constexpr int BQ = BN / 4;
    const int bRow = tid / BQ, bC4 = (tid % BQ) << 2;
    constexpr int BROWSTEP = 256 / BQ;

    auto load_stage = [&](int t, int st) {
        const int ks = t << 5;
        float* As = Abuf + st * 128 * APAD;
        float* Bs = Bbuf + st * 32 * BPAD;
        #pragma unroll
        for (int i = 0; i < 4; i++) {
            const int row = aRow + 32 * i;
            cpasync16(&As[row * APAD + aC4],
                      A + (size_t)(mBase + row) * K + ks + aC4);
        }
        #pragma unroll
        for (int i = 0; i < 32 / BROWSTEP; i++) {
            const int row = bRow + BROWSTEP * i;
            cpasync16(&Bs[row * BPAD + bC4],
                      B + (size_t)(ks + row) * N + nBase + bC4);
        }
        CP_COMMIT();
    };

    load_stage(0, 0);

    for (int t = 0; t < nT; t++) {
        if (t + 1 < nT) {
            load_stage(t + 1, (t + 1) & 1);
            CP_WAIT(1);
        } else {
            CP_WAIT(0);
        }
        __syncthreads();
        const float* As = Abuf + (t & 1) * 128 * APAD;
        const float* Bs = Bbuf + (t & 1) * 32 * BPAD;

        #pragma unroll
        for (int k8 = 0; k8 < 4; k8++) {
            const int kk = k8 << 3;
            unsigned int bf[8][2];
            #pragma unroll
            for (int nt = 0; nt < 8; nt++) {
                const int n = wn * 64 + nt * 8 + g;
                bf[nt][0] = __float_as_uint(Bs[(kk + tg) * BPAD + n]);
                bf[nt][1] = __float_as_uint(Bs[(kk + tg + 4) * BPAD + n]);
            }
            #pragma unroll
            for (int mt = 0; mt < MT; mt++) {
                const int m = (BN == 128) ? (wm * 32 + mt * 16) : (wm * 16);
                const unsigned int a0 = __float_as_uint(As[(m + g) * APAD + kk + tg]);
                const unsigned int a1 = __float_as_uint(As[(m + g + 8) * APAD + kk + tg]);
                const unsigned int a2 = __float_as_uint(As[(m + g) * APAD + kk + tg + 4]);
                const unsigned int a3 = __float_as_uint(As[(m + g + 8) * APAD + kk + tg + 4]);
                #pragma unroll
                for (int nt = 0; nt < 8; nt++)
                    mma_tf32(acc[mt][nt], a0, a1, a2, a3, bf[nt][0], bf[nt][1]);
            }
        }
        __syncthreads();
    }

    #pragma unroll
    for (int mt = 0; mt < MT; mt++) {
        const int r0 = mBase + ((BN == 128) ? (wm * 32 + mt * 16) : (wm * 16)) + g;
        const int r1 = r0 + 8;
        #pragma unroll
        for (int nt = 0; nt < 8; nt++) {
            const int col = nBase + wn * 64 + nt * 8 + 2 * tg;
            const float b0 = bias[col], b1 = bias[col + 1];
            float e00 = acc[mt][nt][0] + b0, e01 = acc[mt][nt][1] + b1;
            float e10 = acc[mt][nt][2] + b0, e11 = acc[mt][nt][3] + b1;
            const size_t i0 = (size_t)r0 * ldc + col;
            const size_t i1 = (size_t)r1 * ldc + col;
            if (MODE == 0) {
                *(float2*)&C[i0] = make_float2(e00, e01);
                *(float2*)&C[i1] = make_float2(e10, e11);
            } else if (MODE == 1) {
                const float2 a0v = *(const float2*)&aux1[i0];
                const float2 a1v = *(const float2*)&aux1[i1];
                const float2 m0v = *(const float2*)&aux2[i0];
                const float2 m1v = *(const float2*)&aux2[i1];
                *(float2*)&C[i0] = make_float2(e00 + a0v.x + 0.1f * m0v.x,
                                               e01 + a0v.y + 0.1f * m0v.y);
                *(float2*)&C[i1] = make_float2(e10 + a1v.x + 0.1f * m1v.x,
                                               e11 + a1v.y + 0.1f * m1v.y);
            } else if (MODE == 2) {
                e00 = 0.5f * e00 * (1.f + erff(e00 * 0.7071067811865475f));
                e01 = 0.5f * e01 * (1.f + erff(e01 * 0.7071067811865475f));
                e10 = 0.5f * e10 * (1.f + erff(e10 * 0.7071067811865475f));
                e11 = 0.5f * e11 * (1.f + erff(e11 * 0.7071067811865475f));
                *(float2*)&C[i0] = make_float2(e00, e01);
                *(float2*)&C[i1] = make_float2(e10, e11);
            } else if (MODE == 3) {
                const float2 a0v = *(const float2*)&aux1[i0];
                const float2 a1v = *(const float2*)&aux1[i1];
                *(float2*)&C[i0] = make_float2(e00 + a0v.x, e01 + a0v.y);
                *(float2*)&C[i1] = make_float2(e10 + a1v.x, e11 + a1v.y);
            } else {
                const float2 p0 = *(const float2*)&aux1[i0];
                const float2 p1 = *(const float2*)&aux1[i1];
                const float2 q0 = *(const float2*)&aux2[i0];
                const float2 q1 = *(const float2*)&aux2[i1];
                *(float2*)&C[i0]  = make_float2(p0.x + e00, p0.y + e01);
                *(float2*)&C[i1]  = make_float2(p1.x + e10, p1.y + e11);
                *(float2*)&C2[i0] = make_float2(q0.x + e00, q0.y + e01);
                *(float2*)&C2[i1] = make_float2(q1.x + e10, q1.y + e11);
            }
        }
    }
}

// --------- d/gw/gf projection: smem-staged weights, 16 rows per block ------
__global__ __launch_bounds__(96) void proj_small_k() {
    extern __shared__ float sw[];             // [24][512]
    __shared__ float sh[24];
    const int tid = threadIdx.x, warp = tid >> 5, lane = tid & 31;
    #pragma unroll
    for (int u = 0; u < 32; u++) {
        const int i4 = tid + 96 * u;          // 3072 float4 total
        *(float4*)&sw[i4 * 4] = *(const float4*)&g_Wt[i4 * 4];
    }
    __syncthreads();

    for (int rr = 0; rr < 16; rr++) {
        const int row = blockIdx.x * 16 + rr;
        const float* xr = g_xn + (size_t)row * NE;
        float acc[8];
        #pragma unroll
        for (int c = 0; c < 8; c++) acc[c] = 0.f;
        #pragma unroll 4
        for (int i = 0; i < 16; i++) {
            const int k = lane + 32 * i;
            const float xv = xr[k];
            #pragma unroll
            for (int c = 0; c < 8; c++)
                acc[c] = fmaf(xv, sw[(warp * 8 + c) * NE + k], acc[c]);
        }
        #pragma unroll
        for (int off = 16; off; off >>= 1)
            #pragma unroll
            for (int c = 0; c < 8; c++) acc[c] += __shfl_xor_sync(~0u, acc[c], off);
        if (lane < 8) sh[warp * 8 + lane] = acc[lane] + g_bsm[warp * 8 + lane];
        __syncthreads();
        if (tid < NH) {
            const float xd = sh[tid], xgw = sh[8 + tid], xgf = sh[16 + tid];
            const float d  = fmaxf(xd, 0.f) + log1pf(expf(-fabsf(xd)));
            const float swv = 1.f / (1.f + expf(-xgw));
            const float sfv = 1.f / (1.f + expf(-xgf));
            g_coef[row * NH + tid] = d * (swv * swv);
            const float dec = fminf(fmaxf(d * (1.f - sfv * sfv), 1e-6f), 0.999f);
            g_logd[row * NH + tid] = logf(dec);
        }
        __syncthreads();
    }
}

// ------- cumsum of log-decay: smem-staged serial chain + parallel exp ------
__global__ __launch_bounds__(256) void cumsum_k() {
    __shared__ float s[NT];
    __shared__ float c[NT];
    const int bh = blockIdx.x, b = bh >> 3, h = bh & 7;
    const int tid = threadIdx.x;
    for (int t = tid; t < NT; t += 256)
        s[t] = g_logd[(b * NT + t) * NH + h];
    __syncthreads();
    if (tid == 0) {
        float acc = 0.f;
        #pragma unroll 8
        for (int t = 0; t < NT; t++) { acc += s[t]; c[t] = acc; }
    }
    __syncthreads();
    for (int t = tid; t < NT; t += 256) {
        const float e = expf(c[t]);          // underflows to 0 exactly like ref
        g_ecum[bh * NT + t] = e;
        g_invd[bh * NT + t] = 1.f / (e + 1e-8f);
    }
}

// ============ chunked scan: phase 1 (per-chunk matmuls, no serial dep) =====
#define SP 68
__global__ __launch_bounds__(256) void scan_p1() {
    extern __shared__ float sm[];
    float* sK = sm;                 // [64][SP]
    float* sQ = sm + 64 * SP;
    float* sA = sm + 2 * 64 * SP;   // A[s][i] = tanh(v)*coef*invd
    float* sG = sm + 3 * 64 * SP;   // G[t][s] (causal)
    float* es = sm + 4 * 64 * SP;   // [64]
    const int tc = blockIdx.x, bh = blockIdx.y, b = bh >> 3, h = bh & 7;
    const int tid = threadIdx.x;

    // stage raw k/q + build A
    #pragma unroll
    for (int f = 0; f < 4; f++) {
        const int e4 = f * 256 + tid;
        const int tt = e4 >> 4, j4 = (e4 & 15) << 2;
        const int row = b * NT + tc * 64 + tt;
        const float* rp = g_kqv + (size_t)row * 1536 + h * 64;
        *(float4*)&sK[tt * SP + j4] = *(const float4*)(rp + j4);
        *(float4*)&sQ[tt * SP + j4] = *(const float4*)(rp + 512 + j4);
        const float4 v = *(const float4*)(rp + 1024 + j4);
        const float sc = g_coef[row * NH + h] * g_invd[bh * NT + tc * 64 + tt];
        float4 a4;
        a4.x = tanhf(v.x) * sc; a4.y = tanhf(v.y) * sc;
        a4.z = tanhf(v.z) * sc; a4.w = tanhf(v.w) * sc;
        *(float4*)&sA[tt * SP + j4] = a4;
    }
    if (tid < 64) es[tid] = g_ecum[bh * NT + tc * 64 + tid];
    __syncthreads();

    // l2-normalize K,Q rows (4 threads per row)
    {
        const int nr = tid >> 2, nq = tid & 3;
        float sk = 0.f, sq = 0.f;
        #pragma unroll
        for (int e = 0; e < 16; e++) {
            const float kv = sK[nr * SP + nq * 16 + e];
            const float qv = sQ[nr * SP + nq * 16 + e];
            sk = fmaf(kv, kv, sk);
            sq = fmaf(qv, qv, sq);
        }
        sk += __shfl_xor_sync(~0u, sk, 1); sk += __shfl_xor_sync(~0u, sk, 2);
        sq += __shfl_xor_sync(~0u, sq, 1); sq += __shfl_xor_sync(~0u, sq, 2);
        const float ik = 1.f / fmaxf(sqrtf(sk), 1e-12f);
        const float iq = 1.f / fmaxf(sqrtf(sq), 1e-12f);
        #pragma unroll
        for (int e = 0; e < 16; e++) {
            sK[nr * SP + nq * 16 + e] *= ik;
            sQ[nr * SP + nq * 16 + e] *= iq;
        }
    }
    __syncthreads();

    // save normalized Q for phase 3
    #pragma unroll
    for (int f = 0; f < 4; f++) {
        const int e4 = f * 256 + tid;
        const int tt = e4 >> 4, j4 = (e4 & 15) << 2;
        *(float4*)&g_qn[((size_t)bh * NT + tc * 64 + tt) * 64 + j4] =
            *(const float4*)&sQ[tt * SP + j4];
    }

    // S_c[i][j] = sum_s A[s][i] * K[s][j]
    {
        const int i4 = (tid & 15) * 4, j4 = (tid >> 4) * 4;
        float acc[4][4];
        #pragma unroll
        for (int a = 0; a < 4; a++)
            #pragma unroll
            for (int c = 0; c < 4; c++) acc[a][c] = 0.f;
        for (int s = 0; s < 64; s++) {
            float av[4], kv[4];
            #pragma unroll
            for (int a = 0; a < 4; a++) av[a] = sA[s * SP + i4 + a];
            #pragma unroll
            for (int c = 0; c < 4; c++) kv[c] = sK[s * SP + j4 + c];
            #pragma unroll
            for (int a = 0; a < 4; a++)
                #pragma unroll
                for (int c = 0; c < 4; c++) acc[a][c] = fmaf(av[a], kv[c], acc[a][c]);
        }
        float* Sp = g_S + ((size_t)bh * NC + tc) * 4096;
        #pragma unroll
        for (int a = 0; a < 4; a++)
            #pragma unroll
            for (int c = 0; c < 4; c++) Sp[(i4 + a) * 64 + j4 + c] = acc[a][c];
    }

    // G[t][s] = q_t . k_s  (causal)
    {
        const int t4 = (tid & 15) * 4, s4 = (tid >> 4) * 4;
        float acc[4][4];
        #pragma unroll
        for (int a = 0; a < 4; a++)
            #pragma unroll
            for (int c = 0; c < 4; c++) acc[a][c] = 0.f;
        if (s4 <= t4 + 3) {
            for (int j = 0; j < 64; j++) {
                float qv[4], kv[4];
                #pragma unroll
                for (int a = 0; a < 4; a++) qv[a] = sQ[(t4 + a) * SP + j];
                #pragma unroll
                for (int c = 0; c < 4; c++) kv[c] = sK[(s4 + c) * SP + j];
                #pragma unroll
                for (int a = 0; a < 4; a++)
                    #pragma unroll
                    for (int c = 0; c < 4; c++) acc[a][c] = fmaf(qv[a], kv[c], acc[a][c]);
            }
        }
        #pragma unroll
        for (int a = 0; a < 4; a++)
            #pragma unroll
            for (int c = 0; c < 4; c++)
                sG[(t4 + a) * SP + s4 + c] = (s4 + c <= t4 + a) ? acc[a][c] : 0.f;
    }
    __syncthreads();

    // r_local[t][i] = sum_{s<=t} G[t][s] * A[s][i]; store es_t * r_local
    {
        const int t4 = (tid & 15) * 4, i4 = (tid >> 4) * 4;
        float acc[4][4];
        #pragma unroll
        for (int a = 0; a < 4; a++)
            #pragma unroll
            for (int c = 0; c < 4; c++) acc[a][c] = 0.f;
        const int smax = t4 + 4;
        for (int s = 0; s < smax; s++) {
            float gv[4], av[4];
            #pragma unroll
            for (int a = 0; a < 4; a++) gv[a] = sG[(t4 + a) * SP + s];
            #pragma unroll
            for (int c = 0; c < 4; c++) av[c] = sA[s * SP + i4 + c];
            #pragma unroll
            for (int a = 0; a < 4; a++)
                #pragma unroll
                for (int c = 0; c < 4; c++) acc[a][c] = fmaf(gv[a], av[c], acc[a][c]);
        }
        #pragma unroll
        for (int a = 0; a < 4; a++) {
            const float e = es[t4 + a];
            const size_t ro = (size_t)(b * NT + tc * 64 + t4 + a) * NHD + h * 64;
            #pragma unroll
            for (int c = 0; c < 4; c++) g_read[ro + i4 + c] = e * acc[a][c];
        }
    }
}

// ============ phase 2: exclusive prefix of chunk sums + next_mem ===========
__global__ __launch_bounds__(256) void scan_p2(float* __restrict__ next_mem) {
    const int bh = blockIdx.x;
    const int e  = blockIdx.y * 256 + threadIdx.x;      // 0..4095
    const float elast = g_ecum[bh * NT + NT - 1];
    float acc = 0.f;
    #pragma unroll
    for (int c = 0; c < NC; c++) {
        g_P[((size_t)bh * NC + c) * 4096 + e] = acc;
        acc += g_S[((size_t)bh * NC + c) * 4096 + e];
    }
    next_mem[(size_t)bh * 4096 + e] = acc * elast;
}

// ============ phase 3: cross term r += es_t * (P_{c-1} q_t) ================
__global__ __launch_bounds__(256) void scan_p3() {
    __shared__ float sQ[64 * SP];
    __shared__ float sP[64 * SP];     // P[i][j]
    __shared__ float es[64];
    const int tc = blockIdx.x + 1, bh = blockIdx.y, b = bh >> 3, h = bh & 7;
    const int tid = threadIdx.x;
    #pragma unroll
    for (int f = 0; f < 4; f++) {
        const int e4 = f * 256 + tid;
        const int tt = e4 >> 4, j4 = (e4 & 15) << 2;
        *(float4*)&sQ[tt * SP + j4] =
            *(const float4*)&g_qn[((size_t)bh * NT + tc * 64 + tt) * 64 + j4];
        *(float4*)&sP[tt * SP + j4] =
            *(const float4*)&g_P[((size_t)bh * NC + tc) * 4096 + tt * 64 + j4];
    }
    if (tid < 64) es[tid] = g_ecum[bh * NT + tc * 64 + tid];
    __syncthreads();

    const int t4 = (tid & 15) * 4, i4 = (tid >> 4) * 4;
    float acc[4][4];
    #pragma unroll
    for (int a = 0; a < 4; a++)
        #pragma unroll
        for (int c = 0; c < 4; c++) acc[a][c] = 0.f;
    for (int j = 0; j < 64; j++) {
        float qv[4], pv[4];
        #pragma unroll
        for (int a = 0; a < 4; a++) qv[a] = sQ[(t4 + a) * SP + j];
        #pragma unroll
        for (int c = 0; c < 4; c++) pv[c] = sP[(i4 + c) * SP + j];
        #pragma unroll
        for (int a = 0; a < 4; a++)
            #pragma unroll
            for (int c = 0; c < 4; c++) acc[a][c] = fmaf(qv[a], pv[c], acc[a][c]);
    }
    #pragma unroll
    for (int a = 0; a < 4; a++) {
        const float e = es[t4 + a];
        const size_t ro = (size_t)(b * NT + tc * 64 + t4 + a) * NHD + h * 64;
        #pragma unroll
        for (int c = 0; c < 4; c++) g_read[ro + i4 + c] += e * acc[a][c];
    }
}

// ---------------------------------------------------------------- launch ---
static float* sym(const void* s) {
    void* p = nullptr;
    cudaGetSymbolAddress(&p, s);
    return (float*)p;
}

extern "C" void kernel_launch(void* const* d_in, const int* in_sizes, int n_in,
                              void* d_out, int out_size) {
    const float* x     = (const float*)d_in[0];
    const float* b_min = (const float*)d_in[1];
    const float* b_max = (const float*)d_in[2];
    const float* motif = (const float*)d_in[3];
    const float* Wk    = (const float*)d_in[4];
    const float* bk    = (const float*)d_in[5];
    const float* Wq    = (const float*)d_in[6];
    const float* bq    = (const float*)d_in[7];
    const float* Wv    = (const float*)d_in[8];
    const float* bv    = (const float*)d_in[9];
    const float* Wo    = (const float*)d_in[10];
    const float* bo    = (const float*)d_in[11];
    const float* Wd    = (const float*)d_in[12];
    const float* bd    = (const float*)d_in[13];
    const float* Wgw   = (const float*)d_in[14];
    const float* bgw   = (const float*)d_in[15];
    const float* Wgf   = (const float*)d_in[16];
    const float* bgf   = (const float*)d_in[17];
    const float* Wps   = (const float*)d_in[18];
    const float* bps   = (const float*)d_in[19];
    const float* ln1g  = (const float*)d_in[20];
    const float* ln1b  = (const float*)d_in[21];
    const float* ln2g  = (const float*)d_in[22];
    const float* ln2b  = (const float*)d_in[23];
    const float* W1    = (const float*)d_in[24];
    const float* b1    = (const float*)d_in[25];
    const float* W2    = (const float*)d_in[26];
    const float* b2    = (const float*)d_in[27];

    float* out    = (float*)d_out;
    float* out_x3 = out;                            // [2,1024,512]
    float* out_nm = out + (size_t)NROWS * NE;       // [2,8,64,64]
    float* out_pm = out_nm + NBH * ND * ND;         // b_min + probe
    float* out_px = out_pm + (size_t)NROWS * NE;    // b_max + probe

    float* xn   = sym(g_xn);
    float* Wkqv = sym(g_Wkqv);
    float* bkqv = sym(g_bkqv);
    float* kqv  = sym(g_kqv);
    float* rd   = sym(g_read);
    float* x2   = sym(g_x2);
    float* hh   = sym(g_hh);
    float* mid  = sym(g_mid);

    const int SM128 = (2 * 128 * APAD + 2 * 32 * 136) * 4;   // 71680
    const int SM64  = (2 * 128 * APAD + 2 * 32 * 72)  * 4;   // 55296
    const int SMP1  = (4 * 64 * SP + 64) * 4;                // 69888
    const int SMPRJ = 24 * NE * 4;                           // 49152
    cudaFuncSetAttribute(tgemm_k<0,128>, cudaFuncAttributeMaxDynamicSharedMemorySize, SM128);
    cudaFuncSetAttribute(tgemm_k<2,128>, cudaFuncAttributeMaxDynamicSharedMemorySize, SM128);
    cudaFuncSetAttribute(tgemm_k<1,64>,  cudaFuncAttributeMaxDynamicSharedMemorySize, SM64);
    cudaFuncSetAttribute(tgemm_k<3,64>,  cudaFuncAttributeMaxDynamicSharedMemorySize, SM64);
    cudaFuncSetAttribute(tgemm_k<4,64>,  cudaFuncAttributeMaxDynamicSharedMemorySize, SM64);
    cudaFuncSetAttribute(scan_p1,        cudaFuncAttributeMaxDynamicSharedMemorySize, SMP1);
    cudaFuncSetAttribute(proj_small_k,   cudaFuncAttributeMaxDynamicSharedMemorySize, SMPRJ);

    ln_k<<<NROWS, 256>>>(x, ln1g, ln1b, xn);
    prep_all<<<(NE * NHD + 255) / 256, 256>>>(Wk, Wq, Wv, bk, bq, bv,
                                              Wd, bd, Wgw, bgw, Wgf, bgf);
    tgemm_k<0,128><<<dim3(12, 16), 256, SM128>>>(xn, Wkqv, bkqv, kqv,
                                                 512, 1536, 1536,
                                                 nullptr, nullptr, nullptr);
    proj_small_k<<<NROWS / 16, 96, SMPRJ>>>();
    cumsum_k<<<NBH, 256>>>();
    scan_p1<<<dim3(NC, NBH), 256, SMP1>>>();
    scan_p2<<<dim3(NBH, 16), 256>>>(out_nm);
    scan_p3<<<dim3(NC - 1, NBH), 256>>>();

    tgemm_k<1,64><<<dim3(8, 16), 256, SM64>>>(rd, Wo, bo, x2, 512, 512, 512,
                                              x, motif, nullptr);
    ln_k<<<NROWS, 256>>>(x2, ln2g, ln2b, hh);
    tgemm_k<2,128><<<dim3(16, 16), 256, SM128>>>(hh, W1, b1, mid,
                                                 512, 2048, 2048,
                                                 nullptr, nullptr, nullptr);
    tgemm_k<3,64><<<dim3(8, 16), 256, SM64>>>(mid, W2, b2, out_x3,
                                              2048, 512, 512,
                                              x2, nullptr, nullptr);
    tgemm_k<4,64><<<dim3(8, 16), 256, SM64>>>(out_x3, Wps, bps, out_pm,
                                              512, 512, 512,
                                              b_min, b_max, out_px);
}

// round 5
// speedup vs baseline: 4.5501x; 1.2596x over previous
#include <cuda_runtime.h>
#include <math.h>

#define NE    512
#define NH    8
#define ND    64
#define NB    2
#define NT    1024
#define NHD   512
#define NROWS 2048          // B*T
#define NFFN  2048
#define NBH   16
#define NC    16            // chunks of 64 along T
#define LDW   1664          // packed fused-proj width (1536 kqv + 24 gates + pad)

// ------------------------------ scratch (static device globals; no allocs) --
static __device__ float g_xn  [NROWS * NE];          // LN1 output
static __device__ float g_Wkqv[NE * LDW];            // packed [Wk|Wq|Wv|Wd|Wgw|Wgf|0]
static __device__ float g_bkqv[LDW];
static __device__ float g_kqv [NROWS * LDW];         // raw k|q|v|gates (pre-activation)
static __device__ float g_coef[NROWS * NH];          // d*gw
static __device__ float g_logd[NROWS * NH];          // log(clip(d*gf))
static __device__ float g_ecum[NBH * NT];            // exp(cumsum(log decay))
static __device__ float g_invd[NBH * NT];            // 1/(ecum+1e-8)
static __device__ float g_read[NROWS * NHD];         // readout
static __device__ float g_x2  [NROWS * NE];
static __device__ float g_hh  [NROWS * NE];          // LN2 output
static __device__ float g_mid [NROWS * NFFN];        // gelu(h@W1+b1)
static __device__ float g_qn  [NBH * NT * 64];       // normalized q
static __device__ float g_S   [NBH * NC * 64 * 64];  // per-chunk state sums
static __device__ float g_P   [NBH * NC * 64 * 64];  // exclusive prefixes

// ------------------------------------------------------------- LayerNorm ---
__global__ __launch_bounds__(256) void ln_k(const float* __restrict__ x,
                                            const float* __restrict__ g,
                                            const float* __restrict__ b,
                                            float* __restrict__ o) {
    __shared__ float sh[8];
    const int row = blockIdx.x, tid = threadIdx.x;
    const float v0 = x[(size_t)row * NE + tid];
    const float v1 = x[(size_t)row * NE + tid + 256];

    float s = v0 + v1;
    #pragma unroll
    for (int off = 16; off; off >>= 1) s += __shfl_xor_sync(~0u, s, off);
    if ((tid & 31) == 0) sh[tid >> 5] = s;
    __syncthreads();
    if (tid < 32) {
        float t = (tid < 8) ? sh[tid] : 0.f;
        #pragma unroll
        for (int off = 4; off; off >>= 1) t += __shfl_xor_sync(~0u, t, off);
        if (tid == 0) sh[0] = t;
    }
    __syncthreads();
    const float mu = sh[0] * (1.f / NE);
    __syncthreads();

    const float d0 = v0 - mu, d1 = v1 - mu;
    s = d0 * d0 + d1 * d1;
    #pragma unroll
    for (int off = 16; off; off >>= 1) s += __shfl_xor_sync(~0u, s, off);
    if ((tid & 31) == 0) sh[tid >> 5] = s;
    __syncthreads();
    if (tid < 32) {
        float t = (tid < 8) ? sh[tid] : 0.f;
        #pragma unroll
        for (int off = 4; off; off >>= 1) t += __shfl_xor_sync(~0u, t, off);
        if (tid == 0) sh[0] = t;
    }
    __syncthreads();
    const float var = sh[0] * (1.f / NE);
    const float inv = 1.f / sqrtf(var + 1e-5f);

    o[(size_t)row * NE + tid]       = d0 * inv * g[tid]       + b[tid];
    o[(size_t)row * NE + tid + 256] = d1 * inv * g[tid + 256] + b[tid + 256];
}

// ------------- pack Wk|Wq|Wv|Wd|Wgw|Wgf (+zero pad) and biases -------------
__global__ void prep_all(const float* __restrict__ Wk, const float* __restrict__ Wq,
                         const float* __restrict__ Wv, const float* __restrict__ bk,
                         const float* __restrict__ bq, const float* __restrict__ bv,
                         const float* __restrict__ Wd,  const float* __restrict__ bd,
                         const float* __restrict__ Wgw, const float* __restrict__ bgw,
                         const float* __restrict__ Wgf, const float* __restrict__ bgf) {
    const int idx = blockIdx.x * 256 + threadIdx.x;    // over 512*1664
    if (idx >= NE * LDW) return;
    const int r = idx / LDW, c = idx % LDW;
    float w;
    if (c < 512)        w = Wk[r * NHD + c];
    else if (c < 1024)  w = Wq[r * NHD + (c - 512)];
    else if (c < 1536)  w = Wv[r * NHD + (c - 1024)];
    else if (c < 1544)  w = Wd [r * NH + (c - 1536)];
    else if (c < 1552)  w = Wgw[r * NH + (c - 1544)];
    else if (c < 1560)  w = Wgf[r * NH + (c - 1552)];
    else                w = 0.f;
    g_Wkqv[idx] = w;
    if (r == 0) {
        float bb;
        if (c < 512)        bb = bk[c];
        else if (c < 1024)  bb = bq[c - 512];
        else if (c < 1536)  bb = bv[c - 1024];
        else if (c < 1544)  bb = bd [c - 1536];
        else if (c < 1552)  bb = bgw[c - 1544];
        else if (c < 1560)  bb = bgf[c - 1552];
        else                bb = 0.f;
        g_bkqv[c] = bb;
    }
}

// ----------------------------------------------------- mma + cp.async ------
__device__ __forceinline__ void mma_tf32(float* d,
                                         unsigned int a0, unsigned int a1,
                                         unsigned int a2, unsigned int a3,
                                         unsigned int b0, unsigned int b1) {
    asm volatile(
        "mma.sync.aligned.m16n8k8.row.col.f32.tf32.tf32.f32 "
        "{%0,%1,%2,%3}, {%4,%5,%6,%7}, {%8,%9}, {%0,%1,%2,%3};"
        : "+f"(d[0]), "+f"(d[1]), "+f"(d[2]), "+f"(d[3])
        : "r"(a0), "r"(a1), "r"(a2), "r"(a3), "r"(b0), "r"(b1));
}

__device__ __forceinline__ void cpasync16(void* s, const void* g) {
    unsigned int sa = (unsigned int)__cvta_generic_to_shared(s);
    asm volatile("cp.async.cg.shared.global [%0], [%1], 16;" :: "r"(sa), "l"(g));
}
#define CP_COMMIT()  asm volatile("cp.async.commit_group;")
#define CP_WAIT(n)   asm volatile("cp.async.wait_group %0;" :: "n"(n))

// ---------------- tf32 tensor-core GEMM, cp.async double-buffered ----------
#define APAD 36
template <int MODE, int BN>
__global__ __launch_bounds__(256) void tgemm_k(
    const float* __restrict__ A, const float* __restrict__ B,
    const float* __restrict__ bias, float* __restrict__ C,
    int K, int N, int ldc,
    const float* __restrict__ aux1, const float* __restrict__ aux2,
    float* __restrict__ C2) {
    constexpr int BPAD = BN + 8;
    constexpr int MT   = (BN == 128) ? 2 : 1;
    extern __shared__ float sm[];
    float* Abuf = sm;
    float* Bbuf = sm + 2 * 128 * APAD;

    const int tid  = threadIdx.x;
    const int warp = tid >> 5, lane = tid & 31;
    const int g    = lane >> 2, tg = lane & 3;
    const int wm   = (BN == 128) ? (warp >> 1) : warp;
    const int wn   = (BN == 128) ? (warp & 1)  : 0;
    const int mBase = blockIdx.y * 128;
    const int nBase = blockIdx.x * BN;

    float acc[MT][8][4];
    #pragma unroll
    for (int mt = 0; mt < MT; mt++)
        #pragma unroll
        for (int nt = 0; nt < 8; nt++)
            #pragma unroll
            for (int e = 0; e < 4; e++) acc[mt][nt][e] = 0.f;

    const int nT = K >> 5;
    const int aRow = tid >> 3, aC4 = (tid & 7) << 2;
    constexpr int BQ = BN / 4;
    const int bRow = tid / BQ, bC4 = (tid % BQ) << 2;
    constexpr int BROWSTEP = 256 / BQ;

    auto load_stage = [&](int t, int st) {
        const int ks = t << 5;
        float* As = Abuf + st * 128 * APAD;
        float* Bs = Bbuf + st * 32 * BPAD;
        #pragma unroll
        for (int i = 0; i < 4; i++) {
            const int row = aRow + 32 * i;
            cpasync16(&As[row * APAD + aC4],
                      A + (size_t)(mBase + row) * K + ks + aC4);
        }
        #pragma unroll
        for (int i = 0; i < 32 / BROWSTEP; i++) {
            const int row = bRow + BROWSTEP * i;
            cpasync16(&Bs[row * BPAD + bC4],
                      B + (size_t)(ks + row) * N + nBase + bC4);
        }
        CP_COMMIT();
    };

    load_stage(0, 0);

    for (int t = 0; t < nT; t++) {
        if (t + 1 < nT) {
            load_stage(t + 1, (t + 1) & 1);
            CP_WAIT(1);
        } else {
            CP_WAIT(0);
        }
        __syncthreads();
        const float* As = Abuf + (t & 1) * 128 * APAD;
        const float* Bs = Bbuf + (t & 1) * 32 * BPAD;

        #pragma unroll
        for (int k8 = 0; k8 < 4; k8++) {
            const int kk = k8 << 3;
            unsigned int bf[8][2];
            #pragma unroll
            for (int nt = 0; nt < 8; nt++) {
                const int n = wn * 64 + nt * 8 + g;
                bf[nt][0] = __float_as_uint(Bs[(kk + tg) * BPAD + n]);
                bf[nt][1] = __float_as_uint(Bs[(kk + tg + 4) * BPAD + n]);
            }
            #pragma unroll
            for (int mt = 0; mt < MT; mt++) {
                const int m = (BN == 128) ? (wm * 32 + mt * 16) : (wm * 16);
                const unsigned int a0 = __float_as_uint(As[(m + g) * APAD + kk + tg]);
                const unsigned int a1 = __float_as_uint(As[(m + g + 8) * APAD + kk + tg]);
                const unsigned int a2 = __float_as_uint(As[(m + g) * APAD + kk + tg + 4]);
                const unsigned int a3 = __float_as_uint(As[(m + g + 8) * APAD + kk + tg + 4]);
                #pragma unroll
                for (int nt = 0; nt < 8; nt++)
                    mma_tf32(acc[mt][nt], a0, a1, a2, a3, bf[nt][0], bf[nt][1]);
            }
        }
        __syncthreads();
    }

    #pragma unroll
    for (int mt = 0; mt < MT; mt++) {
        const int r0 = mBase + ((BN == 128) ? (wm * 32 + mt * 16) : (wm * 16)) + g;
        const int r1 = r0 + 8;
        #pragma unroll
        for (int nt = 0; nt < 8; nt++) {
            const int col = nBase + wn * 64 + nt * 8 + 2 * tg;
            const float b0 = bias[col], b1 = bias[col + 1];
            float e00 = acc[mt][nt][0] + b0, e01 = acc[mt][nt][1] + b1;
            float e10 = acc[mt][nt][2] + b0, e11 = acc[mt][nt][3] + b1;
            const size_t i0 = (size_t)r0 * ldc + col;
            const size_t i1 = (size_t)r1 * ldc + col;
            if (MODE == 0) {
                *(float2*)&C[i0] = make_float2(e00, e01);
                *(float2*)&C[i1] = make_float2(e10, e11);
            } else if (MODE == 1) {
                const float2 a0v = *(const float2*)&aux1[i0];
                const float2 a1v = *(const float2*)&aux1[i1];
                const float2 m0v = *(const float2*)&aux2[i0];
                const float2 m1v = *(const float2*)&aux2[i1];
                *(float2*)&C[i0] = make_float2(e00 + a0v.x + 0.1f * m0v.x,
                                               e01 + a0v.y + 0.1f * m0v.y);
                *(float2*)&C[i1] = make_float2(e10 + a1v.x + 0.1f * m1v.x,
                                               e11 + a1v.y + 0.1f * m1v.y);
            } else if (MODE == 2) {
                e00 = 0.5f * e00 * (1.f + erff(e00 * 0.7071067811865475f));
                e01 = 0.5f * e01 * (1.f + erff(e01 * 0.7071067811865475f));
                e10 = 0.5f * e10 * (1.f + erff(e10 * 0.7071067811865475f));
                e11 = 0.5f * e11 * (1.f + erff(e11 * 0.7071067811865475f));
                *(float2*)&C[i0] = make_float2(e00, e01);
                *(float2*)&C[i1] = make_float2(e10, e11);
            } else if (MODE == 3) {
                const float2 a0v = *(const float2*)&aux1[i0];
                const float2 a1v = *(const float2*)&aux1[i1];
                *(float2*)&C[i0] = make_float2(e00 + a0v.x, e01 + a0v.y);
                *(float2*)&C[i1] = make_float2(e10 + a1v.x, e11 + a1v.y);
            } else {
                const float2 p0 = *(const float2*)&aux1[i0];
                const float2 p1 = *(const float2*)&aux1[i1];
                const float2 q0 = *(const float2*)&aux2[i0];
                const float2 q1 = *(const float2*)&aux2[i1];
                *(float2*)&C[i0]  = make_float2(p0.x + e00, p0.y + e01);
                *(float2*)&C[i1]  = make_float2(p1.x + e10, p1.y + e11);
                *(float2*)&C2[i0] = make_float2(q0.x + e00, q0.y + e01);
                *(float2*)&C2[i1] = make_float2(q1.x + e10, q1.y + e11);
            }
        }
    }
}

// ------------- gate math from fused GEMM outputs (cols 1536..1559) ---------
__global__ __launch_bounds__(256) void gate_k() {
    const int idx = blockIdx.x * 256 + threadIdx.x;    // row*NH + h
    if (idx >= NROWS * NH) return;
    const int row = idx >> 3, h = idx & 7;
    const float* gp = g_kqv + (size_t)row * LDW + 1536;
    const float xd = gp[h], xgw = gp[8 + h], xgf = gp[16 + h];
    const float d  = fmaxf(xd, 0.f) + log1pf(expf(-fabsf(xd)));   // softplus
    const float sw = 1.f / (1.f + expf(-xgw));
    const float sf = 1.f / (1.f + expf(-xgf));
    g_coef[idx] = d * (sw * sw);
    const float dec = fminf(fmaxf(d * (1.f - sf * sf), 1e-6f), 0.999f);
    g_logd[idx] = logf(dec);
}

// ------- cumsum of log-decay: smem-staged serial chain + parallel exp ------
__global__ __launch_bounds__(256) void cumsum_k() {
    __shared__ float s[NT];
    __shared__ float c[NT];
    const int bh = blockIdx.x, b = bh >> 3, h = bh & 7;
    const int tid = threadIdx.x;
    for (int t = tid; t < NT; t += 256)
        s[t] = g_logd[(b * NT + t) * NH + h];
    __syncthreads();
    if (tid == 0) {
        float acc = 0.f;
        #pragma unroll 8
        for (int t = 0; t < NT; t++) { acc += s[t]; c[t] = acc; }
    }
    __syncthreads();
    for (int t = tid; t < NT; t += 256) {
        const float e = expf(c[t]);          // underflows to 0 exactly like ref
        g_ecum[bh * NT + t] = e;
        g_invd[bh * NT + t] = 1.f / (e + 1e-8f);
    }
}

// ============ chunked scan: phase 1 (per-chunk matmuls, no serial dep) =====
#define SP 68
__global__ __launch_bounds__(256) void scan_p1() {
    extern __shared__ float sm[];
    float* sK = sm;                 // [64][SP]
    float* sQ = sm + 64 * SP;
    float* sA = sm + 2 * 64 * SP;   // A[s][i] = tanh(v)*coef*invd
    float* sG = sm + 3 * 64 * SP;   // G[t][s] (causal)
    float* es = sm + 4 * 64 * SP;   // [64]
    const int tc = blockIdx.x, bh = blockIdx.y, b = bh >> 3, h = bh & 7;
    const int tid = threadIdx.x;

    // stage raw k/q + build A
    #pragma unroll
    for (int f = 0; f < 4; f++) {
        const int e4 = f * 256 + tid;
        const int tt = e4 >> 4, j4 = (e4 & 15) << 2;
        const int row = b * NT + tc * 64 + tt;
        const float* rp = g_kqv + (size_t)row * LDW + h * 64;
        *(float4*)&sK[tt * SP + j4] = *(const float4*)(rp + j4);
        *(float4*)&sQ[tt * SP + j4] = *(const float4*)(rp + 512 + j4);
        const float4 v = *(const float4*)(rp + 1024 + j4);
        const float sc = g_coef[row * NH + h] * g_invd[bh * NT + tc * 64 + tt];
        float4 a4;
        a4.x = tanhf(v.x) * sc; a4.y = tanhf(v.y) * sc;
        a4.z = tanhf(v.z) * sc; a4.w = tanhf(v.w) * sc;
        *(float4*)&sA[tt * SP + j4] = a4;
    }
    if (tid < 64) es[tid] = g_ecum[bh * NT + tc * 64 + tid];
    __syncthreads();

    // l2-normalize K,Q rows (4 threads per row)
    {
        const int nr = tid >> 2, nq = tid & 3;
        float sk = 0.f, sq = 0.f;
        #pragma unroll
        for (int e = 0; e < 16; e++) {
            const float kv = sK[nr * SP + nq * 16 + e];
            const float qv = sQ[nr * SP + nq * 16 + e];
            sk = fmaf(kv, kv, sk);
            sq = fmaf(qv, qv, sq);
        }
        sk += __shfl_xor_sync(~0u, sk, 1); sk += __shfl_xor_sync(~0u, sk, 2);
        sq += __shfl_xor_sync(~0u, sq, 1); sq += __shfl_xor_sync(~0u, sq, 2);
        const float ik = 1.f / fmaxf(sqrtf(sk), 1e-12f);
        const float iq = 1.f / fmaxf(sqrtf(sq), 1e-12f);
        #pragma unroll
        for (int e = 0; e < 16; e++) {
            sK[nr * SP + nq * 16 + e] *= ik;
            sQ[nr * SP + nq * 16 + e] *= iq;
        }
    }
    __syncthreads();

    // save normalized Q for phase 3
    #pragma unroll
    for (int f = 0; f < 4; f++) {
        const int e4 = f * 256 + tid;
        const int tt = e4 >> 4, j4 = (e4 & 15) << 2;
        *(float4*)&g_qn[((size_t)bh * NT + tc * 64 + tt) * 64 + j4] =
            *(const float4*)&sQ[tt * SP + j4];
    }

    // S_c[i][j] = sum_s A[s][i] * K[s][j]
    {
        const int i4 = (tid & 15) * 4, j4 = (tid >> 4) * 4;
        float acc[4][4];
        #pragma unroll
        for (int a = 0; a < 4; a++)
            #pragma unroll
            for (int c = 0; c < 4; c++) acc[a][c] = 0.f;
        for (int s = 0; s < 64; s++) {
            float av[4], kv[4];
            #pragma unroll
            for (int a = 0; a < 4; a++) av[a] = sA[s * SP + i4 + a];
            #pragma unroll
            for (int c = 0; c < 4; c++) kv[c] = sK[s * SP + j4 + c];
            #pragma unroll
            for (int a = 0; a < 4; a++)
                #pragma unroll
                for (int c = 0; c < 4; c++) acc[a][c] = fmaf(av[a], kv[c], acc[a][c]);
        }
        float* Sp = g_S + ((size_t)bh * NC + tc) * 4096;
        #pragma unroll
        for (int a = 0; a < 4; a++)
            #pragma unroll
            for (int c = 0; c < 4; c++) Sp[(i4 + a) * 64 + j4 + c] = acc[a][c];
    }

    // G[t][s] = q_t . k_s  (causal)
    {
        const int t4 = (tid & 15) * 4, s4 = (tid >> 4) * 4;
        float acc[4][4];
        #pragma unroll
        for (int a = 0; a < 4; a++)
            #pragma unroll
            for (int c = 0; c < 4; c++) acc[a][c] = 0.f;
        if (s4 <= t4 + 3) {
            for (int j = 0; j < 64; j++) {
                float qv[4], kv[4];
                #pragma unroll
                for (int a = 0; a < 4; a++) qv[a] = sQ[(t4 + a) * SP + j];
                #pragma unroll
                for (int c = 0; c < 4; c++) kv[c] = sK[(s4 + c) * SP + j];
                #pragma unroll
                for (int a = 0; a < 4; a++)
                    #pragma unroll
                    for (int c = 0; c < 4; c++) acc[a][c] = fmaf(qv[a], kv[c], acc[a][c]);
            }
        }
        #pragma unroll
        for (int a = 0; a < 4; a++)
            #pragma unroll
            for (int c = 0; c < 4; c++)
                sG[(t4 + a) * SP + s4 + c] = (s4 + c <= t4 + a) ? acc[a][c] : 0.f;
    }
    __syncthreads();

    // r_local[t][i] = sum_{s<=t} G[t][s] * A[s][i]; store es_t * r_local
    {
        const int t4 = (tid & 15) * 4, i4 = (tid >> 4) * 4;
        float acc[4][4];
        #pragma unroll
        for (int a = 0; a < 4; a++)
            #pragma unroll
            for (int c = 0; c < 4; c++) acc[a][c] = 0.f;
        const int smax = t4 + 4;
        for (int s = 0; s < smax; s++) {
            float gv[4], av[4];
            #pragma unroll
            for (int a = 0; a < 4; a++) gv[a] = sG[(t4 + a) * SP + s];
            #pragma unroll
            for (int c = 0; c < 4; c++) av[c] = sA[s * SP + i4 + c];
            #pragma unroll
            for (int a = 0; a < 4; a++)
                #pragma unroll
                for (int c = 0; c < 4; c++) acc[a][c] = fmaf(gv[a], av[c], acc[a][c]);
        }
        #pragma unroll
        for (int a = 0; a < 4; a++) {
            const float e = es[t4 + a];
            const size_t ro = (size_t)(b * NT + tc * 64 + t4 + a) * NHD + h * 64;
            #pragma unroll
            for (int c = 0; c < 4; c++) g_read[ro + i4 + c] = e * acc[a][c];
        }
    }
}

// ============ phase 2: exclusive prefix of chunk sums + next_mem ===========
__global__ __launch_bounds__(256) void scan_p2(float* __restrict__ next_mem) {
    const int bh = blockIdx.x;
    const int e  = blockIdx.y * 256 + threadIdx.x;      // 0..4095
    const float elast = g_ecum[bh * NT + NT - 1];
    float acc = 0.f;
    #pragma unroll
    for (int c = 0; c < NC; c++) {
        g_P[((size_t)bh * NC + c) * 4096 + e] = acc;
        acc += g_S[((size_t)bh * NC + c) * 4096 + e];
    }
    next_mem[(size_t)bh * 4096 + e] = acc * elast;
}

// ============ phase 3: cross term r += es_t * (P_{c-1} q_t) ================
__global__ __launch_bounds__(256) void scan_p3() {
    __shared__ float sQ[64 * SP];
    __shared__ float sP[64 * SP];     // P[i][j]
    __shared__ float es[64];
    const int tc = blockIdx.x + 1, bh = blockIdx.y, b = bh >> 3, h = bh & 7;
    const int tid = threadIdx.x;
    #pragma unroll
    for (int f = 0; f < 4; f++) {
        const int e4 = f * 256 + tid;
        const int tt = e4 >> 4, j4 = (e4 & 15) << 2;
        *(float4*)&sQ[tt * SP + j4] =
            *(const float4*)&g_qn[((size_t)bh * NT + tc * 64 + tt) * 64 + j4];
        *(float4*)&sP[tt * SP + j4] =
            *(const float4*)&g_P[((size_t)bh * NC + tc) * 4096 + tt * 64 + j4];
    }
    if (tid < 64) es[tid] = g_ecum[bh * NT + tc * 64 + tid];
    __syncthreads();

    const int t4 = (tid & 15) * 4, i4 = (tid >> 4) * 4;
    float acc[4][4];
    #pragma unroll
    for (int a = 0; a < 4; a++)
        #pragma unroll
        for (int c = 0; c < 4; c++) acc[a][c] = 0.f;
    for (int j = 0; j < 64; j++) {
        float qv[4], pv[4];
        #pragma unroll
        for (int a = 0; a < 4; a++) qv[a] = sQ[(t4 + a) * SP + j];
        #pragma unroll
        for (int c = 0; c < 4; c++) pv[c] = sP[(i4 + c) * SP + j];
        #pragma unroll
        for (int a = 0; a < 4; a++)
            #pragma unroll
            for (int c = 0; c < 4; c++) acc[a][c] = fmaf(qv[a], pv[c], acc[a][c]);
    }
    #pragma unroll
    for (int a = 0; a < 4; a++) {
        const float e = es[t4 + a];
        const size_t ro = (size_t)(b * NT + tc * 64 + t4 + a) * NHD + h * 64;
        #pragma unroll
        for (int c = 0; c < 4; c++) g_read[ro + i4 + c] += e * acc[a][c];
    }
}

// ---------------------------------------------------------------- launch ---
static float* sym(const void* s) {
    void* p = nullptr;
    cudaGetSymbolAddress(&p, s);
    return (float*)p;
}

extern "C" void kernel_launch(void* const* d_in, const int* in_sizes, int n_in,
                              void* d_out, int out_size) {
    const float* x     = (const float*)d_in[0];
    const float* b_min = (const float*)d_in[1];
    const float* b_max = (const float*)d_in[2];
    const float* motif = (const float*)d_in[3];
    const float* Wk    = (const float*)d_in[4];
    const float* bk    = (const float*)d_in[5];
    const float* Wq    = (const float*)d_in[6];
    const float* bq    = (const float*)d_in[7];
    const float* Wv    = (const float*)d_in[8];
    const float* bv    = (const float*)d_in[9];
    const float* Wo    = (const float*)d_in[10];
    const float* bo    = (const float*)d_in[11];
    const float* Wd    = (const float*)d_in[12];
    const float* bd    = (const float*)d_in[13];
    const float* Wgw   = (const float*)d_in[14];
    const float* bgw   = (const float*)d_in[15];
    const float* Wgf   = (const float*)d_in[16];
    const float* bgf   = (const float*)d_in[17];
    const float* Wps   = (const float*)d_in[18];
    const float* bps   = (const float*)d_in[19];
    const float* ln1g  = (const float*)d_in[20];
    const float* ln1b  = (const float*)d_in[21];
    const float* ln2g  = (const float*)d_in[22];
    const float* ln2b  = (const float*)d_in[23];
    const float* W1    = (const float*)d_in[24];
    const float* b1    = (const float*)d_in[25];
    const float* W2    = (const float*)d_in[26];
    const float* b2    = (const float*)d_in[27];

    float* out    = (float*)d_out;
    float* out_x3 = out;                            // [2,1024,512]
    float* out_nm = out + (size_t)NROWS * NE;       // [2,8,64,64]
    float* out_pm = out_nm + NBH * ND * ND;         // b_min + probe
    float* out_px = out_pm + (size_t)NROWS * NE;    // b_max + probe

    float* xn   = sym(g_xn);
    float* Wkqv = sym(g_Wkqv);
    float* bkqv = sym(g_bkqv);
    float* kqv  = sym(g_kqv);
    float* rd   = sym(g_read);
    float* x2   = sym(g_x2);
    float* hh   = sym(g_hh);
    float* mid  = sym(g_mid);

    const int SM128 = (2 * 128 * APAD + 2 * 32 * 136) * 4;   // 71680
    const int SM64  = (2 * 128 * APAD + 2 * 32 * 72)  * 4;   // 55296
    const int SMP1  = (4 * 64 * SP + 64) * 4;                // 69888
    cudaFuncSetAttribute(tgemm_k<0,128>, cudaFuncAttributeMaxDynamicSharedMemorySize, SM128);
    cudaFuncSetAttribute(tgemm_k<2,128>, cudaFuncAttributeMaxDynamicSharedMemorySize, SM128);
    cudaFuncSetAttribute(tgemm_k<1,64>,  cudaFuncAttributeMaxDynamicSharedMemorySize, SM64);
    cudaFuncSetAttribute(tgemm_k<3,64>,  cudaFuncAttributeMaxDynamicSharedMemorySize, SM64);
    cudaFuncSetAttribute(tgemm_k<4,64>,  cudaFuncAttributeMaxDynamicSharedMemorySize, SM64);
    cudaFuncSetAttribute(scan_p1,        cudaFuncAttributeMaxDynamicSharedMemorySize, SMP1);

    ln_k<<<NROWS, 256>>>(x, ln1g, ln1b, xn);                                   // 0
    prep_all<<<(NE * LDW + 255) / 256, 256>>>(Wk, Wq, Wv, bk, bq, bv,
                                              Wd, bd, Wgw, bgw, Wgf, bgf);     // 1
    tgemm_k<0,128><<<dim3(13, 16), 256, SM128>>>(xn, Wkqv, bkqv, kqv,
                                                 512, LDW, LDW,
                                                 nullptr, nullptr, nullptr);   // 2
    gate_k<<<(NROWS * NH + 255) / 256, 256>>>();                               // 3
    cumsum_k<<<NBH, 256>>>();                                                  // 4
    scan_p1<<<dim3(NC, NBH), 256, SMP1>>>();                                   // 5 <- profiled
    scan_p2<<<dim3(NBH, 16), 256>>>(out_nm);                                   // 6
    scan_p3<<<dim3(NC - 1, NBH), 256>>>();                                     // 7

    tgemm_k<1,64><<<dim3(8, 16), 256, SM64>>>(rd, Wo, bo, x2, 512, 512, 512,
                                              x, motif, nullptr);              // 8
    ln_k<<<NROWS, 256>>>(x2, ln2g, ln2b, hh);                                  // 9
    tgemm_k<2,128><<<dim3(16, 16), 256, SM128>>>(hh, W1, b1, mid,
                                                 512, 2048, 2048,
                                                 nullptr, nullptr, nullptr);   // 10
    tgemm_k<3,64><<<dim3(8, 16), 256, SM64>>>(mid, W2, b2, out_x3,
                                              2048, 512, 512,
                                              x2, nullptr, nullptr);           // 11
    tgemm_k<4,64><<<dim3(8, 16), 256, SM64>>>(out_x3, Wps, bps, out_pm,
                                              512, 512, 512,
                                              b_min, b_max, out_px);           // 12
}

// round 6
// speedup vs baseline: 4.8736x; 1.0711x over previous
#include <cuda_runtime.h>
#include <math.h>

#define NE    512
#define NH    8
#define ND    64
#define NB    2
#define NT    1024
#define NHD   512
#define NROWS 2048          // B*T
#define NFFN  2048
#define NBH   16
#define NC    16            // chunks of 64 along T
#define LDW   1664          // packed fused-proj width (1536 kqv + 24 gates + pad)

// ------------------------------ scratch (static device globals; no allocs) --
static __device__ float g_xn  [NROWS * NE];          // LN1 output
static __device__ float g_Wkqv[NE * LDW];            // packed [Wk|Wq|Wv|Wd|Wgw|Wgf|0]
static __device__ float g_bkqv[LDW];
static __device__ float g_kqv [NROWS * LDW];         // raw k|q|v|gates (pre-activation)
static __device__ float g_coef[NROWS * NH];          // d*gw
static __device__ float g_logd[NROWS * NH];          // log(clip(d*gf))
static __device__ float g_ecum[NBH * NT];            // exp(cumsum(log decay))
static __device__ float g_invd[NBH * NT];            // 1/(ecum+1e-8)
static __device__ float g_read[NROWS * NHD];         // readout
static __device__ float g_x2  [NROWS * NE];
static __device__ float g_hh  [NROWS * NE];          // LN2 output
static __device__ float g_mid [NROWS * NFFN];        // gelu(h@W1+b1)
static __device__ float g_qn  [NBH * NT * 64];       // normalized q
static __device__ float g_S   [NBH * NC * 64 * 64];  // per-chunk state sums
static __device__ float g_P   [NBH * NC * 64 * 64];  // exclusive prefixes

// ------------------------------------------------------------- LayerNorm ---
__global__ __launch_bounds__(256) void ln_k(const float* __restrict__ x,
                                            const float* __restrict__ g,
                                            const float* __restrict__ b,
                                            float* __restrict__ o) {
    __shared__ float sh[8];
    const int row = blockIdx.x, tid = threadIdx.x;
    const float v0 = x[(size_t)row * NE + tid];
    const float v1 = x[(size_t)row * NE + tid + 256];

    float s = v0 + v1;
    #pragma unroll
    for (int off = 16; off; off >>= 1) s += __shfl_xor_sync(~0u, s, off);
    if ((tid & 31) == 0) sh[tid >> 5] = s;
    __syncthreads();
    if (tid < 32) {
        float t = (tid < 8) ? sh[tid] : 0.f;
        #pragma unroll
        for (int off = 4; off; off >>= 1) t += __shfl_xor_sync(~0u, t, off);
        if (tid == 0) sh[0] = t;
    }
    __syncthreads();
    const float mu = sh[0] * (1.f / NE);
    __syncthreads();

    const float d0 = v0 - mu, d1 = v1 - mu;
    s = d0 * d0 + d1 * d1;
    #pragma unroll
    for (int off = 16; off; off >>= 1) s += __shfl_xor_sync(~0u, s, off);
    if ((tid & 31) == 0) sh[tid >> 5] = s;
    __syncthreads();
    if (tid < 32) {
        float t = (tid < 8) ? sh[tid] : 0.f;
        #pragma unroll
        for (int off = 4; off; off >>= 1) t += __shfl_xor_sync(~0u, t, off);
        if (tid == 0) sh[0] = t;
    }
    __syncthreads();
    const float var = sh[0] * (1.f / NE);
    const float inv = 1.f / sqrtf(var + 1e-5f);

    o[(size_t)row * NE + tid]       = d0 * inv * g[tid]       + b[tid];
    o[(size_t)row * NE + tid + 256] = d1 * inv * g[tid + 256] + b[tid + 256];
}

// ------------- pack Wk|Wq|Wv|Wd|Wgw|Wgf (+zero pad) and biases -------------
__global__ void prep_all(const float* __restrict__ Wk, const float* __restrict__ Wq,
                         const float* __restrict__ Wv, const float* __restrict__ bk,
                         const float* __restrict__ bq, const float* __restrict__ bv,
                         const float* __restrict__ Wd,  const float* __restrict__ bd,
                         const float* __restrict__ Wgw, const float* __restrict__ bgw,
                         const float* __restrict__ Wgf, const float* __restrict__ bgf) {
    const int idx = blockIdx.x * 256 + threadIdx.x;    // over 512*1664
    if (idx >= NE * LDW) return;
    const int r = idx / LDW, c = idx % LDW;
    float w;
    if (c < 512)        w = Wk[r * NHD + c];
    else if (c < 1024)  w = Wq[r * NHD + (c - 512)];
    else if (c < 1536)  w = Wv[r * NHD + (c - 1024)];
    else if (c < 1544)  w = Wd [r * NH + (c - 1536)];
    else if (c < 1552)  w = Wgw[r * NH + (c - 1544)];
    else if (c < 1560)  w = Wgf[r * NH + (c - 1552)];
    else                w = 0.f;
    g_Wkqv[idx] = w;
    if (r == 0) {
        float bb;
        if (c < 512)        bb = bk[c];
        else if (c < 1024)  bb = bq[c - 512];
        else if (c < 1536)  bb = bv[c - 1024];
        else if (c < 1544)  bb = bd [c - 1536];
        else if (c < 1552)  bb = bgw[c - 1544];
        else if (c < 1560)  bb = bgf[c - 1552];
        else                bb = 0.f;
        g_bkqv[c] = bb;
    }
}

// ----------------------------------------------------- mma + cp.async ------
__device__ __forceinline__ void mma_tf32(float* d,
                                         unsigned int a0, unsigned int a1,
                                         unsigned int a2, unsigned int a3,
                                         unsigned int b0, unsigned int b1) {
    asm volatile(
        "mma.sync.aligned.m16n8k8.row.col.f32.tf32.tf32.f32 "
        "{%0,%1,%2,%3}, {%4,%5,%6,%7}, {%8,%9}, {%0,%1,%2,%3};"
        : "+f"(d[0]), "+f"(d[1]), "+f"(d[2]), "+f"(d[3])
        : "r"(a0), "r"(a1), "r"(a2), "r"(a3), "r"(b0), "r"(b1));
}

__device__ __forceinline__ void cpasync16(void* s, const void* g) {
    unsigned int sa = (unsigned int)__cvta_generic_to_shared(s);
    asm volatile("cp.async.cg.shared.global [%0], [%1], 16;" :: "r"(sa), "l"(g));
}
#define CP_COMMIT()  asm volatile("cp.async.commit_group;")
#define CP_WAIT(n)   asm volatile("cp.async.wait_group %0;" :: "n"(n))

// -------- tf32 tensor-core GEMM, 3-stage cp.async, 1 sync per iter ---------
// MODE 0: C = A@B + bias
// MODE 1: C = A@B + bias + aux1 + 0.1*aux2
// MODE 2: C = gelu_exact(A@B + bias)
// MODE 3: C = A@B + bias + aux1
// MODE 4: C = aux1 + v; C2 = aux2 + v
// MODE 5: like 0, plus fused gate math on the block covering cols 1536..1663
#define APAD 36
template <int MODE, int BN>
__global__ __launch_bounds__(256) void tgemm_k(
    const float* __restrict__ A, const float* __restrict__ B,
    const float* __restrict__ bias, float* __restrict__ C,
    int K, int N, int ldc,
    const float* __restrict__ aux1, const float* __restrict__ aux2,
    float* __restrict__ C2) {
    constexpr int BPAD = BN + 8;
    constexpr int MT   = (BN == 128) ? 2 : 1;
    constexpr int ASZ  = 128 * APAD;
    constexpr int BSZ  = 32 * BPAD;
    extern __shared__ float sm[];
    float* Abuf = sm;                       // 3 stages of [128][APAD]
    float* Bbuf = sm + 3 * ASZ;             // 3 stages of [32][BPAD]

    const int tid  = threadIdx.x;
    const int warp = tid >> 5, lane = tid & 31;
    const int g    = lane >> 2, tg = lane & 3;
    const int wm   = (BN == 128) ? (warp >> 1) : warp;
    const int wn   = (BN == 128) ? (warp & 1)  : 0;
    const int mBase = blockIdx.y * 128;
    const int nBase = blockIdx.x * BN;

    float acc[MT][8][4];
    #pragma unroll
    for (int mt = 0; mt < MT; mt++)
        #pragma unroll
        for (int nt = 0; nt < 8; nt++)
            #pragma unroll
            for (int e = 0; e < 4; e++) acc[mt][nt][e] = 0.f;

    const int nT = K >> 5;
    const int aRow = tid >> 3, aC4 = (tid & 7) << 2;
    constexpr int BQ = BN / 4;
    const int bRow = tid / BQ, bC4 = (tid % BQ) << 2;
    constexpr int BROWSTEP = 256 / BQ;

    auto load_stage = [&](int t, int st) {
        const int ks = t << 5;
        float* As = Abuf + st * ASZ;
        float* Bs = Bbuf + st * BSZ;
        #pragma unroll
        for (int i = 0; i < 4; i++) {
            const int row = aRow + 32 * i;
            cpasync16(&As[row * APAD + aC4],
                      A + (size_t)(mBase + row) * K + ks + aC4);
        }
        #pragma unroll
        for (int i = 0; i < 32 / BROWSTEP; i++) {
            const int row = bRow + BROWSTEP * i;
            cpasync16(&Bs[row * BPAD + bC4],
                      B + (size_t)(ks + row) * N + nBase + bC4);
        }
        CP_COMMIT();
    };

    load_stage(0, 0);
    load_stage(1, 1);

    int st = 0;                              // stage of iteration t
    for (int t = 0; t < nT; t++) {
        if (t == nT - 1) { CP_WAIT(0); } else { CP_WAIT(1); }
        __syncthreads();
        if (t + 2 < nT) {
            int st2 = st + 2; if (st2 >= 3) st2 -= 3;
            load_stage(t + 2, st2);
        }
        const float* As = Abuf + st * ASZ;
        const float* Bs = Bbuf + st * BSZ;

        #pragma unroll
        for (int k8 = 0; k8 < 4; k8++) {
            const int kk = k8 << 3;
            unsigned int bf[8][2];
            #pragma unroll
            for (int nt = 0; nt < 8; nt++) {
                const int n = wn * 64 + nt * 8 + g;
                bf[nt][0] = __float_as_uint(Bs[(kk + tg) * BPAD + n]);
                bf[nt][1] = __float_as_uint(Bs[(kk + tg + 4) * BPAD + n]);
            }
            #pragma unroll
            for (int mt = 0; mt < MT; mt++) {
                const int m = (BN == 128) ? (wm * 32 + mt * 16) : (wm * 16);
                const unsigned int a0 = __float_as_uint(As[(m + g) * APAD + kk + tg]);
                const unsigned int a1 = __float_as_uint(As[(m + g + 8) * APAD + kk + tg]);
                const unsigned int a2 = __float_as_uint(As[(m + g) * APAD + kk + tg + 4]);
                const unsigned int a3 = __float_as_uint(As[(m + g + 8) * APAD + kk + tg + 4]);
                #pragma unroll
                for (int nt = 0; nt < 8; nt++)
                    mma_tf32(acc[mt][nt], a0, a1, a2, a3, bf[nt][0], bf[nt][1]);
            }
        }
        if (++st >= 3) st -= 3;
    }

    #pragma unroll
    for (int mt = 0; mt < MT; mt++) {
        const int r0 = mBase + ((BN == 128) ? (wm * 32 + mt * 16) : (wm * 16)) + g;
        const int r1 = r0 + 8;
        #pragma unroll
        for (int nt = 0; nt < 8; nt++) {
            const int col = nBase + wn * 64 + nt * 8 + 2 * tg;
            const float b0 = bias[col], b1 = bias[col + 1];
            float e00 = acc[mt][nt][0] + b0, e01 = acc[mt][nt][1] + b1;
            float e10 = acc[mt][nt][2] + b0, e11 = acc[mt][nt][3] + b1;
            const size_t i0 = (size_t)r0 * ldc + col;
            const size_t i1 = (size_t)r1 * ldc + col;
            if (MODE == 0 || MODE == 5) {
                *(float2*)&C[i0] = make_float2(e00, e01);
                *(float2*)&C[i1] = make_float2(e10, e11);
            } else if (MODE == 1) {
                const float2 a0v = *(const float2*)&aux1[i0];
                const float2 a1v = *(const float2*)&aux1[i1];
                const float2 m0v = *(const float2*)&aux2[i0];
                const float2 m1v = *(const float2*)&aux2[i1];
                *(float2*)&C[i0] = make_float2(e00 + a0v.x + 0.1f * m0v.x,
                                               e01 + a0v.y + 0.1f * m0v.y);
                *(float2*)&C[i1] = make_float2(e10 + a1v.x + 0.1f * m1v.x,
                                               e11 + a1v.y + 0.1f * m1v.y);
            } else if (MODE == 2) {
                e00 = 0.5f * e00 * (1.f + erff(e00 * 0.7071067811865475f));
                e01 = 0.5f * e01 * (1.f + erff(e01 * 0.7071067811865475f));
                e10 = 0.5f * e10 * (1.f + erff(e10 * 0.7071067811865475f));
                e11 = 0.5f * e11 * (1.f + erff(e11 * 0.7071067811865475f));
                *(float2*)&C[i0] = make_float2(e00, e01);
                *(float2*)&C[i1] = make_float2(e10, e11);
            } else if (MODE == 3) {
                const float2 a0v = *(const float2*)&aux1[i0];
                const float2 a1v = *(const float2*)&aux1[i1];
                *(float2*)&C[i0] = make_float2(e00 + a0v.x, e01 + a0v.y);
                *(float2*)&C[i1] = make_float2(e10 + a1v.x, e11 + a1v.y);
            } else {
                const float2 p0 = *(const float2*)&aux1[i0];
                const float2 p1 = *(const float2*)&aux1[i1];
                const float2 q0 = *(const float2*)&aux2[i0];
                const float2 q1 = *(const float2*)&aux2[i1];
                *(float2*)&C[i0]  = make_float2(p0.x + e00, p0.y + e01);
                *(float2*)&C[i1]  = make_float2(p1.x + e10, p1.y + e11);
                *(float2*)&C2[i0] = make_float2(q0.x + e00, q0.y + e01);
                *(float2*)&C2[i1] = make_float2(q1.x + e10, q1.y + e11);
            }
        }
    }

    // -------- fused gate math (MODE 5, block covering cols 1536..1663) -----
    if (MODE == 5 && nBase == 1536) {
        __syncthreads();     // make this block's global C writes visible
        #pragma unroll
        for (int u = 0; u < 4; u++) {
            const int idx = u * 256 + tid;          // 0..1023 = 128 rows x 8 h
            const int row = mBase + (idx >> 3), h = idx & 7;
            const float* gp = C + (size_t)row * ldc + 1536;
            const float xd = gp[h], xgw = gp[8 + h], xgf = gp[16 + h];
            const float d  = fmaxf(xd, 0.f) + log1pf(expf(-fabsf(xd)));
            const float sw = 1.f / (1.f + expf(-xgw));
            const float sf = 1.f / (1.f + expf(-xgf));
            g_coef[row * NH + h] = d * (sw * sw);
            const float dec = fminf(fmaxf(d * (1.f - sf * sf), 1e-6f), 0.999f);
            g_logd[row * NH + h] = logf(dec);
        }
    }
}

// ------- cumsum of log-decay: smem-staged serial chain + parallel exp ------
__global__ __launch_bounds__(256) void cumsum_k() {
    __shared__ float s[NT];
    __shared__ float c[NT];
    const int bh = blockIdx.x, b = bh >> 3, h = bh & 7;
    const int tid = threadIdx.x;
    for (int t = tid; t < NT; t += 256)
        s[t] = g_logd[(b * NT + t) * NH + h];
    __syncthreads();
    if (tid == 0) {
        float acc = 0.f;
        #pragma unroll 8
        for (int t = 0; t < NT; t++) { acc += s[t]; c[t] = acc; }
    }
    __syncthreads();
    for (int t = tid; t < NT; t += 256) {
        const float e = expf(c[t]);          // underflows to 0 exactly like ref
        g_ecum[bh * NT + t] = e;
        g_invd[bh * NT + t] = 1.f / (e + 1e-8f);
    }
}

// ============ chunked scan: phase 1 (per-chunk matmuls, no serial dep) =====
#define SP 68
__global__ __launch_bounds__(256) void scan_p1() {
    extern __shared__ float sm[];
    float* sK = sm;                 // [64][SP]
    float* sQ = sm + 64 * SP;
    float* sA = sm + 2 * 64 * SP;   // A[s][i] = tanh(v)*coef*invd
    float* sG = sm + 3 * 64 * SP;   // G[t][s] (causal)
    float* es = sm + 4 * 64 * SP;   // [64]
    const int tc = blockIdx.x, bh = blockIdx.y, b = bh >> 3, h = bh & 7;
    const int tid = threadIdx.x;

    // stage raw k/q + build A
    #pragma unroll
    for (int f = 0; f < 4; f++) {
        const int e4 = f * 256 + tid;
        const int tt = e4 >> 4, j4 = (e4 & 15) << 2;
        const int row = b * NT + tc * 64 + tt;
        const float* rp = g_kqv + (size_t)row * LDW + h * 64;
        *(float4*)&sK[tt * SP + j4] = *(const float4*)(rp + j4);
        *(float4*)&sQ[tt * SP + j4] = *(const float4*)(rp + 512 + j4);
        const float4 v = *(const float4*)(rp + 1024 + j4);
        const float sc = g_coef[row * NH + h] * g_invd[bh * NT + tc * 64 + tt];
        float4 a4;
        a4.x = tanhf(v.x) * sc; a4.y = tanhf(v.y) * sc;
        a4.z = tanhf(v.z) * sc; a4.w = tanhf(v.w) * sc;
        *(float4*)&sA[tt * SP + j4] = a4;
    }
    if (tid < 64) es[tid] = g_ecum[bh * NT + tc * 64 + tid];
    __syncthreads();

    // l2-normalize K,Q rows (4 threads per row)
    {
        const int nr = tid >> 2, nq = tid & 3;
        float sk = 0.f, sq = 0.f;
        #pragma unroll
        for (int e = 0; e < 16; e++) {
            const float kv = sK[nr * SP + nq * 16 + e];
            const float qv = sQ[nr * SP + nq * 16 + e];
            sk = fmaf(kv, kv, sk);
            sq = fmaf(qv, qv, sq);
        }
        sk += __shfl_xor_sync(~0u, sk, 1); sk += __shfl_xor_sync(~0u, sk, 2);
        sq += __shfl_xor_sync(~0u, sq, 1); sq += __shfl_xor_sync(~0u, sq, 2);
        const float ik = 1.f / fmaxf(sqrtf(sk), 1e-12f);
        const float iq = 1.f / fmaxf(sqrtf(sq), 1e-12f);
        #pragma unroll
        for (int e = 0; e < 16; e++) {
            sK[nr * SP + nq * 16 + e] *= ik;
            sQ[nr * SP + nq * 16 + e] *= iq;
        }
    }
    __syncthreads();

    // save normalized Q for phase 3
    #pragma unroll
    for (int f = 0; f < 4; f++) {
        const int e4 = f * 256 + tid;
        const int tt = e4 >> 4, j4 = (e4 & 15) << 2;
        *(float4*)&g_qn[((size_t)bh * NT + tc * 64 + tt) * 64 + j4] =
            *(const float4*)&sQ[tt * SP + j4];
    }

    // S_c[i][j] = sum_s A[s][i] * K[s][j]
    {
        const int i4 = (tid & 15) * 4, j4 = (tid >> 4) * 4;
        float acc[4][4];
        #pragma unroll
        for (int a = 0; a < 4; a++)
            #pragma unroll
            for (int c = 0; c < 4; c++) acc[a][c] = 0.f;
        for (int s = 0; s < 64; s++) {
            float av[4], kv[4];
            #pragma unroll
            for (int a = 0; a < 4; a++) av[a] = sA[s * SP + i4 + a];
            #pragma unroll
            for (int c = 0; c < 4; c++) kv[c] = sK[s * SP + j4 + c];
            #pragma unroll
            for (int a = 0; a < 4; a++)
                #pragma unroll
                for (int c = 0; c < 4; c++) acc[a][c] = fmaf(av[a], kv[c], acc[a][c]);
        }
        float* Sp = g_S + ((size_t)bh * NC + tc) * 4096;
        #pragma unroll
        for (int a = 0; a < 4; a++)
            #pragma unroll
            for (int c = 0; c < 4; c++) Sp[(i4 + a) * 64 + j4 + c] = acc[a][c];
    }

    // G[t][s] = q_t . k_s  (causal)
    {
        const int t4 = (tid & 15) * 4, s4 = (tid >> 4) * 4;
        float acc[4][4];
        #pragma unroll
        for (int a = 0; a < 4; a++)
            #pragma unroll
            for (int c = 0; c < 4; c++) acc[a][c] = 0.f;
        if (s4 <= t4 + 3) {
            for (int j = 0; j < 64; j++) {
                float qv[4], kv[4];
                #pragma unroll
                for (int a = 0; a < 4; a++) qv[a] = sQ[(t4 + a) * SP + j];
                #pragma unroll
                for (int c = 0; c < 4; c++) kv[c] = sK[(s4 + c) * SP + j];
                #pragma unroll
                for (int a = 0; a < 4; a++)
                    #pragma unroll
                    for (int c = 0; c < 4; c++) acc[a][c] = fmaf(qv[a], kv[c], acc[a][c]);
            }
        }
        #pragma unroll
        for (int a = 0; a < 4; a++)
            #pragma unroll
            for (int c = 0; c < 4; c++)
                sG[(t4 + a) * SP + s4 + c] = (s4 + c <= t4 + a) ? acc[a][c] : 0.f;
    }
    __syncthreads();

    // r_local[t][i] = sum_{s<=t} G[t][s] * A[s][i]; store es_t * r_local
    {
        const int t4 = (tid & 15) * 4, i4 = (tid >> 4) * 4;
        float acc[4][4];
        #pragma unroll
        for (int a = 0; a < 4; a++)
            #pragma unroll
            for (int c = 0; c < 4; c++) acc[a][c] = 0.f;
        const int smax = t4 + 4;
        for (int s = 0; s < smax; s++) {
            float gv[4], av[4];
            #pragma unroll
            for (int a = 0; a < 4; a++) gv[a] = sG[(t4 + a) * SP + s];
            #pragma unroll
            for (int c = 0; c < 4; c++) av[c] = sA[s * SP + i4 + c];
            #pragma unroll
            for (int a = 0; a < 4; a++)
                #pragma unroll
                for (int c = 0; c < 4; c++) acc[a][c] = fmaf(gv[a], av[c], acc[a][c]);
        }
        #pragma unroll
        for (int a = 0; a < 4; a++) {
            const float e = es[t4 + a];
            const size_t ro = (size_t)(b * NT + tc * 64 + t4 + a) * NHD + h * 64;
            #pragma unroll
            for (int c = 0; c < 4; c++) g_read[ro + i4 + c] = e * acc[a][c];
        }
    }
}

// ============ phase 2: exclusive prefix of chunk sums + next_mem ===========
__global__ __launch_bounds__(256) void scan_p2(float* __restrict__ next_mem) {
    const int bh = blockIdx.x;
    const int e  = blockIdx.y * 256 + threadIdx.x;      // 0..4095
    const float elast = g_ecum[bh * NT + NT - 1];
    float acc = 0.f;
    #pragma unroll
    for (int c = 0; c < NC; c++) {
        g_P[((size_t)bh * NC + c) * 4096 + e] = acc;
        acc += g_S[((size_t)bh * NC + c) * 4096 + e];
    }
    next_mem[(size_t)bh * 4096 + e] = acc * elast;
}

// ============ phase 3: cross term r += es_t * (P_{c-1} q_t) ================
__global__ __launch_bounds__(256) void scan_p3() {
    __shared__ float sQ[64 * SP];
    __shared__ float sP[64 * SP];     // P[i][j]
    __shared__ float es[64];
    const int tc = blockIdx.x + 1, bh = blockIdx.y, b = bh >> 3, h = bh & 7;
    const int tid = threadIdx.x;
    #pragma unroll
    for (int f = 0; f < 4; f++) {
        const int e4 = f * 256 + tid;
        const int tt = e4 >> 4, j4 = (e4 & 15) << 2;
        *(float4*)&sQ[tt * SP + j4] =
            *(const float4*)&g_qn[((size_t)bh * NT + tc * 64 + tt) * 64 + j4];
        *(float4*)&sP[tt * SP + j4] =
            *(const float4*)&g_P[((size_t)bh * NC + tc) * 4096 + tt * 64 + j4];
    }
    if (tid < 64) es[tid] = g_ecum[bh * NT + tc * 64 + tid];
    __syncthreads();

    const int t4 = (tid & 15) * 4, i4 = (tid >> 4) * 4;
    float acc[4][4];
    #pragma unroll
    for (int a = 0; a < 4; a++)
        #pragma unroll
        for (int c = 0; c < 4; c++) acc[a][c] = 0.f;
    for (int j = 0; j < 64; j++) {
        float qv[4], pv[4];
        #pragma unroll
        for (int a = 0; a < 4; a++) qv[a] = sQ[(t4 + a) * SP + j];
        #pragma unroll
        for (int c = 0; c < 4; c++) pv[c] = sP[(i4 + c) * SP + j];
        #pragma unroll
        for (int a = 0; a < 4; a++)
            #pragma unroll
            for (int c = 0; c < 4; c++) acc[a][c] = fmaf(qv[a], pv[c], acc[a][c]);
    }
    #pragma unroll
    for (int a = 0; a < 4; a++) {
        const float e = es[t4 + a];
        const size_t ro = (size_t)(b * NT + tc * 64 + t4 + a) * NHD + h * 64;
        #pragma unroll
        for (int c = 0; c < 4; c++) g_read[ro + i4 + c] += e * acc[a][c];
    }
}

// ---------------------------------------------------------------- launch ---
static float* sym(const void* s) {
    void* p = nullptr;
    cudaGetSymbolAddress(&p, s);
    return (float*)p;
}

extern "C" void kernel_launch(void* const* d_in, const int* in_sizes, int n_in,
                              void* d_out, int out_size) {
    const float* x     = (const float*)d_in[0];
    const float* b_min = (const float*)d_in[1];
    const float* b_max = (const float*)d_in[2];
    const float* motif = (const float*)d_in[3];
    const float* Wk    = (const float*)d_in[4];
    const float* bk    = (const float*)d_in[5];
    const float* Wq    = (const float*)d_in[6];
    const float* bq    = (const float*)d_in[7];
    const float* Wv    = (const float*)d_in[8];
    const float* bv    = (const float*)d_in[9];
    const float* Wo    = (const float*)d_in[10];
    const float* bo    = (const float*)d_in[11];
    const float* Wd    = (const float*)d_in[12];
    const float* bd    = (const float*)d_in[13];
    const float* Wgw   = (const float*)d_in[14];
    const float* bgw   = (const float*)d_in[15];
    const float* Wgf   = (const float*)d_in[16];
    const float* bgf   = (const float*)d_in[17];
    const float* Wps   = (const float*)d_in[18];
    const float* bps   = (const float*)d_in[19];
    const float* ln1g  = (const float*)d_in[20];
    const float* ln1b  = (const float*)d_in[21];
    const float* ln2g  = (const float*)d_in[22];
    const float* ln2b  = (const float*)d_in[23];
    const float* W1    = (const float*)d_in[24];
    const float* b1    = (const float*)d_in[25];
    const float* W2    = (const float*)d_in[26];
    const float* b2    = (const float*)d_in[27];

    float* out    = (float*)d_out;
    float* out_x3 = out;                            // [2,1024,512]
    float* out_nm = out + (size_t)NROWS * NE;       // [2,8,64,64]
    float* out_pm = out_nm + NBH * ND * ND;         // b_min + probe
    float* out_px = out_pm + (size_t)NROWS * NE;    // b_max + probe

    float* xn   = sym(g_xn);
    float* Wkqv = sym(g_Wkqv);
    float* bkqv = sym(g_bkqv);
    float* kqv  = sym(g_kqv);
    float* rd   = sym(g_read);
    float* x2   = sym(g_x2);
    float* hh   = sym(g_hh);
    float* mid  = sym(g_mid);

    const int SM128 = 3 * (128 * APAD + 32 * 136) * 4;   // 107520
    const int SM64  = 3 * (128 * APAD + 32 * 72)  * 4;   // 82944
    const int SMP1  = (4 * 64 * SP + 64) * 4;            // 69888
    cudaFuncSetAttribute(tgemm_k<5,128>, cudaFuncAttributeMaxDynamicSharedMemorySize, SM128);
    cudaFuncSetAttribute(tgemm_k<2,128>, cudaFuncAttributeMaxDynamicSharedMemorySize, SM128);
    cudaFuncSetAttribute(tgemm_k<1,64>,  cudaFuncAttributeMaxDynamicSharedMemorySize, SM64);
    cudaFuncSetAttribute(tgemm_k<3,64>,  cudaFuncAttributeMaxDynamicSharedMemorySize, SM64);
    cudaFuncSetAttribute(tgemm_k<4,64>,  cudaFuncAttributeMaxDynamicSharedMemorySize, SM64);
    cudaFuncSetAttribute(scan_p1,        cudaFuncAttributeMaxDynamicSharedMemorySize, SMP1);

    ln_k<<<NROWS, 256>>>(x, ln1g, ln1b, xn);                                   // 0
    prep_all<<<(NE * LDW + 255) / 256, 256>>>(Wk, Wq, Wv, bk, bq, bv,
                                              Wd, bd, Wgw, bgw, Wgf, bgf);     // 1
    tgemm_k<5,128><<<dim3(13, 16), 256, SM128>>>(xn, Wkqv, bkqv, kqv,
                                                 512, LDW, LDW,
                                                 nullptr, nullptr, nullptr);   // 2
    cumsum_k<<<NBH, 256>>>();                                                  // 3
    scan_p1<<<dim3(NC, NBH), 256, SMP1>>>();                                   // 4
    scan_p2<<<dim3(NBH, 16), 256>>>(out_nm);                                   // 5
    scan_p3<<<dim3(NC - 1, NBH), 256>>>();                                     // 6

    tgemm_k<1,64><<<dim3(8, 16), 256, SM64>>>(rd, Wo, bo, x2, 512, 512, 512,
                                              x, motif, nullptr);              // 7
    ln_k<<<NROWS, 256>>>(x2, ln2g, ln2b, hh);                                  // 8
    tgemm_k<2,128><<<dim3(16, 16), 256, SM128>>>(hh, W1, b1, mid,
                                                 512, 2048, 2048,
                                                 nullptr, nullptr, nullptr);   // 9
    tgemm_k<3,64><<<dim3(8, 16), 256, SM64>>>(mid, W2, b2, out_x3,
                                              2048, 512, 512,
                                              x2, nullptr, nullptr);           // 10
    tgemm_k<4,64><<<dim3(8, 16), 256, SM64>>>(out_x3, Wps, bps, out_pm,
                                              512, 512, 512,
                                              b_min, b_max, out_px);           // 11
}

// round 7
// speedup vs baseline: 5.5944x; 1.1479x over previous
#include <cuda_runtime.h>
#include <math.h>

#define NE    512
#define NH    8
#define ND    64
#define NB    2
#define NT    1024
#define NHD   512
#define NROWS 2048          // B*T
#define NFFN  2048
#define NBH   16
#define NC    16            // chunks of 64 along T
#define LDW   1664          // packed fused-proj width (1536 kqv + 24 gates + pad)

// ------------------------------ scratch (static device globals; no allocs) --
static __device__ float g_xn  [NROWS * NE];          // LN1 output
static __device__ float g_Wkqv[NE * LDW];            // packed [Wk|Wq|Wv|Wd|Wgw|Wgf|0]
static __device__ float g_bkqv[LDW];
static __device__ float g_kqv [NROWS * LDW];         // raw k|q|v|gates (pre-activation)
static __device__ float g_coef[NROWS * NH];          // d*gw
static __device__ float g_logd[NROWS * NH];          // log(clip(d*gf))
static __device__ float g_ecum[NBH * NT];            // exp(cumsum(log decay))
static __device__ float g_invd[NBH * NT];            // 1/(ecum+1e-8)
static __device__ float g_read[NROWS * NHD];         // readout
static __device__ float g_x2  [NROWS * NE];
static __device__ float g_hh  [NROWS * NE];          // LN2 output
static __device__ float g_mid [NROWS * NFFN];        // gelu(h@W1+b1)
static __device__ float g_qn  [NBH * NT * 64];       // normalized q
static __device__ float g_S   [NBH * NC * 64 * 64];  // per-chunk state sums
static __device__ float g_P   [NBH * NC * 64 * 64];  // exclusive prefixes

// ------------------------------------------------------------- LayerNorm ---
__global__ __launch_bounds__(256) void ln_k(const float* __restrict__ x,
                                            const float* __restrict__ g,
                                            const float* __restrict__ b,
                                            float* __restrict__ o) {
    __shared__ float sh[8];
    const int row = blockIdx.x, tid = threadIdx.x;
    const float v0 = x[(size_t)row * NE + tid];
    const float v1 = x[(size_t)row * NE + tid + 256];

    float s = v0 + v1;
    #pragma unroll
    for (int off = 16; off; off >>= 1) s += __shfl_xor_sync(~0u, s, off);
    if ((tid & 31) == 0) sh[tid >> 5] = s;
    __syncthreads();
    if (tid < 32) {
        float t = (tid < 8) ? sh[tid] : 0.f;
        #pragma unroll
        for (int off = 4; off; off >>= 1) t += __shfl_xor_sync(~0u, t, off);
        if (tid == 0) sh[0] = t;
    }
    __syncthreads();
    const float mu = sh[0] * (1.f / NE);
    __syncthreads();

    const float d0 = v0 - mu, d1 = v1 - mu;
    s = d0 * d0 + d1 * d1;
    #pragma unroll
    for (int off = 16; off; off >>= 1) s += __shfl_xor_sync(~0u, s, off);
    if ((tid & 31) == 0) sh[tid >> 5] = s;
    __syncthreads();
    if (tid < 32) {
        float t = (tid < 8) ? sh[tid] : 0.f;
        #pragma unroll
        for (int off = 4; off; off >>= 1) t += __shfl_xor_sync(~0u, t, off);
        if (tid == 0) sh[0] = t;
    }
    __syncthreads();
    const float var = sh[0] * (1.f / NE);
    const float inv = 1.f / sqrtf(var + 1e-5f);

    o[(size_t)row * NE + tid]       = d0 * inv * g[tid]       + b[tid];
    o[(size_t)row * NE + tid + 256] = d1 * inv * g[tid + 256] + b[tid + 256];
}

// ------------- pack Wk|Wq|Wv|Wd|Wgw|Wgf (+zero pad) and biases -------------
__global__ void prep_all(const float* __restrict__ Wk, const float* __restrict__ Wq,
                         const float* __restrict__ Wv, const float* __restrict__ bk,
                         const float* __restrict__ bq, const float* __restrict__ bv,
                         const float* __restrict__ Wd,  const float* __restrict__ bd,
                         const float* __restrict__ Wgw, const float* __restrict__ bgw,
                         const float* __restrict__ Wgf, const float* __restrict__ bgf) {
    const int idx = blockIdx.x * 256 + threadIdx.x;    // over 512*1664
    if (idx >= NE * LDW) return;
    const int r = idx / LDW, c = idx % LDW;
    float w;
    if (c < 512)        w = Wk[r * NHD + c];
    else if (c < 1024)  w = Wq[r * NHD + (c - 512)];
    else if (c < 1536)  w = Wv[r * NHD + (c - 1024)];
    else if (c < 1544)  w = Wd [r * NH + (c - 1536)];
    else if (c < 1552)  w = Wgw[r * NH + (c - 1544)];
    else if (c < 1560)  w = Wgf[r * NH + (c - 1552)];
    else                w = 0.f;
    g_Wkqv[idx] = w;
    if (r == 0) {
        float bb;
        if (c < 512)        bb = bk[c];
        else if (c < 1024)  bb = bq[c - 512];
        else if (c < 1536)  bb = bv[c - 1024];
        else if (c < 1544)  bb = bd [c - 1536];
        else if (c < 1552)  bb = bgw[c - 1544];
        else if (c < 1560)  bb = bgf[c - 1552];
        else                bb = 0.f;
        g_bkqv[c] = bb;
    }
}

// ----------------------------------------------------- mma + cp.async ------
__device__ __forceinline__ void mma_tf32(float* d,
                                         unsigned int a0, unsigned int a1,
                                         unsigned int a2, unsigned int a3,
                                         unsigned int b0, unsigned int b1) {
    asm volatile(
        "mma.sync.aligned.m16n8k8.row.col.f32.tf32.tf32.f32 "
        "{%0,%1,%2,%3}, {%4,%5,%6,%7}, {%8,%9}, {%0,%1,%2,%3};"
        : "+f"(d[0]), "+f"(d[1]), "+f"(d[2]), "+f"(d[3])
        : "r"(a0), "r"(a1), "r"(a2), "r"(a3), "r"(b0), "r"(b1));
}

__device__ __forceinline__ void cpasync16(void* s, const void* g) {
    unsigned int sa = (unsigned int)__cvta_generic_to_shared(s);
    asm volatile("cp.async.cg.shared.global [%0], [%1], 16;" :: "r"(sa), "l"(g));
}
#define CP_COMMIT()  asm volatile("cp.async.commit_group;")
#define CP_WAIT(n)   asm volatile("cp.async.wait_group %0;" :: "n"(n))

// -------- tf32 tensor-core GEMM, 3-stage cp.async, 1 sync per iter ---------
// MODE 0: C = A@B + bias
// MODE 1: C = A@B + bias + aux1 + 0.1*aux2
// MODE 2: C = gelu_exact(A@B + bias)
// MODE 3: C = A@B + bias + aux1
// MODE 4: C = aux1 + v; C2 = aux2 + v
// MODE 5: like 0, plus fused gate math on the block covering cols 1536..1663
#define APAD 36
template <int MODE, int BN>
__global__ __launch_bounds__(256, 2) void tgemm_k(
    const float* __restrict__ A, const float* __restrict__ B,
    const float* __restrict__ bias, float* __restrict__ C,
    int K, int N, int ldc,
    const float* __restrict__ aux1, const float* __restrict__ aux2,
    float* __restrict__ C2) {
    constexpr int BPAD = BN + 8;
    constexpr int MT   = (BN == 128) ? 2 : 1;
    constexpr int ASZ  = 128 * APAD;
    constexpr int BSZ  = 32 * BPAD;
    extern __shared__ float sm[];
    float* Abuf = sm;                       // 3 stages of [128][APAD]
    float* Bbuf = sm + 3 * ASZ;             // 3 stages of [32][BPAD]

    const int tid  = threadIdx.x;
    const int warp = tid >> 5, lane = tid & 31;
    const int g    = lane >> 2, tg = lane & 3;
    const int wm   = (BN == 128) ? (warp >> 1) : warp;
    const int wn   = (BN == 128) ? (warp & 1)  : 0;
    const int mBase = blockIdx.y * 128;
    const int nBase = blockIdx.x * BN;

    float acc[MT][8][4];
    #pragma unroll
    for (int mt = 0; mt < MT; mt++)
        #pragma unroll
        for (int nt = 0; nt < 8; nt++)
            #pragma unroll
            for (int e = 0; e < 4; e++) acc[mt][nt][e] = 0.f;

    const int nT = K >> 5;
    const int aRow = tid >> 3, aC4 = (tid & 7) << 2;
    constexpr int BQ = BN / 4;
    const int bRow = tid / BQ, bC4 = (tid % BQ) << 2;
    constexpr int BROWSTEP = 256 / BQ;

    auto load_stage = [&](int t, int st) {
        const int ks = t << 5;
        float* As = Abuf + st * ASZ;
        float* Bs = Bbuf + st * BSZ;
        #pragma unroll
        for (int i = 0; i < 4; i++) {
            const int row = aRow + 32 * i;
            cpasync16(&As[row * APAD + aC4],
                      A + (size_t)(mBase + row) * K + ks + aC4);
        }
        #pragma unroll
        for (int i = 0; i < 32 / BROWSTEP; i++) {
            const int row = bRow + BROWSTEP * i;
            cpasync16(&Bs[row * BPAD + bC4],
                      B + (size_t)(ks + row) * N + nBase + bC4);
        }
        CP_COMMIT();
    };

    load_stage(0, 0);
    load_stage(1, 1);

    int st = 0;                              // stage of iteration t
    for (int t = 0; t < nT; t++) {
        if (t == nT - 1) { CP_WAIT(0); } else { CP_WAIT(1); }
        __syncthreads();
        if (t + 2 < nT) {
            int st2 = st + 2; if (st2 >= 3) st2 -= 3;
            load_stage(t + 2, st2);
        }
        const float* As = Abuf + st * ASZ;
        const float* Bs = Bbuf + st * BSZ;

        #pragma unroll
        for (int k8 = 0; k8 < 4; k8++) {
            const int kk = k8 << 3;
            unsigned int bf[8][2];
            #pragma unroll
            for (int nt = 0; nt < 8; nt++) {
                const int n = wn * 64 + nt * 8 + g;
                bf[nt][0] = __float_as_uint(Bs[(kk + tg) * BPAD + n]);
                bf[nt][1] = __float_as_uint(Bs[(kk + tg + 4) * BPAD + n]);
            }
            #pragma unroll
            for (int mt = 0; mt < MT; mt++) {
                const int m = (BN == 128) ? (wm * 32 + mt * 16) : (wm * 16);
                const unsigned int a0 = __float_as_uint(As[(m + g) * APAD + kk + tg]);
                const unsigned int a1 = __float_as_uint(As[(m + g + 8) * APAD + kk + tg]);
                const unsigned int a2 = __float_as_uint(As[(m + g) * APAD + kk + tg + 4]);
                const unsigned int a3 = __float_as_uint(As[(m + g + 8) * APAD + kk + tg + 4]);
                #pragma unroll
                for (int nt = 0; nt < 8; nt++)
                    mma_tf32(acc[mt][nt], a0, a1, a2, a3, bf[nt][0], bf[nt][1]);
            }
        }
        if (++st >= 3) st -= 3;
    }

    #pragma unroll
    for (int mt = 0; mt < MT; mt++) {
        const int r0 = mBase + ((BN == 128) ? (wm * 32 + mt * 16) : (wm * 16)) + g;
        const int r1 = r0 + 8;
        #pragma unroll
        for (int nt = 0; nt < 8; nt++) {
            const int col = nBase + wn * 64 + nt * 8 + 2 * tg;
            const float b0 = bias[col], b1 = bias[col + 1];
            float e00 = acc[mt][nt][0] + b0, e01 = acc[mt][nt][1] + b1;
            float e10 = acc[mt][nt][2] + b0, e11 = acc[mt][nt][3] + b1;
            const size_t i0 = (size_t)r0 * ldc + col;
            const size_t i1 = (size_t)r1 * ldc + col;
            if (MODE == 0 || MODE == 5) {
                *(float2*)&C[i0] = make_float2(e00, e01);
                *(float2*)&C[i1] = make_float2(e10, e11);
            } else if (MODE == 1) {
                const float2 a0v = *(const float2*)&aux1[i0];
                const float2 a1v = *(const float2*)&aux1[i1];
                const float2 m0v = *(const float2*)&aux2[i0];
                const float2 m1v = *(const float2*)&aux2[i1];
                *(float2*)&C[i0] = make_float2(e00 + a0v.x + 0.1f * m0v.x,
                                               e01 + a0v.y + 0.1f * m0v.y);
                *(float2*)&C[i1] = make_float2(e10 + a1v.x + 0.1f * m1v.x,
                                               e11 + a1v.y + 0.1f * m1v.y);
            } else if (MODE == 2) {
                e00 = 0.5f * e00 * (1.f + erff(e00 * 0.7071067811865475f));
                e01 = 0.5f * e01 * (1.f + erff(e01 * 0.7071067811865475f));
                e10 = 0.5f * e10 * (1.f + erff(e10 * 0.7071067811865475f));
                e11 = 0.5f * e11 * (1.f + erff(e11 * 0.7071067811865475f));
                *(float2*)&C[i0] = make_float2(e00, e01);
                *(float2*)&C[i1] = make_float2(e10, e11);
            } else if (MODE == 3) {
                const float2 a0v = *(const float2*)&aux1[i0];
                const float2 a1v = *(const float2*)&aux1[i1];
                *(float2*)&C[i0] = make_float2(e00 + a0v.x, e01 + a0v.y);
                *(float2*)&C[i1] = make_float2(e10 + a1v.x, e11 + a1v.y);
            } else {
                const float2 p0 = *(const float2*)&aux1[i0];
                const float2 p1 = *(const float2*)&aux1[i1];
                const float2 q0 = *(const float2*)&aux2[i0];
                const float2 q1 = *(const float2*)&aux2[i1];
                *(float2*)&C[i0]  = make_float2(p0.x + e00, p0.y + e01);
                *(float2*)&C[i1]  = make_float2(p1.x + e10, p1.y + e11);
                *(float2*)&C2[i0] = make_float2(q0.x + e00, q0.y + e01);
                *(float2*)&C2[i1] = make_float2(q1.x + e10, q1.y + e11);
            }
        }
    }

    // -------- fused gate math (MODE 5, block covering cols 1536..1663) -----
    if (MODE == 5 && nBase == 1536) {
        __syncthreads();     // make this block's global C writes visible
        #pragma unroll
        for (int u = 0; u < 4; u++) {
            const int idx = u * 256 + tid;          // 0..1023 = 128 rows x 8 h
            const int row = mBase + (idx >> 3), h = idx & 7;
            const float* gp = C + (size_t)row * ldc + 1536;
            const float xd = gp[h], xgw = gp[8 + h], xgf = gp[16 + h];
            const float d  = fmaxf(xd, 0.f) + log1pf(expf(-fabsf(xd)));
            const float sw = 1.f / (1.f + expf(-xgw));
            const float sf = 1.f / (1.f + expf(-xgf));
            g_coef[row * NH + h] = d * (sw * sw);
            const float dec = fminf(fmaxf(d * (1.f - sf * sf), 1e-6f), 0.999f);
            g_logd[row * NH + h] = logf(dec);
        }
    }
}

// ------- cumsum of log-decay: two-level serial (64 chunks of 16) -----------
// Thread j accumulates its 16 elements in original order (registers), thread 0
// chains the 64 chunk totals, then each thread offsets its local prefixes.
__global__ __launch_bounds__(64) void cumsum_k() {
    __shared__ float csum[64];
    const int bh = blockIdx.x, b = bh >> 3, h = bh & 7;
    const int tid = threadIdx.x;
    const int t0 = tid * 16;

    float v[16];
    float acc = 0.f;
    #pragma unroll
    for (int i = 0; i < 16; i++) {
        acc += g_logd[(b * NT + t0 + i) * NH + h];
        v[i] = acc;
    }
    csum[tid] = acc;
    __syncthreads();
    if (tid == 0) {
        float a = 0.f;
        #pragma unroll
        for (int j = 0; j < 64; j++) {
            const float t = csum[j];
            csum[j] = a;
            a += t;
        }
    }
    __syncthreads();
    const float base = csum[tid];
    #pragma unroll
    for (int i = 0; i < 16; i++) {
        const float e = expf(base + v[i]);   // underflows to 0 like the ref
        g_ecum[bh * NT + t0 + i] = e;
        g_invd[bh * NT + t0 + i] = 1.f / (e + 1e-8f);
    }
}

// ============ chunked scan: phase 1 (per-chunk matmuls, no serial dep) =====
#define SP 68
__global__ __launch_bounds__(256) void scan_p1() {
    extern __shared__ float sm[];
    float* sK = sm;                 // [64][SP]
    float* sQ = sm + 64 * SP;
    float* sA = sm + 2 * 64 * SP;   // A[s][i] = tanh(v)*coef*invd
    float* sG = sm + 3 * 64 * SP;   // G[t][s] (causal)
    float* es = sm + 4 * 64 * SP;   // [64]
    const int tc = blockIdx.x, bh = blockIdx.y, b = bh >> 3, h = bh & 7;
    const int tid = threadIdx.x;

    // stage raw k/q + build A
    #pragma unroll
    for (int f = 0; f < 4; f++) {
        const int e4 = f * 256 + tid;
        const int tt = e4 >> 4, j4 = (e4 & 15) << 2;
        const int row = b * NT + tc * 64 + tt;
        const float* rp = g_kqv + (size_t)row * LDW + h * 64;
        *(float4*)&sK[tt * SP + j4] = *(const float4*)(rp + j4);
        *(float4*)&sQ[tt * SP + j4] = *(const float4*)(rp + 512 + j4);
        const float4 v = *(const float4*)(rp + 1024 + j4);
        const float sc = g_coef[row * NH + h] * g_invd[bh * NT + tc * 64 + tt];
        float4 a4;
        a4.x = tanhf(v.x) * sc; a4.y = tanhf(v.y) * sc;
        a4.z = tanhf(v.z) * sc; a4.w = tanhf(v.w) * sc;
        *(float4*)&sA[tt * SP + j4] = a4;
    }
    if (tid < 64) es[tid] = g_ecum[bh * NT + tc * 64 + tid];
    __syncthreads();

    // l2-normalize K,Q rows (4 threads per row)
    {
        const int nr = tid >> 2, nq = tid & 3;
        float sk = 0.f, sq = 0.f;
        #pragma unroll
        for (int e = 0; e < 16; e++) {
            const float kv = sK[nr * SP + nq * 16 + e];
            const float qv = sQ[nr * SP + nq * 16 + e];
            sk = fmaf(kv, kv, sk);
            sq = fmaf(qv, qv, sq);
        }
        sk += __shfl_xor_sync(~0u, sk, 1); sk += __shfl_xor_sync(~0u, sk, 2);
        sq += __shfl_xor_sync(~0u, sq, 1); sq += __shfl_xor_sync(~0u, sq, 2);
        const float ik = 1.f / fmaxf(sqrtf(sk), 1e-12f);
        const float iq = 1.f / fmaxf(sqrtf(sq), 1e-12f);
        #pragma unroll
        for (int e = 0; e < 16; e++) {
            sK[nr * SP + nq * 16 + e] *= ik;
            sQ[nr * SP + nq * 16 + e] *= iq;
        }
    }
    __syncthreads();

    // save normalized Q for phase 3
    #pragma unroll
    for (int f = 0; f < 4; f++) {
        const int e4 = f * 256 + tid;
        const int tt = e4 >> 4, j4 = (e4 & 15) << 2;
        *(float4*)&g_qn[((size_t)bh * NT + tc * 64 + tt) * 64 + j4] =
            *(const float4*)&sQ[tt * SP + j4];
    }

    // S_c[i][j] = sum_s A[s][i] * K[s][j]
    {
        const int i4 = (tid & 15) * 4, j4 = (tid >> 4) * 4;
        float acc[4][4];
        #pragma unroll
        for (int a = 0; a < 4; a++)
            #pragma unroll
            for (int c = 0; c < 4; c++) acc[a][c] = 0.f;
        for (int s = 0; s < 64; s++) {
            float av[4], kv[4];
            #pragma unroll
            for (int a = 0; a < 4; a++) av[a] = sA[s * SP + i4 + a];
            #pragma unroll
            for (int c = 0; c < 4; c++) kv[c] = sK[s * SP + j4 + c];
            #pragma unroll
            for (int a = 0; a < 4; a++)
                #pragma unroll
                for (int c = 0; c < 4; c++) acc[a][c] = fmaf(av[a], kv[c], acc[a][c]);
        }
        float* Sp = g_S + ((size_t)bh * NC + tc) * 4096;
        #pragma unroll
        for (int a = 0; a < 4; a++)
            #pragma unroll
            for (int c = 0; c < 4; c++) Sp[(i4 + a) * 64 + j4 + c] = acc[a][c];
    }

    // G[t][s] = q_t . k_s  (causal)
    {
        const int t4 = (tid & 15) * 4, s4 = (tid >> 4) * 4;
        float acc[4][4];
        #pragma unroll
        for (int a = 0; a < 4; a++)
            #pragma unroll
            for (int c = 0; c < 4; c++) acc[a][c] = 0.f;
        if (s4 <= t4 + 3) {
            for (int j = 0; j < 64; j++) {
                float qv[4], kv[4];
                #pragma unroll
                for (int a = 0; a < 4; a++) qv[a] = sQ[(t4 + a) * SP + j];
                #pragma unroll
                for (int c = 0; c < 4; c++) kv[c] = sK[(s4 + c) * SP + j];
                #pragma unroll
                for (int a = 0; a < 4; a++)
                    #pragma unroll
                    for (int c = 0; c < 4; c++) acc[a][c] = fmaf(qv[a], kv[c], acc[a][c]);
            }
        }
        #pragma unroll
        for (int a = 0; a < 4; a++)
            #pragma unroll
            for (int c = 0; c < 4; c++)
                sG[(t4 + a) * SP + s4 + c] = (s4 + c <= t4 + a) ? acc[a][c] : 0.f;
    }
    __syncthreads();

    // r_local[t][i] = sum_{s<=t} G[t][s] * A[s][i]; store es_t * r_local
    {
        const int t4 = (tid & 15) * 4, i4 = (tid >> 4) * 4;
        float acc[4][4];
        #pragma unroll
        for (int a = 0; a < 4; a++)
            #pragma unroll
            for (int c = 0; c < 4; c++) acc[a][c] = 0.f;
        const int smax = t4 + 4;
        for (int s = 0; s < smax; s++) {
            float gv[4], av[4];
            #pragma unroll
            for (int a = 0; a < 4; a++) gv[a] = sG[(t4 + a) * SP + s];
            #pragma unroll
            for (int c = 0; c < 4; c++) av[c] = sA[s * SP + i4 + c];
            #pragma unroll
            for (int a = 0; a < 4; a++)
                #pragma unroll
                for (int c = 0; c < 4; c++) acc[a][c] = fmaf(gv[a], av[c], acc[a][c]);
        }
        #pragma unroll
        for (int a = 0; a < 4; a++) {
            const float e = es[t4 + a];
            const size_t ro = (size_t)(b * NT + tc * 64 + t4 + a) * NHD + h * 64;
            #pragma unroll
            for (int c = 0; c < 4; c++) g_read[ro + i4 + c] = e * acc[a][c];
        }
    }
}

// ============ phase 2: exclusive prefix of chunk sums + next_mem ===========
__global__ __launch_bounds__(256) void scan_p2(float* __restrict__ next_mem) {
    const int bh = blockIdx.x;
    const int e  = blockIdx.y * 256 + threadIdx.x;      // 0..4095
    const float elast = g_ecum[bh * NT + NT - 1];
    float acc = 0.f;
    #pragma unroll
    for (int c = 0; c < NC; c++) {
        g_P[((size_t)bh * NC + c) * 4096 + e] = acc;
        acc += g_S[((size_t)bh * NC + c) * 4096 + e];
    }
    next_mem[(size_t)bh * 4096 + e] = acc * elast;
}

// ============ phase 3: cross term r += es_t * (P_{c-1} q_t) ================
__global__ __launch_bounds__(256) void scan_p3() {
    __shared__ float sQ[64 * SP];
    __shared__ float sP[64 * SP];     // P[i][j]
    __shared__ float es[64];
    const int tc = blockIdx.x + 1, bh = blockIdx.y, b = bh >> 3, h = bh & 7;
    const int tid = threadIdx.x;
    #pragma unroll
    for (int f = 0; f < 4; f++) {
        const int e4 = f * 256 + tid;
        const int tt = e4 >> 4, j4 = (e4 & 15) << 2;
        *(float4*)&sQ[tt * SP + j4] =
            *(const float4*)&g_qn[((size_t)bh * NT + tc * 64 + tt) * 64 + j4];
        *(float4*)&sP[tt * SP + j4] =
            *(const float4*)&g_P[((size_t)bh * NC + tc) * 4096 + tt * 64 + j4];
    }
    if (tid < 64) es[tid] = g_ecum[bh * NT + tc * 64 + tid];
    __syncthreads();

    const int t4 = (tid & 15) * 4, i4 = (tid >> 4) * 4;
    float acc[4][4];
    #pragma unroll
    for (int a = 0; a < 4; a++)
        #pragma unroll
        for (int c = 0; c < 4; c++) acc[a][c] = 0.f;
    for (int j = 0; j < 64; j++) {
        float qv[4], pv[4];
        #pragma unroll
        for (int a = 0; a < 4; a++) qv[a] = sQ[(t4 + a) * SP + j];
        #pragma unroll
        for (int c = 0; c < 4; c++) pv[c] = sP[(i4 + c) * SP + j];
        #pragma unroll
        for (int a = 0; a < 4; a++)
            #pragma unroll
            for (int c = 0; c < 4; c++) acc[a][c] = fmaf(qv[a], pv[c], acc[a][c]);
    }
    #pragma unroll
    for (int a = 0; a < 4; a++) {
        const float e = es[t4 + a];
        const size_t ro = (size_t)(b * NT + tc * 64 + t4 + a) * NHD + h * 64;
        #pragma unroll
        for (int c = 0; c < 4; c++) g_read[ro + i4 + c] += e * acc[a][c];
    }
}

// ---------------------------------------------------------------- launch ---
static float* sym(const void* s) {
    void* p = nullptr;
    cudaGetSymbolAddress(&p, s);
    return (float*)p;
}

extern "C" void kernel_launch(void* const* d_in, const int* in_sizes, int n_in,
                              void* d_out, int out_size) {
    const float* x     = (const float*)d_in[0];
    const float* b_min = (const float*)d_in[1];
    const float* b_max = (const float*)d_in[2];
    const float* motif = (const float*)d_in[3];
    const float* Wk    = (const float*)d_in[4];
    const float* bk    = (const float*)d_in[5];
    const float* Wq    = (const float*)d_in[6];
    const float* bq    = (const float*)d_in[7];
    const float* Wv    = (const float*)d_in[8];
    const float* bv    = (const float*)d_in[9];
    const float* Wo    = (const float*)d_in[10];
    const float* bo    = (const float*)d_in[11];
    const float* Wd    = (const float*)d_in[12];
    const float* bd    = (const float*)d_in[13];
    const float* Wgw   = (const float*)d_in[14];
    const float* bgw   = (const float*)d_in[15];
    const float* Wgf   = (const float*)d_in[16];
    const float* bgf   = (const float*)d_in[17];
    const float* Wps   = (const float*)d_in[18];
    const float* bps   = (const float*)d_in[19];
    const float* ln1g  = (const float*)d_in[20];
    const float* ln1b  = (const float*)d_in[21];
    const float* ln2g  = (const float*)d_in[22];
    const float* ln2b  = (const float*)d_in[23];
    const float* W1    = (const float*)d_in[24];
    const float* b1    = (const float*)d_in[25];
    const float* W2    = (const float*)d_in[26];
    const float* b2    = (const float*)d_in[27];

    float* out    = (float*)d_out;
    float* out_x3 = out;                            // [2,1024,512]
    float* out_nm = out + (size_t)NROWS * NE;       // [2,8,64,64]
    float* out_pm = out_nm + NBH * ND * ND;         // b_min + probe
    float* out_px = out_pm + (size_t)NROWS * NE;    // b_max + probe

    float* xn   = sym(g_xn);
    float* Wkqv = sym(g_Wkqv);
    float* bkqv = sym(g_bkqv);
    float* kqv  = sym(g_kqv);
    float* rd   = sym(g_read);
    float* x2   = sym(g_x2);
    float* hh   = sym(g_hh);
    float* mid  = sym(g_mid);

    const int SM128 = 3 * (128 * APAD + 32 * 136) * 4;   // 107520
    const int SM64  = 3 * (128 * APAD + 32 * 72)  * 4;   // 82944
    const int SMP1  = (4 * 64 * SP + 64) * 4;            // 69888
    cudaFuncSetAttribute(tgemm_k<5,128>, cudaFuncAttributeMaxDynamicSharedMemorySize, SM128);
    cudaFuncSetAttribute(tgemm_k<2,128>, cudaFuncAttributeMaxDynamicSharedMemorySize, SM128);
    cudaFuncSetAttribute(tgemm_k<1,64>,  cudaFuncAttributeMaxDynamicSharedMemorySize, SM64);
    cudaFuncSetAttribute(tgemm_k<3,64>,  cudaFuncAttributeMaxDynamicSharedMemorySize, SM64);
    cudaFuncSetAttribute(tgemm_k<4,64>,  cudaFuncAttributeMaxDynamicSharedMemorySize, SM64);
    cudaFuncSetAttribute(scan_p1,        cudaFuncAttributeMaxDynamicSharedMemorySize, SMP1);

    ln_k<<<NROWS, 256>>>(x, ln1g, ln1b, xn);                                   // 0
    prep_all<<<(NE * LDW + 255) / 256, 256>>>(Wk, Wq, Wv, bk, bq, bv,
                                              Wd, bd, Wgw, bgw, Wgf, bgf);     // 1
    tgemm_k<5,128><<<dim3(13, 16), 256, SM128>>>(xn, Wkqv, bkqv, kqv,
                                                 512, LDW, LDW,
                                                 nullptr, nullptr, nullptr);   // 2
    cumsum_k<<<NBH, 64>>>();                                                   // 3
    scan_p1<<<dim3(NC, NBH), 256, SMP1>>>();                                   // 4
    scan_p2<<<dim3(NBH, 16), 256>>>(out_nm);                                   // 5
    scan_p3<<<dim3(NC - 1, NBH), 256>>>();                                     // 6

    tgemm_k<1,64><<<dim3(8, 16), 256, SM64>>>(rd, Wo, bo, x2, 512, 512, 512,
                                              x, motif, nullptr);              // 7
    ln_k<<<NROWS, 256>>>(x2, ln2g, ln2b, hh);                                  // 8
    tgemm_k<2,128><<<dim3(16, 16), 256, SM128>>>(hh, W1, b1, mid,
                                                 512, 2048, 2048,
                                                 nullptr, nullptr, nullptr);   // 9
    tgemm_k<3,64><<<dim3(8, 16), 256, SM64>>>(mid, W2, b2, out_x3,
                                              2048, 512, 512,
                                              x2, nullptr, nullptr);           // 10
    tgemm_k<4,64><<<dim3(8, 16), 256, SM64>>>(out_x3, Wps, bps, out_pm,
                                              512, 512, 512,
                                              b_min, b_max, out_px);           // 11
}

// round 9
// speedup vs baseline: 5.6051x; 1.0019x over previous
#include <cuda_runtime.h>
#include <math.h>

#define NE    512
#define NH    8
#define ND    64
#define NB    2
#define NT    1024
#define NHD   512
#define NROWS 2048          // B*T
#define NFFN  2048
#define NBH   16
#define NC    16            // chunks of 64 along T
#define LDW   1664          // packed fused-proj width (1536 kqv + 24 gates + pad)

// ------------------------------ scratch (static device globals; no allocs) --
static __device__ float g_xn  [NROWS * NE];          // LN1 output
static __device__ float g_Wkqv[NE * LDW];            // packed [Wk|Wq|Wv|Wd|Wgw|Wgf|0]
static __device__ float g_bkqv[LDW];
static __device__ float g_kqv [NROWS * LDW];         // raw k|q|v|gates (pre-activation)
static __device__ float g_coef[NROWS * NH];          // d*gw
static __device__ float g_logd[NROWS * NH];          // log(clip(d*gf))
static __device__ float g_ecum[NBH * NT];            // exp(cumsum(log decay))
static __device__ float g_invd[NBH * NT];            // 1/(ecum+1e-8)
static __device__ float g_read[NROWS * NHD];         // readout
static __device__ float g_x2  [NROWS * NE];
static __device__ float g_hh  [NROWS * NE];          // LN2 output
static __device__ float g_mid [NROWS * NFFN];        // gelu(h@W1+b1)
static __device__ float g_qn  [NBH * NT * 64];       // normalized q
static __device__ float g_S   [NBH * NC * 64 * 64];  // per-chunk state sums
static __device__ float g_P   [NBH * NC * 64 * 64];  // exclusive prefixes

// ------------------- single-pass LayerNorm (sum + sumsq together) ----------
__device__ __forceinline__ void ln_body(const float* __restrict__ x,
                                        const float* __restrict__ g,
                                        const float* __restrict__ b,
                                        float* __restrict__ o,
                                        int row, int tid, float* sh) {
    const float v0 = x[(size_t)row * NE + tid];
    const float v1 = x[(size_t)row * NE + tid + 256];

    float s  = v0 + v1;
    float s2 = v0 * v0 + v1 * v1;
    #pragma unroll
    for (int off = 16; off; off >>= 1) {
        s  += __shfl_xor_sync(~0u, s,  off);
        s2 += __shfl_xor_sync(~0u, s2, off);
    }
    if ((tid & 31) == 0) { sh[tid >> 5] = s; sh[8 + (tid >> 5)] = s2; }
    __syncthreads();
    if (tid < 32) {
        float t  = (tid < 8) ? sh[tid] : 0.f;
        float t2 = (tid < 8) ? sh[8 + tid] : 0.f;
        #pragma unroll
        for (int off = 4; off; off >>= 1) {
            t  += __shfl_xor_sync(~0u, t,  off);
            t2 += __shfl_xor_sync(~0u, t2, off);
        }
        if (tid == 0) { sh[0] = t; sh[8] = t2; }
    }
    __syncthreads();
    const float mu  = sh[0] * (1.f / NE);
    const float var = sh[8] * (1.f / NE) - mu * mu;
    const float inv = 1.f / sqrtf(var + 1e-5f);

    o[(size_t)row * NE + tid]       = (v0 - mu) * inv * g[tid]       + b[tid];
    o[(size_t)row * NE + tid + 256] = (v1 - mu) * inv * g[tid + 256] + b[tid + 256];
}

__global__ __launch_bounds__(256) void ln_k(const float* __restrict__ x,
                                            const float* __restrict__ g,
                                            const float* __restrict__ b,
                                            float* __restrict__ o) {
    __shared__ float sh[16];
    ln_body(x, g, b, o, blockIdx.x, threadIdx.x, sh);
}

// --------- fused: ln1 (blocks 0..2047) + weight/bias packing (rest) --------
__global__ __launch_bounds__(256) void ln_prep_k(
    const float* __restrict__ x, const float* __restrict__ ln1g,
    const float* __restrict__ ln1b,
    const float* __restrict__ Wk, const float* __restrict__ Wq,
    const float* __restrict__ Wv, const float* __restrict__ bk,
    const float* __restrict__ bq, const float* __restrict__ bv,
    const float* __restrict__ Wd,  const float* __restrict__ bd,
    const float* __restrict__ Wgw, const float* __restrict__ bgw,
    const float* __restrict__ Wgf, const float* __restrict__ bgf) {
    __shared__ float sh[16];
    if (blockIdx.x < NROWS) {
        ln_body(x, ln1g, ln1b, g_xn, blockIdx.x, threadIdx.x, sh);
        return;
    }
    const int idx = (blockIdx.x - NROWS) * 256 + threadIdx.x;  // over 512*1664
    if (idx >= NE * LDW) return;
    const int r = idx / LDW, c = idx % LDW;
    float w;
    if (c < 512)        w = Wk[r * NHD + c];
    else if (c < 1024)  w = Wq[r * NHD + (c - 512)];
    else if (c < 1536)  w = Wv[r * NHD + (c - 1024)];
    else if (c < 1544)  w = Wd [r * NH + (c - 1536)];
    else if (c < 1552)  w = Wgw[r * NH + (c - 1544)];
    else if (c < 1560)  w = Wgf[r * NH + (c - 1552)];
    else                w = 0.f;
    g_Wkqv[idx] = w;
    if (r == 0) {
        float bb;
        if (c < 512)        bb = bk[c];
        else if (c < 1024)  bb = bq[c - 512];
        else if (c < 1536)  bb = bv[c - 1024];
        else if (c < 1544)  bb = bd [c - 1536];
        else if (c < 1552)  bb = bgw[c - 1544];
        else if (c < 1560)  bb = bgf[c - 1552];
        else                bb = 0.f;
        g_bkqv[c] = bb;
    }
}

// ----------------------------------------------------- mma + cp.async ------
__device__ __forceinline__ void mma_tf32(float* d,
                                         unsigned int a0, unsigned int a1,
                                         unsigned int a2, unsigned int a3,
                                         unsigned int b0, unsigned int b1) {
    asm volatile(
        "mma.sync.aligned.m16n8k8.row.col.f32.tf32.tf32.f32 "
        "{%0,%1,%2,%3}, {%4,%5,%6,%7}, {%8,%9}, {%0,%1,%2,%3};"
        : "+f"(d[0]), "+f"(d[1]), "+f"(d[2]), "+f"(d[3])
        : "r"(a0), "r"(a1), "r"(a2), "r"(a3), "r"(b0), "r"(b1));
}

__device__ __forceinline__ void cpasync16(void* s, const void* g) {
    unsigned int sa = (unsigned int)__cvta_generic_to_shared(s);
    asm volatile("cp.async.cg.shared.global [%0], [%1], 16;" :: "r"(sa), "l"(g));
}
#define CP_COMMIT()  asm volatile("cp.async.commit_group;")
#define CP_WAIT(n)   asm volatile("cp.async.wait_group %0;" :: "n"(n))

// -------- tf32 tensor-core GEMM, 3-stage cp.async, 1 sync per iter ---------
// MODE 1: C = A@B + bias + aux1 + 0.1*aux2
// MODE 2: C = gelu_exact(A@B + bias)
// MODE 3: C = A@B + bias + aux1
// MODE 4: C = aux1 + v; C2 = aux2 + v
// MODE 5: C = A@B + bias, plus fused gate math on the block covering 1536+
#define APAD 36
template <int MODE, int BN>
__global__ __launch_bounds__(256, 2) void tgemm_k(
    const float* __restrict__ A, const float* __restrict__ B,
    const float* __restrict__ bias, float* __restrict__ C,
    int K, int N, int ldc,
    const float* __restrict__ aux1, const float* __restrict__ aux2,
    float* __restrict__ C2) {
    constexpr int BPAD = BN + 8;
    constexpr int MT   = (BN == 128) ? 2 : 1;
    constexpr int ASZ  = 128 * APAD;
    constexpr int BSZ  = 32 * BPAD;
    extern __shared__ float sm[];
    float* Abuf = sm;                       // 3 stages of [128][APAD]
    float* Bbuf = sm + 3 * ASZ;             // 3 stages of [32][BPAD]

    const int tid  = threadIdx.x;
    const int warp = tid >> 5, lane = tid & 31;
    const int g    = lane >> 2, tg = lane & 3;
    const int wm   = (BN == 128) ? (warp >> 1) : warp;
    const int wn   = (BN == 128) ? (warp & 1)  : 0;
    const int mBase = blockIdx.y * 128;
    const int nBase = blockIdx.x * BN;

    float acc[MT][8][4];
    #pragma unroll
    for (int mt = 0; mt < MT; mt++)
        #pragma unroll
        for (int nt = 0; nt < 8; nt++)
            #pragma unroll
            for (int e = 0; e < 4; e++) acc[mt][nt][e] = 0.f;

    const int nT = K >> 5;
    const int aRow = tid >> 3, aC4 = (tid & 7) << 2;
    constexpr int BQ = BN / 4;
    const int bRow = tid / BQ, bC4 = (tid % BQ) << 2;
    constexpr int BROWSTEP = 256 / BQ;

    auto load_stage = [&](int t, int st) {
        const int ks = t << 5;
        float* As = Abuf + st * ASZ;
        float* Bs = Bbuf + st * BSZ;
        #pragma unroll
        for (int i = 0; i < 4; i++) {
            const int row = aRow + 32 * i;
            cpasync16(&As[row * APAD + aC4],
                      A + (size_t)(mBase + row) * K + ks + aC4);
        }
        #pragma unroll
        for (int i = 0; i < 32 / BROWSTEP; i++) {
            const int row = bRow + BROWSTEP * i;
            cpasync16(&Bs[row * BPAD + bC4],
                      B + (size_t)(ks + row) * N + nBase + bC4);
        }
        CP_COMMIT();
    };

    load_stage(0, 0);
    load_stage(1, 1);

    int st = 0;                              // stage of iteration t
    for (int t = 0; t < nT; t++) {
        if (t == nT - 1) { CP_WAIT(0); } else { CP_WAIT(1); }
        __syncthreads();
        if (t + 2 < nT) {
            int st2 = st + 2; if (st2 >= 3) st2 -= 3;
            load_stage(t + 2, st2);
        }
        const float* As = Abuf + st * ASZ;
        const float* Bs = Bbuf + st * BSZ;

        #pragma unroll
        for (int k8 = 0; k8 < 4; k8++) {
            const int kk = k8 << 3;
            unsigned int bf[8][2];
            #pragma unroll
            for (int nt = 0; nt < 8; nt++) {
                const int n = wn * 64 + nt * 8 + g;
                bf[nt][0] = __float_as_uint(Bs[(kk + tg) * BPAD + n]);
                bf[nt][1] = __float_as_uint(Bs[(kk + tg + 4) * BPAD + n]);
            }
            #pragma unroll
            for (int mt = 0; mt < MT; mt++) {
                const int m = (BN == 128) ? (wm * 32 + mt * 16) : (wm * 16);
                const unsigned int a0 = __float_as_uint(As[(m + g) * APAD + kk + tg]);
                const unsigned int a1 = __float_as_uint(As[(m + g + 8) * APAD + kk + tg]);
                const unsigned int a2 = __float_as_uint(As[(m + g) * APAD + kk + tg + 4]);
                const unsigned int a3 = __float_as_uint(As[(m + g + 8) * APAD + kk + tg + 4]);
                #pragma unroll
                for (int nt = 0; nt < 8; nt++)
                    mma_tf32(acc[mt][nt], a0, a1, a2, a3, bf[nt][0], bf[nt][1]);
            }
        }
        if (++st >= 3) st -= 3;
    }

    #pragma unroll
    for (int mt = 0; mt < MT; mt++) {
        const int r0 = mBase + ((BN == 128) ? (wm * 32 + mt * 16) : (wm * 16)) + g;
        const int r1 = r0 + 8;
        #pragma unroll
        for (int nt = 0; nt < 8; nt++) {
            const int col = nBase + wn * 64 + nt * 8 + 2 * tg;
            const float b0 = bias[col], b1 = bias[col + 1];
            float e00 = acc[mt][nt][0] + b0, e01 = acc[mt][nt][1] + b1;
            float e10 = acc[mt][nt][2] + b0, e11 = acc[mt][nt][3] + b1;
            const size_t i0 = (size_t)r0 * ldc + col;
            const size_t i1 = (size_t)r1 * ldc + col;
            if (MODE == 5) {
                *(float2*)&C[i0] = make_float2(e00, e01);
                *(float2*)&C[i1] = make_float2(e10, e11);
            } else if (MODE == 1) {
                const float2 a0v = *(const float2*)&aux1[i0];
                const float2 a1v = *(const float2*)&aux1[i1];
                const float2 m0v = *(const float2*)&aux2[i0];
                const float2 m1v = *(const float2*)&aux2[i1];
                *(float2*)&C[i0] = make_float2(e00 + a0v.x + 0.1f * m0v.x,
                                               e01 + a0v.y + 0.1f * m0v.y);
                *(float2*)&C[i1] = make_float2(e10 + a1v.x + 0.1f * m1v.x,
                                               e11 + a1v.y + 0.1f * m1v.y);
            } else if (MODE == 2) {
                e00 = 0.5f * e00 * (1.f + erff(e00 * 0.7071067811865475f));
                e01 = 0.5f * e01 * (1.f + erff(e01 * 0.7071067811865475f));
                e10 = 0.5f * e10 * (1.f + erff(e10 * 0.7071067811865475f));
                e11 = 0.5f * e11 * (1.f + erff(e11 * 0.7071067811865475f));
                *(float2*)&C[i0] = make_float2(e00, e01);
                *(float2*)&C[i1] = make_float2(e10, e11);
            } else if (MODE == 3) {
                const float2 a0v = *(const float2*)&aux1[i0];
                const float2 a1v = *(const float2*)&aux1[i1];
                *(float2*)&C[i0] = make_float2(e00 + a0v.x, e01 + a0v.y);
                *(float2*)&C[i1] = make_float2(e10 + a1v.x, e11 + a1v.y);
            } else {
                const float2 p0 = *(const float2*)&aux1[i0];
                const float2 p1 = *(const float2*)&aux1[i1];
                const float2 q0 = *(const float2*)&aux2[i0];
                const float2 q1 = *(const float2*)&aux2[i1];
                *(float2*)&C[i0]  = make_float2(p0.x + e00, p0.y + e01);
                *(float2*)&C[i1]  = make_float2(p1.x + e10, p1.y + e11);
                *(float2*)&C2[i0] = make_float2(q0.x + e00, q0.y + e01);
                *(float2*)&C2[i1] = make_float2(q1.x + e10, q1.y + e11);
            }
        }
    }

    // -------- fused gate math (MODE 5, block covering cols 1536..1663) -----
    if (MODE == 5 && nBase == 1536) {
        __syncthreads();     // make this block's global C writes visible
        #pragma unroll
        for (int u = 0; u < 4; u++) {
            const int idx = u * 256 + tid;          // 0..1023 = 128 rows x 8 h
            const int row = mBase + (idx >> 3), h = idx & 7;
            const float* gp = C + (size_t)row * ldc + 1536;
            const float xd = gp[h], xgw = gp[8 + h], xgf = gp[16 + h];
            const float d  = fmaxf(xd, 0.f) + log1pf(expf(-fabsf(xd)));
            const float sw = 1.f / (1.f + expf(-xgw));
            const float sf = 1.f / (1.f + expf(-xgf));
            g_coef[row * NH + h] = d * (sw * sw);
            const float dec = fminf(fmaxf(d * (1.f - sf * sf), 1e-6f), 0.999f);
            g_logd[row * NH + h] = logf(dec);
        }
    }
}

// ------- cumsum of log-decay: two-level serial (64 chunks of 16) -----------
__global__ __launch_bounds__(64) void cumsum_k() {
    __shared__ float csum[64];
    const int bh = blockIdx.x, b = bh >> 3, h = bh & 7;
    const int tid = threadIdx.x;
    const int t0 = tid * 16;

    float v[16];
    float acc = 0.f;
    #pragma unroll
    for (int i = 0; i < 16; i++) {
        acc += g_logd[(b * NT + t0 + i) * NH + h];
        v[i] = acc;
    }
    csum[tid] = acc;
    __syncthreads();
    if (tid == 0) {
        float a = 0.f;
        #pragma unroll
        for (int j = 0; j < 64; j++) {
            const float t = csum[j];
            csum[j] = a;
            a += t;
        }
    }
    __syncthreads();
    const float base = csum[tid];
    #pragma unroll
    for (int i = 0; i < 16; i++) {
        const float e = expf(base + v[i]);   // underflows to 0 like the ref
        g_ecum[bh * NT + t0 + i] = e;
        g_invd[bh * NT + t0 + i] = 1.f / (e + 1e-8f);
    }
}

// ============ chunked scan: phase 1 (per-chunk matmuls, no serial dep) =====
#define SP 68
__global__ __launch_bounds__(256) void scan_p1() {
    extern __shared__ float sm[];
    float* sK = sm;                 // [64][SP]
    float* sQ = sm + 64 * SP;
    float* sA = sm + 2 * 64 * SP;   // A[s][i] = tanh(v)*coef*invd
    float* sG = sm + 3 * 64 * SP;   // G[t][s] (causal)
    float* es = sm + 4 * 64 * SP;   // [64]
    const int tc = blockIdx.x, bh = blockIdx.y, b = bh >> 3, h = bh & 7;
    const int tid = threadIdx.x;

    #pragma unroll
    for (int f = 0; f < 4; f++) {
        const int e4 = f * 256 + tid;
        const int tt = e4 >> 4, j4 = (e4 & 15) << 2;
        const int row = b * NT + tc * 64 + tt;
        const float* rp = g_kqv + (size_t)row * LDW + h * 64;
        *(float4*)&sK[tt * SP + j4] = *(const float4*)(rp + j4);
        *(float4*)&sQ[tt * SP + j4] = *(const float4*)(rp + 512 + j4);
        const float4 v = *(const float4*)(rp + 1024 + j4);
        const float sc = g_coef[row * NH + h] * g_invd[bh * NT + tc * 64 + tt];
        float4 a4;
        a4.x = tanhf(v.x) * sc; a4.y = tanhf(v.y) * sc;
        a4.z = tanhf(v.z) * sc; a4.w = tanhf(v.w) * sc;
        *(float4*)&sA[tt * SP + j4] = a4;
    }
    if (tid < 64) es[tid] = g_ecum[bh * NT + tc * 64 + tid];
    __syncthreads();

    {
        const int nr = tid >> 2, nq = tid & 3;
        float sk = 0.f, sq = 0.f;
        #pragma unroll
        for (int e = 0; e < 16; e++) {
            const float kv = sK[nr * SP + nq * 16 + e];
            const float qv = sQ[nr * SP + nq * 16 + e];
            sk = fmaf(kv, kv, sk);
            sq = fmaf(qv, qv, sq);
        }
        sk += __shfl_xor_sync(~0u, sk, 1); sk += __shfl_xor_sync(~0u, sk, 2);
        sq += __shfl_xor_sync(~0u, sq, 1); sq += __shfl_xor_sync(~0u, sq, 2);
        const float ik = 1.f / fmaxf(sqrtf(sk), 1e-12f);
        const float iq = 1.f / fmaxf(sqrtf(sq), 1e-12f);
        #pragma unroll
        for (int e = 0; e < 16; e++) {
            sK[nr * SP + nq * 16 + e] *= ik;
            sQ[nr * SP + nq * 16 + e] *= iq;
        }
    }
    __syncthreads();

    #pragma unroll
    for (int f = 0; f < 4; f++) {
        const int e4 = f * 256 + tid;
        const int tt = e4 >> 4, j4 = (e4 & 15) << 2;
        *(float4*)&g_qn[((size_t)bh * NT + tc * 64 + tt) * 64 + j4] =
            *(const float4*)&sQ[tt * SP + j4];
    }

    {
        const int i4 = (tid & 15) * 4, j4 = (tid >> 4) * 4;
        float acc[4][4];
        #pragma unroll
        for (int a = 0; a < 4; a++)
            #pragma unroll
            for (int c = 0; c < 4; c++) acc[a][c] = 0.f;
        for (int s = 0; s < 64; s++) {
            float av[4], kv[4];
            #pragma unroll
            for (int a = 0; a < 4; a++) av[a] = sA[s * SP + i4 + a];
            #pragma unroll
            for (int c = 0; c < 4; c++) kv[c] = sK[s * SP + j4 + c];
            #pragma unroll
            for (int a = 0; a < 4; a++)
                #pragma unroll
                for (int c = 0; c < 4; c++) acc[a][c] = fmaf(av[a], kv[c], acc[a][c]);
        }
        float* Sp = g_S + ((size_t)bh * NC + tc) * 4096;
        #pragma unroll
        for (int a = 0; a < 4; a++)
            #pragma unroll
            for (int c = 0; c < 4; c++) Sp[(i4 + a) * 64 + j4 + c] = acc[a][c];
    }

    {
        const int t4 = (tid & 15) * 4, s4 = (tid >> 4) * 4;
        float acc[4][4];
        #pragma unroll
        for (int a = 0; a < 4; a++)
            #pragma unroll
            for (int c = 0; c < 4; c++) acc[a][c] = 0.f;
        if (s4 <= t4 + 3) {
            for (int j = 0; j < 64; j++) {
                float qv[4], kv[4];
                #pragma unroll
                for (int a = 0; a < 4; a++) qv[a] = sQ[(t4 + a) * SP + j];
                #pragma unroll
                for (int c = 0; c < 4; c++) kv[c] = sK[(s4 + c) * SP + j];
                #pragma unroll
                for (int a = 0; a < 4; a++)
                    #pragma unroll
                    for (int c = 0; c < 4; c++) acc[a][c] = fmaf(qv[a], kv[c], acc[a][c]);
            }
        }
        #pragma unroll
        for (int a = 0; a < 4; a++)
            #pragma unroll
            for (int c = 0; c < 4; c++)
                sG[(t4 + a) * SP + s4 + c] = (s4 + c <= t4 + a) ? acc[a][c] : 0.f;
    }
    __syncthreads();

    {
        const int t4 = (tid & 15) * 4, i4 = (tid >> 4) * 4;
        float acc[4][4];
        #pragma unroll
        for (int a = 0; a < 4; a++)
            #pragma unroll
            for (int c = 0; c < 4; c++) acc[a][c] = 0.f;
        const int smax = t4 + 4;
        for (int s = 0; s < smax; s++) {
            float gv[4], av[4];
            #pragma unroll
            for (int a = 0; a < 4; a++) gv[a] = sG[(t4 + a) * SP + s];
            #pragma unroll
            for (int c = 0; c < 4; c++) av[c] = sA[s * SP + i4 + c];
            #pragma unroll
            for (int a = 0; a < 4; a++)
                #pragma unroll
                for (int c = 0; c < 4; c++) acc[a][c] = fmaf(gv[a], av[c], acc[a][c]);
        }
        #pragma unroll
        for (int a = 0; a < 4; a++) {
            const float e = es[t4 + a];
            const size_t ro = (size_t)(b * NT + tc * 64 + t4 + a) * NHD + h * 64;
            #pragma unroll
            for (int c = 0; c < 4; c++) g_read[ro + i4 + c] = e * acc[a][c];
        }
    }
}

// ============ phase 2: exclusive prefix of chunk sums + next_mem ===========
__global__ __launch_bounds__(256) void scan_p2(float* __restrict__ next_mem) {
    const int bh = blockIdx.x;
    const int e  = blockIdx.y * 256 + threadIdx.x;      // 0..4095
    const float elast = g_ecum[bh * NT + NT - 1];
    float acc = 0.f;
    #pragma unroll
    for (int c = 0; c < NC; c++) {
        g_P[((size_t)bh * NC + c) * 4096 + e] = acc;
        acc += g_S[((size_t)bh * NC + c) * 4096 + e];
    }
    next_mem[(size_t)bh * 4096 + e] = acc * elast;
}

// ============ phase 3: cross term r += es_t * (P_{c-1} q_t) ================
__global__ __launch_bounds__(256) void scan_p3() {
    __shared__ float sQ[64 * SP];
    __shared__ float sP[64 * SP];     // P[i][j]
    __shared__ float es[64];
    const int tc = blockIdx.x + 1, bh = blockIdx.y, b = bh >> 3, h = bh & 7;
    const int tid = threadIdx.x;
    #pragma unroll
    for (int f = 0; f < 4; f++) {
        const int e4 = f * 256 + tid;
        const int tt = e4 >> 4, j4 = (e4 & 15) << 2;
        *(float4*)&sQ[tt * SP + j4] =
            *(const float4*)&g_qn[((size_t)bh * NT + tc * 64 + tt) * 64 + j4];
        *(float4*)&sP[tt * SP + j4] =
            *(const float4*)&g_P[((size_t)bh * NC + tc) * 4096 + tt * 64 + j4];
    }
    if (tid < 64) es[tid] = g_ecum[bh * NT + tc * 64 + tid];
    __syncthreads();

    const int t4 = (tid & 15) * 4, i4 = (tid >> 4) * 4;
    float acc[4][4];
    #pragma unroll
    for (int a = 0; a < 4; a++)
        #pragma unroll
        for (int c = 0; c < 4; c++) acc[a][c] = 0.f;
    for (int j = 0; j < 64; j++) {
        float qv[4], pv[4];
        #pragma unroll
        for (int a = 0; a < 4; a++) qv[a] = sQ[(t4 + a) * SP + j];
        #pragma unroll
        for (int c = 0; c < 4; c++) pv[c] = sP[(i4 + c) * SP + j];
        #pragma unroll
        for (int a = 0; a < 4; a++)
            #pragma unroll
            for (int c = 0; c < 4; c++) acc[a][c] = fmaf(qv[a], pv[c], acc[a][c]);
    }
    #pragma unroll
    for (int a = 0; a < 4; a++) {
        const float e = es[t4 + a];
        const size_t ro = (size_t)(b * NT + tc * 64 + t4 + a) * NHD + h * 64;
        #pragma unroll
        for (int c = 0; c < 4; c++) g_read[ro + i4 + c] += e * acc[a][c];
    }
}

// ---------------------------------------------------------------- launch ---
static float* sym(const void* s) {
    void* p = nullptr;
    cudaGetSymbolAddress(&p, s);
    return (float*)p;
}

extern "C" void kernel_launch(void* const* d_in, const int* in_sizes, int n_in,
                              void* d_out, int out_size) {
    const float* x     = (const float*)d_in[0];
    const float* b_min = (const float*)d_in[1];
    const float* b_max = (const float*)d_in[2];
    const float* motif = (const float*)d_in[3];
    const float* Wk    = (const float*)d_in[4];
    const float* bk    = (const float*)d_in[5];
    const float* Wq    = (const float*)d_in[6];
    const float* bq    = (const float*)d_in[7];
    const float* Wv    = (const float*)d_in[8];
    const float* bv    = (const float*)d_in[9];
    const float* Wo    = (const float*)d_in[10];
    const float* bo    = (const float*)d_in[11];
    const float* Wd    = (const float*)d_in[12];
    const float* bd    = (const float*)d_in[13];
    const float* Wgw   = (const float*)d_in[14];
    const float* bgw   = (const float*)d_in[15];
    const float* Wgf   = (const float*)d_in[16];
    const float* bgf   = (const float*)d_in[17];
    const float* Wps   = (const float*)d_in[18];
    const float* bps   = (const float*)d_in[19];
    const float* ln1g  = (const float*)d_in[20];
    const float* ln1b  = (const float*)d_in[21];
    const float* ln2g  = (const float*)d_in[22];
    const float* ln2b  = (const float*)d_in[23];
    const float* W1    = (const float*)d_in[24];
    const float* b1    = (const float*)d_in[25];
    const float* W2    = (const float*)d_in[26];
    const float* b2    = (const float*)d_in[27];

    float* out    = (float*)d_out;
    float* out_x3 = out;                            // [2,1024,512]
    float* out_nm = out + (size_t)NROWS * NE;       // [2,8,64,64]
    float* out_pm = out_nm + NBH * ND * ND;         // b_min + probe
    float* out_px = out_pm + (size_t)NROWS * NE;    // b_max + probe

    float* xn   = sym(g_xn);
    float* Wkqv = sym(g_Wkqv);
    float* bkqv = sym(g_bkqv);
    float* kqv  = sym(g_kqv);
    float* rd   = sym(g_read);
    float* x2   = sym(g_x2);
    float* hh   = sym(g_hh);
    float* mid  = sym(g_mid);

    const int SM128 = 3 * (128 * APAD + 32 * 136) * 4;   // 107520
    const int SM64  = 3 * (128 * APAD + 32 * 72)  * 4;   // 82944
    const int SMP1  = (4 * 64 * SP + 64) * 4;            // 69888
    cudaFuncSetAttribute(tgemm_k<5,128>, cudaFuncAttributeMaxDynamicSharedMemorySize, SM128);
    cudaFuncSetAttribute(tgemm_k<2,128>, cudaFuncAttributeMaxDynamicSharedMemorySize, SM128);
    cudaFuncSetAttribute(tgemm_k<1,64>,  cudaFuncAttributeMaxDynamicSharedMemorySize, SM64);
    cudaFuncSetAttribute(tgemm_k<3,64>,  cudaFuncAttributeMaxDynamicSharedMemorySize, SM64);
    cudaFuncSetAttribute(tgemm_k<4,64>,  cudaFuncAttributeMaxDynamicSharedMemorySize, SM64);
    cudaFuncSetAttribute(scan_p1,        cudaFuncAttributeMaxDynamicSharedMemorySize, SMP1);

    // fused: LN1 (blocks 0..2047) + weight/bias packing (blocks 2048..)
    const int PREP_BLOCKS = (NE * LDW + 255) / 256;
    ln_prep_k<<<NROWS + PREP_BLOCKS, 256>>>(x, ln1g, ln1b,
                                            Wk, Wq, Wv, bk, bq, bv,
                                            Wd, bd, Wgw, bgw, Wgf, bgf);       // 0
    tgemm_k<5,128><<<dim3(13, 16), 256, SM128>>>(xn, Wkqv, bkqv, kqv,
                                                 512, LDW, LDW,
                                                 nullptr, nullptr, nullptr);   // 1
    cumsum_k<<<NBH, 64>>>();                                                   // 2
    scan_p1<<<dim3(NC, NBH), 256, SMP1>>>();                                   // 3
    scan_p2<<<dim3(NBH, 16), 256>>>(out_nm);                                   // 4
    scan_p3<<<dim3(NC - 1, NBH), 256>>>();                                     // 5 <- profiled

    tgemm_k<1,64><<<dim3(8, 16), 256, SM64>>>(rd, Wo, bo, x2, 512, 512, 512,
                                              x, motif, nullptr);              // 6
    ln_k<<<NROWS, 256>>>(x2, ln2g, ln2b, hh);                                  // 7
    tgemm_k<2,128><<<dim3(16, 16), 256, SM128>>>(hh, W1, b1, mid,
                                                 512, 2048, 2048,
                                                 nullptr, nullptr, nullptr);   // 8
    tgemm_k<3,64><<<dim3(8, 16), 256, SM64>>>(mid, W2, b2, out_x3,
                                              2048, 512, 512,
                                              x2, nullptr, nullptr);           // 9
    tgemm_k<4,64><<<dim3(8, 16), 256, SM64>>>(out_x3, Wps, bps, out_pm,
                                              512, 512, 512,
                                              b_min, b_max, out_px);           // 10
}

// round 10
// speedup vs baseline: 5.9973x; 1.0700x over previous
#include <cuda_runtime.h>
#include <math.h>

#define NE    512
#define NH    8
#define ND    64
#define NB    2
#define NT    1024
#define NHD   512
#define NROWS 2048          // B*T
#define NFFN  2048
#define NBH   16
#define NC    16            // chunks of 64 along T
#define LDW   1664          // packed fused-proj width (1536 kqv + 24 gates + pad)

// ------------------------------ scratch (static device globals; no allocs) --
static __device__ float g_xn  [NROWS * NE];          // LN1 output
static __device__ float g_Wkqv[NE * LDW];            // packed [Wk|Wq|Wv|Wd|Wgw|Wgf|0]
static __device__ float g_bkqv[LDW];
static __device__ float g_kqv [NROWS * LDW];         // raw k|q|v|gates (pre-activation)
static __device__ float g_coef[NROWS * NH];          // d*gw
static __device__ float g_logd[NROWS * NH];          // log(clip(d*gf))
static __device__ float g_ecum[NBH * NT];            // exp(cumsum(log decay))
static __device__ float g_invd[NBH * NT];            // 1/(ecum+1e-8)
static __device__ float g_read[NROWS * NHD];         // readout
static __device__ float g_x2  [NROWS * NE];
static __device__ float g_hh  [NROWS * NE];          // LN2 output
static __device__ float g_mid [NROWS * NFFN];        // gelu(h@W1+b1)
static __device__ float g_qn  [NBH * NC * 64 * 64];  // normalized q, TRANSPOSED [j][t]
static __device__ float g_S   [NBH * NC * 64 * 64];  // per-chunk state sums
static __device__ float g_P   [NBH * NC * 64 * 64];  // exclusive prefixes

// ------------------- single-pass LayerNorm (sum + sumsq together) ----------
__device__ __forceinline__ void ln_body(const float* __restrict__ x,
                                        const float* __restrict__ g,
                                        const float* __restrict__ b,
                                        float* __restrict__ o,
                                        int row, int tid, float* sh) {
    const float v0 = x[(size_t)row * NE + tid];
    const float v1 = x[(size_t)row * NE + tid + 256];

    float s  = v0 + v1;
    float s2 = v0 * v0 + v1 * v1;
    #pragma unroll
    for (int off = 16; off; off >>= 1) {
        s  += __shfl_xor_sync(~0u, s,  off);
        s2 += __shfl_xor_sync(~0u, s2, off);
    }
    if ((tid & 31) == 0) { sh[tid >> 5] = s; sh[8 + (tid >> 5)] = s2; }
    __syncthreads();
    if (tid < 32) {
        float t  = (tid < 8) ? sh[tid] : 0.f;
        float t2 = (tid < 8) ? sh[8 + tid] : 0.f;
        #pragma unroll
        for (int off = 4; off; off >>= 1) {
            t  += __shfl_xor_sync(~0u, t,  off);
            t2 += __shfl_xor_sync(~0u, t2, off);
        }
        if (tid == 0) { sh[0] = t; sh[8] = t2; }
    }
    __syncthreads();
    const float mu  = sh[0] * (1.f / NE);
    const float var = sh[8] * (1.f / NE) - mu * mu;
    const float inv = 1.f / sqrtf(var + 1e-5f);

    o[(size_t)row * NE + tid]       = (v0 - mu) * inv * g[tid]       + b[tid];
    o[(size_t)row * NE + tid + 256] = (v1 - mu) * inv * g[tid + 256] + b[tid + 256];
}

__global__ __launch_bounds__(256) void ln_k(const float* __restrict__ x,
                                            const float* __restrict__ g,
                                            const float* __restrict__ b,
                                            float* __restrict__ o) {
    __shared__ float sh[16];
    ln_body(x, g, b, o, blockIdx.x, threadIdx.x, sh);
}

// --------- fused: ln1 (blocks 0..2047) + weight/bias packing (rest) --------
__global__ __launch_bounds__(256) void ln_prep_k(
    const float* __restrict__ x, const float* __restrict__ ln1g,
    const float* __restrict__ ln1b,
    const float* __restrict__ Wk, const float* __restrict__ Wq,
    const float* __restrict__ Wv, const float* __restrict__ bk,
    const float* __restrict__ bq, const float* __restrict__ bv,
    const float* __restrict__ Wd,  const float* __restrict__ bd,
    const float* __restrict__ Wgw, const float* __restrict__ bgw,
    const float* __restrict__ Wgf, const float* __restrict__ bgf) {
    __shared__ float sh[16];
    if (blockIdx.x < NROWS) {
        ln_body(x, ln1g, ln1b, g_xn, blockIdx.x, threadIdx.x, sh);
        return;
    }
    const int idx = (blockIdx.x - NROWS) * 256 + threadIdx.x;  // over 512*1664
    if (idx >= NE * LDW) return;
    const int r = idx / LDW, c = idx % LDW;
    float w;
    if (c < 512)        w = Wk[r * NHD + c];
    else if (c < 1024)  w = Wq[r * NHD + (c - 512)];
    else if (c < 1536)  w = Wv[r * NHD + (c - 1024)];
    else if (c < 1544)  w = Wd [r * NH + (c - 1536)];
    else if (c < 1552)  w = Wgw[r * NH + (c - 1544)];
    else if (c < 1560)  w = Wgf[r * NH + (c - 1552)];
    else                w = 0.f;
    g_Wkqv[idx] = w;
    if (r == 0) {
        float bb;
        if (c < 512)        bb = bk[c];
        else if (c < 1024)  bb = bq[c - 512];
        else if (c < 1536)  bb = bv[c - 1024];
        else if (c < 1544)  bb = bd [c - 1536];
        else if (c < 1552)  bb = bgw[c - 1544];
        else if (c < 1560)  bb = bgf[c - 1552];
        else                bb = 0.f;
        g_bkqv[c] = bb;
    }
}

// ----------------------------------------------------- mma + cp.async ------
__device__ __forceinline__ void mma_tf32(float* d,
                                         unsigned int a0, unsigned int a1,
                                         unsigned int a2, unsigned int a3,
                                         unsigned int b0, unsigned int b1) {
    asm volatile(
        "mma.sync.aligned.m16n8k8.row.col.f32.tf32.tf32.f32 "
        "{%0,%1,%2,%3}, {%4,%5,%6,%7}, {%8,%9}, {%0,%1,%2,%3};"
        : "+f"(d[0]), "+f"(d[1]), "+f"(d[2]), "+f"(d[3])
        : "r"(a0), "r"(a1), "r"(a2), "r"(a3), "r"(b0), "r"(b1));
}

__device__ __forceinline__ void cpasync16(void* s, const void* g) {
    unsigned int sa = (unsigned int)__cvta_generic_to_shared(s);
    asm volatile("cp.async.cg.shared.global [%0], [%1], 16;" :: "r"(sa), "l"(g));
}
#define CP_COMMIT()  asm volatile("cp.async.commit_group;")
#define CP_WAIT(n)   asm volatile("cp.async.wait_group %0;" :: "n"(n))

// -------- tf32 tensor-core GEMM, 3-stage cp.async, 1 sync per iter ---------
// MODE 1: C = A@B + bias + aux1 + 0.1*aux2
// MODE 2: C = gelu_exact(A@B + bias)
// MODE 3: C = A@B + bias + aux1
// MODE 4: C = aux1 + v; C2 = aux2 + v
// MODE 5: C = A@B + bias, plus fused gate math on the block covering 1536+
#define APAD 36
template <int MODE, int BN>
__global__ __launch_bounds__(256, 2) void tgemm_k(
    const float* __restrict__ A, const float* __restrict__ B,
    const float* __restrict__ bias, float* __restrict__ C,
    int K, int N, int ldc,
    const float* __restrict__ aux1, const float* __restrict__ aux2,
    float* __restrict__ C2) {
    constexpr int BPAD = BN + 8;
    constexpr int MT   = (BN == 128) ? 2 : 1;
    constexpr int ASZ  = 128 * APAD;
    constexpr int BSZ  = 32 * BPAD;
    extern __shared__ float sm[];
    float* Abuf = sm;                       // 3 stages of [128][APAD]
    float* Bbuf = sm + 3 * ASZ;             // 3 stages of [32][BPAD]

    const int tid  = threadIdx.x;
    const int warp = tid >> 5, lane = tid & 31;
    const int g    = lane >> 2, tg = lane & 3;
    const int wm   = (BN == 128) ? (warp >> 1) : warp;
    const int wn   = (BN == 128) ? (warp & 1)  : 0;
    const int mBase = blockIdx.y * 128;
    const int nBase = blockIdx.x * BN;

    float acc[MT][8][4];
    #pragma unroll
    for (int mt = 0; mt < MT; mt++)
        #pragma unroll
        for (int nt = 0; nt < 8; nt++)
            #pragma unroll
            for (int e = 0; e < 4; e++) acc[mt][nt][e] = 0.f;

    const int nT = K >> 5;
    const int aRow = tid >> 3, aC4 = (tid & 7) << 2;
    constexpr int BQ = BN / 4;
    const int bRow = tid / BQ, bC4 = (tid % BQ) << 2;
    constexpr int BROWSTEP = 256 / BQ;

    auto load_stage = [&](int t, int st) {
        const int ks = t << 5;
        float* As = Abuf + st * ASZ;
        float* Bs = Bbuf + st * BSZ;
        #pragma unroll
        for (int i = 0; i < 4; i++) {
            const int row = aRow + 32 * i;
            cpasync16(&As[row * APAD + aC4],
                      A + (size_t)(mBase + row) * K + ks + aC4);
        }
        #pragma unroll
        for (int i = 0; i < 32 / BROWSTEP; i++) {
            const int row = bRow + BROWSTEP * i;
            cpasync16(&Bs[row * BPAD + bC4],
                      B + (size_t)(ks + row) * N + nBase + bC4);
        }
        CP_COMMIT();
    };

    load_stage(0, 0);
    load_stage(1, 1);

    int st = 0;                              // stage of iteration t
    for (int t = 0; t < nT; t++) {
        if (t == nT - 1) { CP_WAIT(0); } else { CP_WAIT(1); }
        __syncthreads();
        if (t + 2 < nT) {
            int st2 = st + 2; if (st2 >= 3) st2 -= 3;
            load_stage(t + 2, st2);
        }
        const float* As = Abuf + st * ASZ;
        const float* Bs = Bbuf + st * BSZ;

        #pragma unroll
        for (int k8 = 0; k8 < 4; k8++) {
            const int kk = k8 << 3;
            unsigned int bf[8][2];
            #pragma unroll
            for (int nt = 0; nt < 8; nt++) {
                const int n = wn * 64 + nt * 8 + g;
                bf[nt][0] = __float_as_uint(Bs[(kk + tg) * BPAD + n]);
                bf[nt][1] = __float_as_uint(Bs[(kk + tg + 4) * BPAD + n]);
            }
            #pragma unroll
            for (int mt = 0; mt < MT; mt++) {
                const int m = (BN == 128) ? (wm * 32 + mt * 16) : (wm * 16);
                const unsigned int a0 = __float_as_uint(As[(m + g) * APAD + kk + tg]);
                const unsigned int a1 = __float_as_uint(As[(m + g + 8) * APAD + kk + tg]);
                const unsigned int a2 = __float_as_uint(As[(m + g) * APAD + kk + tg + 4]);
                const unsigned int a3 = __float_as_uint(As[(m + g + 8) * APAD + kk + tg + 4]);
                #pragma unroll
                for (int nt = 0; nt < 8; nt++)
                    mma_tf32(acc[mt][nt], a0, a1, a2, a3, bf[nt][0], bf[nt][1]);
            }
        }
        if (++st >= 3) st -= 3;
    }

    #pragma unroll
    for (int mt = 0; mt < MT; mt++) {
        const int r0 = mBase + ((BN == 128) ? (wm * 32 + mt * 16) : (wm * 16)) + g;
        const int r1 = r0 + 8;
        #pragma unroll
        for (int nt = 0; nt < 8; nt++) {
            const int col = nBase + wn * 64 + nt * 8 + 2 * tg;
            const float b0 = bias[col], b1 = bias[col + 1];
            float e00 = acc[mt][nt][0] + b0, e01 = acc[mt][nt][1] + b1;
            float e10 = acc[mt][nt][2] + b0, e11 = acc[mt][nt][3] + b1;
            const size_t i0 = (size_t)r0 * ldc + col;
            const size_t i1 = (size_t)r1 * ldc + col;
            if (MODE == 5) {
                *(float2*)&C[i0] = make_float2(e00, e01);
                *(float2*)&C[i1] = make_float2(e10, e11);
            } else if (MODE == 1) {
                const float2 a0v = *(const float2*)&aux1[i0];
                const float2 a1v = *(const float2*)&aux1[i1];
                const float2 m0v = *(const float2*)&aux2[i0];
                const float2 m1v = *(const float2*)&aux2[i1];
                *(float2*)&C[i0] = make_float2(e00 + a0v.x + 0.1f * m0v.x,
                                               e01 + a0v.y + 0.1f * m0v.y);
                *(float2*)&C[i1] = make_float2(e10 + a1v.x + 0.1f * m1v.x,
                                               e11 + a1v.y + 0.1f * m1v.y);
            } else if (MODE == 2) {
                e00 = 0.5f * e00 * (1.f + erff(e00 * 0.7071067811865475f));
                e01 = 0.5f * e01 * (1.f + erff(e01 * 0.7071067811865475f));
                e10 = 0.5f * e10 * (1.f + erff(e10 * 0.7071067811865475f));
                e11 = 0.5f * e11 * (1.f + erff(e11 * 0.7071067811865475f));
                *(float2*)&C[i0] = make_float2(e00, e01);
                *(float2*)&C[i1] = make_float2(e10, e11);
            } else if (MODE == 3) {
                const float2 a0v = *(const float2*)&aux1[i0];
                const float2 a1v = *(const float2*)&aux1[i1];
                *(float2*)&C[i0] = make_float2(e00 + a0v.x, e01 + a0v.y);
                *(float2*)&C[i1] = make_float2(e10 + a1v.x, e11 + a1v.y);
            } else {
                const float2 p0 = *(const float2*)&aux1[i0];
                const float2 p1 = *(const float2*)&aux1[i1];
                const float2 q0 = *(const float2*)&aux2[i0];
                const float2 q1 = *(const float2*)&aux2[i1];
                *(float2*)&C[i0]  = make_float2(p0.x + e00, p0.y + e01);
                *(float2*)&C[i1]  = make_float2(p1.x + e10, p1.y + e11);
                *(float2*)&C2[i0] = make_float2(q0.x + e00, q0.y + e01);
                *(float2*)&C2[i1] = make_float2(q1.x + e10, q1.y + e11);
            }
        }
    }

    // -------- fused gate math (MODE 5, block covering cols 1536..1663) -----
    if (MODE == 5 && nBase == 1536) {
        __syncthreads();     // make this block's global C writes visible
        #pragma unroll
        for (int u = 0; u < 4; u++) {
            const int idx = u * 256 + tid;          // 0..1023 = 128 rows x 8 h
            const int row = mBase + (idx >> 3), h = idx & 7;
            const float* gp = C + (size_t)row * ldc + 1536;
            const float xd = gp[h], xgw = gp[8 + h], xgf = gp[16 + h];
            const float d  = fmaxf(xd, 0.f) + log1pf(expf(-fabsf(xd)));
            const float sw = 1.f / (1.f + expf(-xgw));
            const float sf = 1.f / (1.f + expf(-xgf));
            g_coef[row * NH + h] = d * (sw * sw);
            const float dec = fminf(fmaxf(d * (1.f - sf * sf), 1e-6f), 0.999f);
            g_logd[row * NH + h] = logf(dec);
        }
    }
}

// ------- cumsum of log-decay: two-level serial (64 chunks of 16) -----------
__global__ __launch_bounds__(64) void cumsum_k() {
    __shared__ float csum[64];
    const int bh = blockIdx.x, b = bh >> 3, h = bh & 7;
    const int tid = threadIdx.x;
    const int t0 = tid * 16;

    float v[16];
    float acc = 0.f;
    #pragma unroll
    for (int i = 0; i < 16; i++) {
        acc += g_logd[(b * NT + t0 + i) * NH + h];
        v[i] = acc;
    }
    csum[tid] = acc;
    __syncthreads();
    if (tid == 0) {
        float a = 0.f;
        #pragma unroll
        for (int j = 0; j < 64; j++) {
            const float t = csum[j];
            csum[j] = a;
            a += t;
        }
    }
    __syncthreads();
    const float base = csum[tid];
    #pragma unroll
    for (int i = 0; i < 16; i++) {
        const float e = expf(base + v[i]);   // underflows to 0 like the ref
        g_ecum[bh * NT + t0 + i] = e;
        g_invd[bh * NT + t0 + i] = 1.f / (e + 1e-8f);
    }
}

// 4x4 outer-product accumulate: acc[a][c] += q[a] * p[c] (float4 components)
#define OP16(acc, q, p) do {                                                  \
    acc[0][0] = fmaf((q).x, (p).x, acc[0][0]);                                \
    acc[0][1] = fmaf((q).x, (p).y, acc[0][1]);                                \
    acc[0][2] = fmaf((q).x, (p).z, acc[0][2]);                                \
    acc[0][3] = fmaf((q).x, (p).w, acc[0][3]);                                \
    acc[1][0] = fmaf((q).y, (p).x, acc[1][0]);                                \
    acc[1][1] = fmaf((q).y, (p).y, acc[1][1]);                                \
    acc[1][2] = fmaf((q).y, (p).z, acc[1][2]);                                \
    acc[1][3] = fmaf((q).y, (p).w, acc[1][3]);                                \
    acc[2][0] = fmaf((q).z, (p).x, acc[2][0]);                                \
    acc[2][1] = fmaf((q).z, (p).y, acc[2][1]);                                \
    acc[2][2] = fmaf((q).z, (p).z, acc[2][2]);                                \
    acc[2][3] = fmaf((q).z, (p).w, acc[2][3]);                                \
    acc[3][0] = fmaf((q).w, (p).x, acc[3][0]);                                \
    acc[3][1] = fmaf((q).w, (p).y, acc[3][1]);                                \
    acc[3][2] = fmaf((q).w, (p).z, acc[3][2]);                                \
    acc[3][3] = fmaf((q).w, (p).w, acc[3][3]);                                \
} while (0)

// ============ chunked scan: phase 1 (conflict-free via transposes) =========
#define SP 68
__global__ __launch_bounds__(256) void scan_p1() {
    extern __shared__ float sm[];
    float* sK  = sm;                  // [t][j] row-major
    float* sQ  = sm + 64 * SP;        // [t][j]
    float* sA  = sm + 2 * 64 * SP;    // [s][i] = tanh(v)*coef*invd
    float* sQt = sm + 3 * 64 * SP;    // [j][t] transposed
    float* sKt = sm + 4 * 64 * SP;    // [j][s] transposed
    float* sGt = sm + 5 * 64 * SP;    // [s][t] causal-zeroed (G transposed)
    float* es  = sm + 6 * 64 * SP;    // [64]
    const int tc = blockIdx.x, bh = blockIdx.y, b = bh >> 3, h = bh & 7;
    const int tid = threadIdx.x;

    // stage raw k/q + build A
    #pragma unroll
    for (int f = 0; f < 4; f++) {
        const int e4 = f * 256 + tid;
        const int tt = e4 >> 4, j4 = (e4 & 15) << 2;
        const int row = b * NT + tc * 64 + tt;
        const float* rp = g_kqv + (size_t)row * LDW + h * 64;
        *(float4*)&sK[tt * SP + j4] = *(const float4*)(rp + j4);
        *(float4*)&sQ[tt * SP + j4] = *(const float4*)(rp + 512 + j4);
        const float4 v = *(const float4*)(rp + 1024 + j4);
        const float sc = g_coef[row * NH + h] * g_invd[bh * NT + tc * 64 + tt];
        float4 a4;
        a4.x = tanhf(v.x) * sc; a4.y = tanhf(v.y) * sc;
        a4.z = tanhf(v.z) * sc; a4.w = tanhf(v.w) * sc;
        *(float4*)&sA[tt * SP + j4] = a4;
    }
    if (tid < 64) es[tid] = g_ecum[bh * NT + tc * 64 + tid];
    __syncthreads();

    // l2-normalize K,Q rows (4 threads per row)
    {
        const int nr = tid >> 2, nq = tid & 3;
        float sk = 0.f, sq = 0.f;
        #pragma unroll
        for (int e = 0; e < 16; e++) {
            const float kv = sK[nr * SP + nq * 16 + e];
            const float qv = sQ[nr * SP + nq * 16 + e];
            sk = fmaf(kv, kv, sk);
            sq = fmaf(qv, qv, sq);
        }
        sk += __shfl_xor_sync(~0u, sk, 1); sk += __shfl_xor_sync(~0u, sk, 2);
        sq += __shfl_xor_sync(~0u, sq, 1); sq += __shfl_xor_sync(~0u, sq, 2);
        const float ik = 1.f / fmaxf(sqrtf(sk), 1e-12f);
        const float iq = 1.f / fmaxf(sqrtf(sq), 1e-12f);
        #pragma unroll
        for (int e = 0; e < 16; e++) {
            sK[nr * SP + nq * 16 + e] *= ik;
            sQ[nr * SP + nq * 16 + e] *= iq;
        }
    }
    __syncthreads();

    // build transposes sQt[j][t], sKt[j][s]
    #pragma unroll
    for (int f = 0; f < 4; f++) {
        const int e4 = f * 256 + tid;
        const int tt = e4 >> 4, j4 = (e4 & 15) << 2;
        const float4 q = *(const float4*)&sQ[tt * SP + j4];
        const float4 k = *(const float4*)&sK[tt * SP + j4];
        sQt[(j4 + 0) * SP + tt] = q.x; sQt[(j4 + 1) * SP + tt] = q.y;
        sQt[(j4 + 2) * SP + tt] = q.z; sQt[(j4 + 3) * SP + tt] = q.w;
        sKt[(j4 + 0) * SP + tt] = k.x; sKt[(j4 + 1) * SP + tt] = k.y;
        sKt[(j4 + 2) * SP + tt] = k.z; sKt[(j4 + 3) * SP + tt] = k.w;
    }
    __syncthreads();

    // export normalized Q TRANSPOSED [j][t] for phase 3
    #pragma unroll
    for (int f = 0; f < 4; f++) {
        const int e4 = f * 256 + tid;
        const int jj = e4 >> 4, t4 = (e4 & 15) << 2;
        *(float4*)&g_qn[(((size_t)bh * NC + tc) * 64 + jj) * 64 + t4] =
            *(const float4*)&sQt[jj * SP + t4];
    }

    // S_c[i][j] = sum_s A[s][i] * K[s][j]   (row-major reads, conflict-free)
    {
        const int i4 = (tid & 15) * 4, j4 = (tid >> 4) * 4;
        float acc[4][4];
        #pragma unroll
        for (int a = 0; a < 4; a++)
            #pragma unroll
            for (int c = 0; c < 4; c++) acc[a][c] = 0.f;
        for (int s = 0; s < 64; s++) {
            const float4 av = *(const float4*)&sA[s * SP + i4];
            const float4 kv = *(const float4*)&sK[s * SP + j4];
            OP16(acc, av, kv);
        }
        float* Sp = g_S + ((size_t)bh * NC + tc) * 4096;
        #pragma unroll
        for (int a = 0; a < 4; a++)
            #pragma unroll
            for (int c = 0; c < 4; c++) Sp[(i4 + a) * 64 + j4 + c] = acc[a][c];
    }

    // G[t][s] = q_t . k_s (causal), computed from transposes, stored as sGt[s][t]
    {
        const int t4 = (tid & 15) * 4, s4 = (tid >> 4) * 4;
        float acc[4][4];
        #pragma unroll
        for (int a = 0; a < 4; a++)
            #pragma unroll
            for (int c = 0; c < 4; c++) acc[a][c] = 0.f;
        if (s4 <= t4 + 3) {
            for (int j = 0; j < 64; j++) {
                const float4 qv = *(const float4*)&sQt[j * SP + t4];
                const float4 kv = *(const float4*)&sKt[j * SP + s4];
                OP16(acc, qv, kv);
            }
        }
        #pragma unroll
        for (int c = 0; c < 4; c++) {
            float4 o;
            o.x = (s4 + c <= t4 + 0) ? acc[0][c] : 0.f;
            o.y = (s4 + c <= t4 + 1) ? acc[1][c] : 0.f;
            o.z = (s4 + c <= t4 + 2) ? acc[2][c] : 0.f;
            o.w = (s4 + c <= t4 + 3) ? acc[3][c] : 0.f;
            *(float4*)&sGt[(s4 + c) * SP + t4] = o;
        }
    }
    __syncthreads();

    // r_local[t][i] = sum_{s<=t} G[t][s] * A[s][i]; store es_t * r_local
    {
        const int t4 = (tid & 15) * 4, i4 = (tid >> 4) * 4;
        float acc[4][4];
        #pragma unroll
        for (int a = 0; a < 4; a++)
            #pragma unroll
            for (int c = 0; c < 4; c++) acc[a][c] = 0.f;
        const int smax = t4 + 4;
        for (int s = 0; s < smax; s++) {
            const float4 gv = *(const float4*)&sGt[s * SP + t4];
            const float4 av = *(const float4*)&sA[s * SP + i4];
            OP16(acc, gv, av);
        }
        #pragma unroll
        for (int a = 0; a < 4; a++) {
            const float e = es[t4 + a];
            const size_t ro = (size_t)(b * NT + tc * 64 + t4 + a) * NHD + h * 64;
            #pragma unroll
            for (int c = 0; c < 4; c++) g_read[ro + i4 + c] = e * acc[a][c];
        }
    }
}

// ============ phase 2: exclusive prefix of chunk sums + next_mem ===========
__global__ __launch_bounds__(256) void scan_p2(float* __restrict__ next_mem) {
    const int bh = blockIdx.x;
    const int e  = blockIdx.y * 256 + threadIdx.x;      // 0..4095
    const float elast = g_ecum[bh * NT + NT - 1];
    float acc = 0.f;
    #pragma unroll
    for (int c = 0; c < NC; c++) {
        g_P[((size_t)bh * NC + c) * 4096 + e] = acc;
        acc += g_S[((size_t)bh * NC + c) * 4096 + e];
    }
    next_mem[(size_t)bh * 4096 + e] = acc * elast;
}

// ============ phase 3: cross term r += es_t * (P_{c-1} q_t) ================
__global__ __launch_bounds__(256) void scan_p3() {
    __shared__ float sQt[64 * SP];    // [j][t] (g_qn already transposed)
    __shared__ float sPt[64 * SP];    // [j][i] (transpose-staged from g_P)
    __shared__ float es[64];
    const int tc = blockIdx.x + 1, bh = blockIdx.y, b = bh >> 3, h = bh & 7;
    const int tid = threadIdx.x;
    #pragma unroll
    for (int f = 0; f < 4; f++) {
        const int e4 = f * 256 + tid;
        const int r = e4 >> 4, c4 = (e4 & 15) << 2;
        *(float4*)&sQt[r * SP + c4] =
            *(const float4*)&g_qn[(((size_t)bh * NC + tc) * 64 + r) * 64 + c4];
        const float4 p =
            *(const float4*)&g_P[((size_t)bh * NC + tc) * 4096 + r * 64 + c4];
        sPt[(c4 + 0) * SP + r] = p.x; sPt[(c4 + 1) * SP + r] = p.y;
        sPt[(c4 + 2) * SP + r] = p.z; sPt[(c4 + 3) * SP + r] = p.w;
    }
    if (tid < 64) es[tid] = g_ecum[bh * NT + tc * 64 + tid];
    __syncthreads();

    const int t4 = (tid & 15) * 4, i4 = (tid >> 4) * 4;
    float acc[4][4];
    #pragma unroll
    for (int a = 0; a < 4; a++)
        #pragma unroll
        for (int c = 0; c < 4; c++) acc[a][c] = 0.f;
    for (int j = 0; j < 64; j++) {
        const float4 qv = *(const float4*)&sQt[j * SP + t4];
        const float4 pv = *(const float4*)&sPt[j * SP + i4];
        OP16(acc, qv, pv);
    }
    #pragma unroll
    for (int a = 0; a < 4; a++) {
        const float e = es[t4 + a];
        const size_t ro = (size_t)(b * NT + tc * 64 + t4 + a) * NHD + h * 64;
        #pragma unroll
        for (int c = 0; c < 4; c++) g_read[ro + i4 + c] += e * acc[a][c];
    }
}

// ---------------------------------------------------------------- launch ---
static float* sym(const void* s) {
    void* p = nullptr;
    cudaGetSymbolAddress(&p, s);
    return (float*)p;
}

extern "C" void kernel_launch(void* const* d_in, const int* in_sizes, int n_in,
                              void* d_out, int out_size) {
    const float* x     = (const float*)d_in[0];
    const float* b_min = (const float*)d_in[1];
    const float* b_max = (const float*)d_in[2];
    const float* motif = (const float*)d_in[3];
    const float* Wk    = (const float*)d_in[4];
    const float* bk    = (const float*)d_in[5];
    const float* Wq    = (const float*)d_in[6];
    const float* bq    = (const float*)d_in[7];
    const float* Wv    = (const float*)d_in[8];
    const float* bv    = (const float*)d_in[9];
    const float* Wo    = (const float*)d_in[10];
    const float* bo    = (const float*)d_in[11];
    const float* Wd    = (const float*)d_in[12];
    const float* bd    = (const float*)d_in[13];
    const float* Wgw   = (const float*)d_in[14];
    const float* bgw   = (const float*)d_in[15];
    const float* Wgf   = (const float*)d_in[16];
    const float* bgf   = (const float*)d_in[17];
    const float* Wps   = (const float*)d_in[18];
    const float* bps   = (const float*)d_in[19];
    const float* ln1g  = (const float*)d_in[20];
    const float* ln1b  = (const float*)d_in[21];
    const float* ln2g  = (const float*)d_in[22];
    const float* ln2b  = (const float*)d_in[23];
    const float* W1    = (const float*)d_in[24];
    const float* b1    = (const float*)d_in[25];
    const float* W2    = (const float*)d_in[26];
    const float* b2    = (const float*)d_in[27];

    float* out    = (float*)d_out;
    float* out_x3 = out;                            // [2,1024,512]
    float* out_nm = out + (size_t)NROWS * NE;       // [2,8,64,64]
    float* out_pm = out_nm + NBH * ND * ND;         // b_min + probe
    float* out_px = out_pm + (size_t)NROWS * NE;    // b_max + probe

    float* xn   = sym(g_xn);
    float* Wkqv = sym(g_Wkqv);
    float* bkqv = sym(g_bkqv);
    float* kqv  = sym(g_kqv);
    float* rd   = sym(g_read);
    float* x2   = sym(g_x2);
    float* hh   = sym(g_hh);
    float* mid  = sym(g_mid);

    const int SM128 = 3 * (128 * APAD + 32 * 136) * 4;   // 107520
    const int SM64  = 3 * (128 * APAD + 32 * 72)  * 4;   // 82944
    const int SMP1  = (6 * 64 * SP + 64) * 4;            // 104704
    cudaFuncSetAttribute(tgemm_k<5,128>, cudaFuncAttributeMaxDynamicSharedMemorySize, SM128);
    cudaFuncSetAttribute(tgemm_k<2,128>, cudaFuncAttributeMaxDynamicSharedMemorySize, SM128);
    cudaFuncSetAttribute(tgemm_k<1,64>,  cudaFuncAttributeMaxDynamicSharedMemorySize, SM64);
    cudaFuncSetAttribute(tgemm_k<3,64>,  cudaFuncAttributeMaxDynamicSharedMemorySize, SM64);
    cudaFuncSetAttribute(tgemm_k<4,64>,  cudaFuncAttributeMaxDynamicSharedMemorySize, SM64);
    cudaFuncSetAttribute(scan_p1,        cudaFuncAttributeMaxDynamicSharedMemorySize, SMP1);

    // fused: LN1 (blocks 0..2047) + weight/bias packing (blocks 2048..)
    const int PREP_BLOCKS = (NE * LDW + 255) / 256;
    ln_prep_k<<<NROWS + PREP_BLOCKS, 256>>>(x, ln1g, ln1b,
                                            Wk, Wq, Wv, bk, bq, bv,
                                            Wd, bd, Wgw, bgw, Wgf, bgf);       // 0
    tgemm_k<5,128><<<dim3(13, 16), 256, SM128>>>(xn, Wkqv, bkqv, kqv,
                                                 512, LDW, LDW,
                                                 nullptr, nullptr, nullptr);   // 1
    cumsum_k<<<NBH, 64>>>();                                                   // 2
    scan_p1<<<dim3(NC, NBH), 256, SMP1>>>();                                   // 3
    scan_p2<<<dim3(NBH, 16), 256>>>(out_nm);                                   // 4
    scan_p3<<<dim3(NC - 1, NBH), 256>>>();                                     // 5 <- profiled

    tgemm_k<1,64><<<dim3(8, 16), 256, SM64>>>(rd, Wo, bo, x2, 512, 512, 512,
                                              x, motif, nullptr);              // 6
    ln_k<<<NROWS, 256>>>(x2, ln2g, ln2b, hh);                                  // 7
    tgemm_k<2,128><<<dim3(16, 16), 256, SM128>>>(hh, W1, b1, mid,
                                                 512, 2048, 2048,
                                                 nullptr, nullptr, nullptr);   // 8
    tgemm_k<3,64><<<dim3(8, 16), 256, SM64>>>(mid, W2, b2, out_x3,
                                              2048, 512, 512,
                                              x2, nullptr, nullptr);           // 9
    tgemm_k<4,64><<<dim3(8, 16), 256, SM64>>>(out_x3, Wps, bps, out_pm,
                                              512, 512, 512,
                                              b_min, b_max, out_px);           // 10
}